// round 9
// baseline (speedup 1.0000x reference)
#include <cuda_runtime.h>
#include <cuda_bf16.h>
#include <cuda_fp16.h>
#include <cuda_fp8.h>
#include <math.h>

#define NN    20000
#define IN_F  256
#define H     128
#define HN    4
#define S     5
#define KM    2
#define Bq    1024
#define M     16
#define D     512
#define ALPHA 0.2f
#define BM_   (Bq*M)      /* 16384 */
#define R_    (BM_ + Bq)  /* 17408 */
#define PAIRS (S*HN)      /* 20 */

#define KC    32          /* K halves per pipeline stage (fc) */
#define HS    40          /* fc smem row stride in halves */
#define QKS   136         /* full-K smem row stride in halves */
#define AS8   272         /* fp8 smem row stride in bytes */
#define SCALE_HI 2048.0f
#define SCALE_LO 4.8828125e-4f

__constant__ int c_kofs[S] = {0,0,1,1,1};

// ---------------- scratch ----------------
__device__ __nv_bfloat16 g_xhi[NN*IN_F];
__device__ __nv_bfloat16 g_xlo[NN*IN_F];
__device__ __nv_bfloat16 g_fwh[S*4*H*IN_F];
__device__ __nv_bfloat16 g_fwl[S*4*H*IN_F];
__device__ __half        g_vwh[PAIRS*H*H];
__device__ unsigned char g_vwc[PAIRS*H*256];
__device__ __nv_bfloat16 g_awh[KM*HN*H*H];
__device__ __nv_bfloat16 g_awl[KM*HN*H*H];
__device__ __half        g_ckh[PAIRS*H*H];
__device__ unsigned char g_ckc[PAIRS*H*256];
__device__ float g_ckb[PAIRS*H];
__device__ __nv_bfloat16 g_cqwh[PAIRS*H*H];
__device__ __nv_bfloat16 g_cqwl[PAIRS*H*H];
__device__ float g_cqb[PAIRS*H];
__device__ float g_xsh[PAIRS*Bq*H];
__device__ __nv_bfloat16 g_xshh[PAIRS*Bq*H];
__device__ __nv_bfloat16 g_xshl[PAIRS*Bq*H];
__device__ __half        g_yhf[(size_t)PAIRS*BM_*H];
__device__ unsigned char g_yc [(size_t)PAIRS*BM_*256];
__device__ float g_wh2[PAIRS*Bq*H];
__device__ float g_sout[S*Bq*D];
__device__ float g_mp[Bq*KM*D];

// ---------------- helpers ----------------
__device__ __forceinline__ void mma_bf16(float* d, const unsigned* a, const unsigned* b) {
    asm volatile(
      "mma.sync.aligned.m16n8k16.row.col.f32.bf16.bf16.f32 "
      "{%0,%1,%2,%3}, {%4,%5,%6,%7}, {%8,%9}, {%0,%1,%2,%3};\n"
      : "+f"(d[0]), "+f"(d[1]), "+f"(d[2]), "+f"(d[3])
      : "r"(a[0]), "r"(a[1]), "r"(a[2]), "r"(a[3]), "r"(b[0]), "r"(b[1]));
}
__device__ __forceinline__ void mma_f16(float* d, const unsigned* a, const unsigned* b) {
    asm volatile(
      "mma.sync.aligned.m16n8k16.row.col.f32.f16.f16.f32 "
      "{%0,%1,%2,%3}, {%4,%5,%6,%7}, {%8,%9}, {%0,%1,%2,%3};\n"
      : "+f"(d[0]), "+f"(d[1]), "+f"(d[2]), "+f"(d[3])
      : "r"(a[0]), "r"(a[1]), "r"(a[2]), "r"(a[3]), "r"(b[0]), "r"(b[1]));
}
__device__ __forceinline__ void mma_e4m3(float* d, const unsigned* a, const unsigned* b) {
    asm volatile(
      "mma.sync.aligned.m16n8k32.row.col.f32.e4m3.e4m3.f32 "
      "{%0,%1,%2,%3}, {%4,%5,%6,%7}, {%8,%9}, {%0,%1,%2,%3};\n"
      : "+f"(d[0]), "+f"(d[1]), "+f"(d[2]), "+f"(d[3])
      : "r"(a[0]), "r"(a[1]), "r"(a[2]), "r"(a[3]), "r"(b[0]), "r"(b[1]));
}
__device__ __forceinline__ void ldsm4(unsigned& r0, unsigned& r1, unsigned& r2, unsigned& r3,
                                      unsigned addr) {
    asm volatile("ldmatrix.sync.aligned.m8n8.x4.shared.b16 {%0,%1,%2,%3}, [%4];\n"
      : "=r"(r0), "=r"(r1), "=r"(r2), "=r"(r3) : "r"(addr));
}
__device__ __forceinline__ unsigned s2u(const void* p) {
    return (unsigned)__cvta_generic_to_shared(p);
}
__device__ __forceinline__ void split_bf(float x, __nv_bfloat16& h, __nv_bfloat16& l) {
    h = __float2bfloat16_rn(x);
    l = __float2bfloat16_rn(x - __bfloat162float(h));
}
__device__ __forceinline__ unsigned char f2e4m3(float x) {
    return (unsigned char)__nv_cvt_float_to_fp8(x, __NV_SATFINITE, __NV_E4M3);
}
__device__ __forceinline__ void cpa16(void* dst, const void* src) {
    unsigned d = (unsigned)__cvta_generic_to_shared(dst);
    asm volatile("cp.async.cg.shared.global [%0], [%1], 16;\n" :: "r"(d), "l"(src));
}
__device__ __forceinline__ void cp_commit() { asm volatile("cp.async.commit_group;\n"); }
__device__ __forceinline__ void cp_wait1() { asm volatile("cp.async.wait_group 1;\n"); }
__device__ __forceinline__ void cp_wait0() { asm volatile("cp.async.wait_group 0;\n"); }
__device__ __forceinline__ float lrelu_f(float v) { return v >= 0.f ? v : ALPHA*v; }

// ---------------- split: x, fc_w, attW -> bf16 hi/lo; v_w -> fp16 + fp8 corr ---
#define SPL_N1 (NN*IN_F)
#define SPL_N2 (S*4*H*IN_F)
#define SPL_N3 (PAIRS*H*H)
#define SPL_N4 (KM*HN*H*H)
#define SPL_TOT (SPL_N1 + SPL_N2 + SPL_N3 + SPL_N4)
__global__ void split_all(
    const float* __restrict__ x,    __nv_bfloat16* __restrict__ xhi, __nv_bfloat16* __restrict__ xlo,
    const float* __restrict__ fcw,  __nv_bfloat16* __restrict__ fwh, __nv_bfloat16* __restrict__ fwl,
    const float* __restrict__ vw,   __half* __restrict__ vwh, unsigned char* __restrict__ vwc,
    const float* __restrict__ attw, __nv_bfloat16* __restrict__ awh, __nv_bfloat16* __restrict__ awl)
{
    int i = blockIdx.x*256 + threadIdx.x;
    if (i < SPL_N1) { split_bf(x[i], xhi[i], xlo[i]); return; }
    if (i < SPL_N1+SPL_N2) { int j = i - SPL_N1; split_bf(fcw[j], fwh[j], fwl[j]); return; }
    if (i < SPL_N1+SPL_N2+SPL_N3) {
        int j = i - SPL_N1 - SPL_N2;
        float v = vw[j];
        __half h = __float2half_rn(v);
        float l = v - __half2float(h);
        vwh[j] = h;
        int n = j / H, c = j % H;
        // B-order: first half lo*2^11, second half hi
        vwc[(size_t)n*256 + c]       = f2e4m3(l*SCALE_HI);
        vwc[(size_t)n*256 + 128 + c] = f2e4m3(v);
        return;
    }
    if (i < SPL_TOT) { int j = i - SPL_N1 - SPL_N2 - SPL_N3; split_bf(attw[j], awh[j], awl[j]); }
}

// ---------------- combined weights (ck -> fp16+fp8, cq -> bf16 hi/lo) ---------
__global__ __launch_bounds__(256) void combine_gemm(
    const float* __restrict__ a1w, const float* __restrict__ a1b,
    const float* __restrict__ k_w, const float* __restrict__ k_b,
    __half* __restrict__ ckh, unsigned char* __restrict__ ckc, float* __restrict__ ckb,
    const float* __restrict__ a2w, const float* __restrict__ a2b,
    const float* __restrict__ q_w, const float* __restrict__ q_b,
    __nv_bfloat16* __restrict__ cqh, __nv_bfloat16* __restrict__ cql, float* __restrict__ cqb)
{
    int ot = blockIdx.x, z = blockIdx.y, which = blockIdx.z, tid = threadIdx.x;
    const float* aw = which ? a2w : a1w;
    const float* ab = which ? a2b : a1b;
    const float* w  = which ? q_w : k_w;
    const float* wb = which ? q_b : k_b;
    float* cb = which ? cqb : ckb;
    int kz = c_kofs[z/HN]*HN + (z % HN);
    const float* A = aw + ((size_t)kz*H + ot*32)*H;
    const float* W = w + (size_t)z*H*H;
    __shared__ float sa[32][36];
    __shared__ float sw[32][132];
    int tx = tid & 15, ty = tid >> 4;
    float acc[2][8];
    #pragma unroll
    for (int r = 0; r < 2; ++r)
        #pragma unroll
        for (int c = 0; c < 8; ++c) acc[r][c] = 0.f;
    for (int kc = 0; kc < 4; ++kc) {
        {
            int r = tid >> 3, c4 = (tid & 7)*4;
            *(float4*)&sa[r][c4] = *(const float4*)(A + r*H + kc*32 + c4);
        }
        #pragma unroll
        for (int i = 0; i < 4; ++i) {
            int idx = tid + i*256;
            int r = idx >> 5, c4 = (idx & 31)*4;
            *(float4*)&sw[r][c4] = *(const float4*)(W + (kc*32 + r)*H + c4);
        }
        __syncthreads();
        #pragma unroll 8
        for (int j = 0; j < 32; ++j) {
            float a0 = sa[ty*2][j], a1 = sa[ty*2+1][j];
            #pragma unroll
            for (int c = 0; c < 8; ++c) {
                float wv = sw[j][tx*8 + c];
                acc[0][c] += a0*wv;
                acc[1][c] += a1*wv;
            }
        }
        __syncthreads();
    }
    #pragma unroll
    for (int r = 0; r < 2; ++r)
        #pragma unroll
        for (int c = 0; c < 8; ++c) {
            int row = ot*32 + ty*2 + r, col = tx*8 + c;
            float v = acc[r][c];
            if (which) {
                size_t idx = ((size_t)z*H + row)*H + col;
                split_bf(v, cqh[idx], cql[idx]);
            } else {
                __half h = __float2half_rn(v);
                float l = v - __half2float(h);
                ckh[((size_t)z*H + row)*H + col] = h;
                size_t b8 = ((size_t)z*H + row)*256;
                ckc[b8 + col]       = f2e4m3(l*SCALE_HI);  // B-order: lo first
                ckc[b8 + 128 + col] = f2e4m3(v);
            }
        }
    if (tid < 32) {
        int o = ot*32 + tid;
        float bacc = ab[kz*H + o];
        const float* arow = aw + ((size_t)kz*H + o)*H;
        const float* brow = wb + z*H;
        for (int j = 0; j < H; ++j) bacc += arow[j]*brow[j];
        cb[z*H + o] = bacc;
    }
}

// ================= fc GEMM (bf16-split TC, ldmatrix, gather) =================
#define FC2_SMEM (8*128*HS*2 + 512)
__global__ __launch_bounds__(256,2) void fc_bf16(
    const __nv_bfloat16* __restrict__ xh, const __nv_bfloat16* __restrict__ xl,
    const int* __restrict__ neigh, const int* __restrict__ tgt,
    const __nv_bfloat16* __restrict__ fwh, const __nv_bfloat16* __restrict__ fwl,
    const float* __restrict__ fcb,
    __half* __restrict__ yhf, unsigned char* __restrict__ yc,
    float* __restrict__ xsh,
    __nv_bfloat16* __restrict__ xshh, __nv_bfloat16* __restrict__ xshl)
{
    extern __shared__ __align__(16) char smc[];
    __nv_bfloat16* Ah = (__nv_bfloat16*)smc;
    __nv_bfloat16* Al = Ah + 2*128*HS;
    __nv_bfloat16* Bh = Al + 2*128*HS;
    __nv_bfloat16* Bl = Bh + 2*128*HS;
    int* rows = (int*)(Bl + 2*128*HS);
    int mt = blockIdx.x, nt = blockIdx.y, s = blockIdx.z;
    int tid = threadIdx.x;
    if (tid < 128) {
        int r = mt*128 + tid;
        rows[tid] = (r < BM_) ? neigh[s*BM_ + r] : tgt[r - BM_];
    }
    __syncthreads();
    size_t wb = ((size_t)s*512 + nt*128)*IN_F;

    auto prefetch = [&](int kc, int buf) {
        #pragma unroll
        for (int i = 0; i < 2; ++i) {
            int idx = tid + i*256;
            int r = idx >> 2, seg = (idx & 3)*8;
            int so = buf*128*HS + r*HS + seg;
            size_t ga = (size_t)rows[r]*IN_F + kc*KC + seg;
            size_t gb = wb + (size_t)r*IN_F + kc*KC + seg;
            cpa16(Ah + so, xh + ga);
            cpa16(Al + so, xl + ga);
            cpa16(Bh + so, fwh + gb);
            cpa16(Bl + so, fwl + gb);
        }
    };

    int w = tid >> 5, lane = tid & 31;
    int wm = (w & 3)*32, wn = (w >> 2)*64;
    int arow = lane & 15, acol = (lane & 16) ? 8 : 0;
    int bn = (lane & 7) + ((lane & 16) ? 8 : 0), bk = (lane & 8) ? 8 : 0;
    unsigned aAh = s2u(Ah), aAl = s2u(Al), aBh = s2u(Bh), aBl = s2u(Bl);

    float acc[2][8][4];
    #pragma unroll
    for (int i = 0; i < 2; ++i)
        #pragma unroll
        for (int j = 0; j < 8; ++j)
            #pragma unroll
            for (int e = 0; e < 4; ++e) acc[i][j][e] = 0.f;

    prefetch(0, 0); cp_commit();
    const int NCH = IN_F/KC;  // 8
    for (int kc = 0; kc < NCH; ++kc) {
        if (kc+1 < NCH) { prefetch(kc+1, (kc+1)&1); cp_commit(); cp_wait1(); }
        else            { cp_wait0(); }
        __syncthreads();
        unsigned bufo = (unsigned)((kc&1)*128*HS*2);
        #pragma unroll
        for (int kk = 0; kk < 2; ++kk) {
            int kb = kk*16;
            unsigned ah[2][4], al[2][4];
            #pragma unroll
            for (int mi = 0; mi < 2; ++mi) {
                unsigned off = bufo + (unsigned)(((wm + mi*16 + arow)*HS + kb + acol)*2);
                ldsm4(ah[mi][0], ah[mi][1], ah[mi][2], ah[mi][3], aAh + off);
                ldsm4(al[mi][0], al[mi][1], al[mi][2], al[mi][3], aAl + off);
            }
            unsigned bh[8][2], bl[8][2];
            #pragma unroll
            for (int nj = 0; nj < 4; ++nj) {
                unsigned off = bufo + (unsigned)(((wn + nj*16 + bn)*HS + kb + bk)*2);
                ldsm4(bh[nj*2][0], bh[nj*2][1], bh[nj*2+1][0], bh[nj*2+1][1], aBh + off);
                ldsm4(bl[nj*2][0], bl[nj*2][1], bl[nj*2+1][0], bl[nj*2+1][1], aBl + off);
            }
            #pragma unroll
            for (int ni = 0; ni < 8; ++ni)
                #pragma unroll
                for (int mi = 0; mi < 2; ++mi) {
                    mma_bf16(acc[mi][ni], ah[mi], bl[ni]);
                    mma_bf16(acc[mi][ni], al[mi], bh[ni]);
                    mma_bf16(acc[mi][ni], ah[mi], bh[ni]);
                }
        }
        __syncthreads();
    }

    int zp = s*HN + nt;
    int gid = lane >> 2, tig = lane & 3;
    float* Cs = (float*)smc;  // 128x132
    #pragma unroll
    for (int mi = 0; mi < 2; ++mi)
        #pragma unroll
        for (int ni = 0; ni < 8; ++ni)
            #pragma unroll
            for (int e = 0; e < 4; ++e) {
                int r = wm + mi*16 + gid + ((e >= 2) ? 8 : 0);
                int c = wn + ni*8 + 2*tig + (e & 1);
                Cs[r*132 + c] = lrelu_f(acc[mi][ni][e] + fcb[zp*H + c]);
            }
    __syncthreads();
    #pragma unroll
    for (int t = 0; t < 16; ++t) {
        int idx = tid + t*256;
        int rr = idx >> 5, c4 = (idx & 31)*4;
        float4 v = *(const float4*)(Cs + rr*132 + c4);
        int gr = mt*128 + rr;
        if (gr < BM_) {
            // fp16 hi + fp8 corr (A-order: hi first half, lo*2^11 second)
            __half h0 = __float2half_rn(v.x), h1 = __float2half_rn(v.y);
            __half h2_ = __float2half_rn(v.z), h3 = __float2half_rn(v.w);
            float l0 = v.x - __half2float(h0), l1 = v.y - __half2float(h1);
            float l2 = v.z - __half2float(h2_), l3 = v.w - __half2float(h3);
            size_t b16 = ((size_t)zp*BM_ + gr)*H + c4;
            __half2 p0 = {h0, h1}, p1 = {h2_, h3};
            uint2 uh; uh.x = *(unsigned*)&p0; uh.y = *(unsigned*)&p1;
            *(uint2*)(yhf + b16) = uh;
            size_t b8 = ((size_t)zp*BM_ + gr)*256 + c4;
            uchar4 hb = {f2e4m3(v.x), f2e4m3(v.y), f2e4m3(v.z), f2e4m3(v.w)};
            uchar4 lb = {f2e4m3(l0*SCALE_HI), f2e4m3(l1*SCALE_HI),
                         f2e4m3(l2*SCALE_HI), f2e4m3(l3*SCALE_HI)};
            *(uchar4*)(yc + b8) = hb;
            *(uchar4*)(yc + b8 + 128) = lb;
        } else {
            size_t base = ((size_t)zp*Bq + (gr - BM_))*H + c4;
            *(float4*)(xsh + base) = v;
            __nv_bfloat16 h0,h1,h2_,h3,l0,l1,l2,l3;
            split_bf(v.x,h0,l0); split_bf(v.y,h1,l1);
            split_bf(v.z,h2_,l2); split_bf(v.w,h3,l3);
            __nv_bfloat162 ph0 = {h0,h1}, ph1 = {h2_,h3};
            __nv_bfloat162 pl0 = {l0,l1}, pl1 = {l2,l3};
            uint2 uh, ul;
            uh.x = *(unsigned*)&ph0; uh.y = *(unsigned*)&ph1;
            ul.x = *(unsigned*)&pl0; ul.y = *(unsigned*)&pl1;
            *(uint2*)(xshh + base) = uh;
            *(uint2*)(xshl + base) = ul;
        }
    }
}

// ================= qk_fused (mma.sync bf16-split + ldmatrix) =================
#define QK_SMEM (4*128*QKS*2)
__global__ __launch_bounds__(256,1) void qk_fused(
    const __nv_bfloat16* __restrict__ xshh, const __nv_bfloat16* __restrict__ xshl,
    const __nv_bfloat16* __restrict__ cqh, const __nv_bfloat16* __restrict__ cql,
    const float* __restrict__ cqb,
    const __nv_bfloat16* __restrict__ awh, const __nv_bfloat16* __restrict__ awl,
    float* __restrict__ wh2)
{
    extern __shared__ __align__(16) char smc[];
    __nv_bfloat16* Axh = (__nv_bfloat16*)smc;
    __nv_bfloat16* Axl = Axh + 128*QKS;
    __nv_bfloat16* Bh  = Axl + 128*QKS;
    __nv_bfloat16* Bl  = Bh + 128*QKS;
    int mt = blockIdx.x, z = blockIdx.y;
    int tid = threadIdx.x;
    int kz = c_kofs[z/HN]*HN + (z % HN);

    const __nv_bfloat16* Agh = xshh + ((size_t)z*Bq + mt*128)*H;
    const __nv_bfloat16* Agl = xshl + ((size_t)z*Bq + mt*128)*H;
    const __nv_bfloat16* Bgh = cqh + (size_t)z*H*H;
    const __nv_bfloat16* Bgl = cql + (size_t)z*H*H;

    #pragma unroll
    for (int i = 0; i < 8; ++i) {
        int idx = tid + i*256;
        int r = idx >> 4, seg = (idx & 15)*8;
        cpa16(Axh + r*QKS + seg, Agh + (size_t)r*H + seg);
        cpa16(Axl + r*QKS + seg, Agl + (size_t)r*H + seg);
        cpa16(Bh + r*QKS + seg, Bgh + (size_t)r*H + seg);
        cpa16(Bl + r*QKS + seg, Bgl + (size_t)r*H + seg);
    }
    cp_commit(); cp_wait0();
    __syncthreads();

    int w = tid >> 5, lane = tid & 31, gid = lane >> 2, tig = lane & 3;
    int wm = (w & 3)*32, wn = (w >> 2)*64;
    int arow = lane & 15, acol = (lane & 16) ? 8 : 0;
    int bn = (lane & 7) + ((lane & 16) ? 8 : 0), bk = (lane & 8) ? 8 : 0;
    unsigned aAh = s2u(Axh), aAl = s2u(Axl), aBh = s2u(Bh), aBl = s2u(Bl);
    float acc[2][8][4];

    auto run_gemm = [&]() {
        #pragma unroll
        for (int i = 0; i < 2; ++i)
            #pragma unroll
            for (int j = 0; j < 8; ++j)
                #pragma unroll
                for (int e = 0; e < 4; ++e) acc[i][j][e] = 0.f;
        #pragma unroll
        for (int kk = 0; kk < 8; ++kk) {
            int kb = kk*16;
            unsigned ah[2][4], al[2][4];
            #pragma unroll
            for (int mi = 0; mi < 2; ++mi) {
                unsigned off = (unsigned)(((wm + mi*16 + arow)*QKS + kb + acol)*2);
                ldsm4(ah[mi][0], ah[mi][1], ah[mi][2], ah[mi][3], aAh + off);
                ldsm4(al[mi][0], al[mi][1], al[mi][2], al[mi][3], aAl + off);
            }
            unsigned bh[8][2], bl[8][2];
            #pragma unroll
            for (int nj = 0; nj < 4; ++nj) {
                unsigned off = (unsigned)(((wn + nj*16 + bn)*QKS + kb + bk)*2);
                ldsm4(bh[nj*2][0], bh[nj*2][1], bh[nj*2+1][0], bh[nj*2+1][1], aBh + off);
                ldsm4(bl[nj*2][0], bl[nj*2][1], bl[nj*2+1][0], bl[nj*2+1][1], aBl + off);
            }
            #pragma unroll
            for (int ni = 0; ni < 8; ++ni)
                #pragma unroll
                for (int mi = 0; mi < 2; ++mi) {
                    mma_bf16(acc[mi][ni], ah[mi], bl[ni]);
                    mma_bf16(acc[mi][ni], al[mi], bh[ni]);
                    mma_bf16(acc[mi][ni], ah[mi], bh[ni]);
                }
        }
    };

    run_gemm();
    __syncthreads();
    #pragma unroll
    for (int mi = 0; mi < 2; ++mi)
        #pragma unroll
        for (int ni = 0; ni < 8; ++ni)
            #pragma unroll
            for (int e = 0; e < 4; ++e) {
                int r = wm + mi*16 + gid + ((e >= 2) ? 8 : 0);
                int c = wn + ni*8 + 2*tig + (e & 1);
                float v = lrelu_f(acc[mi][ni][e] + cqb[z*H + c]);
                __nv_bfloat16 hh, ll;
                split_bf(v, hh, ll);
                Axh[r*QKS + c] = hh;
                Axl[r*QKS + c] = ll;
            }
    const __nv_bfloat16* Wgh = awh + (size_t)kz*H*H;
    const __nv_bfloat16* Wgl = awl + (size_t)kz*H*H;
    #pragma unroll
    for (int i = 0; i < 8; ++i) {
        int idx = tid + i*256;
        int r = idx >> 4, seg = (idx & 15)*8;
        cpa16(Bh + r*QKS + seg, Wgh + (size_t)r*H + seg);
        cpa16(Bl + r*QKS + seg, Wgl + (size_t)r*H + seg);
    }
    cp_commit(); cp_wait0();
    __syncthreads();

    run_gemm();
    #pragma unroll
    for (int mi = 0; mi < 2; ++mi)
        #pragma unroll
        for (int ni = 0; ni < 8; ++ni)
            #pragma unroll
            for (int e = 0; e < 4; ++e) {
                int r = wm + mi*16 + gid + ((e >= 2) ? 8 : 0);
                int c = wn + ni*8 + 2*tig + (e & 1);
                wh2[((size_t)z*Bq + mt*128 + r)*H + c] = acc[mi][ni][e];
            }
}

// ================= fused h1/vh GEMM + attention (fp16 main + fp8 corr) =========
// corr pass: e4m3 stacked-K (K'=256, m16n8k32), scale 2^-11; main pass: fp16 k16.
#define FU_AH_OFF 0
#define FU_BH_OFF (128*QKS*2)
#define FU_AC_OFF (FU_BH_OFF + 256*QKS*2)
#define FU_BC_OFF (FU_AC_OFF + 128*AS8)
#define FU_SMEM   (FU_BC_OFF + 256*AS8)   /* 208896 */
__global__ __launch_bounds__(512,1) void fused_attn(
    const __half* __restrict__ yhf, const unsigned char* __restrict__ yc,
    const __half* __restrict__ ckh, const unsigned char* __restrict__ ckc,
    const float* __restrict__ ckb,
    const __half* __restrict__ vwh, const unsigned char* __restrict__ vwc,
    const float* __restrict__ vb,  const float* __restrict__ wh2,
    const float* __restrict__ xsh, float* __restrict__ sout)
{
    extern __shared__ __align__(16) char smc[];
    float* sm = (float*)smc;
    __half* Ah = (__half*)(smc + FU_AH_OFF);           // [128][QKS] fp16
    __half* Bh = (__half*)(smc + FU_BH_OFF);           // [256][QKS] fp16
    unsigned char* Ac = (unsigned char*)(smc + FU_AC_OFF);  // [128][AS8] fp8
    unsigned char* Bc = (unsigned char*)(smc + FU_BC_OFF);  // [256][AS8] fp8
    int mt = blockIdx.x, z = blockIdx.y;
    int tid = threadIdx.x;

    const __half* Agh = yhf + ((size_t)z*BM_ + mt*128)*H;
    const unsigned char* Agc = yc + ((size_t)z*BM_ + mt*128)*256;
    size_t wkb = (size_t)z*H*H;
    size_t wkb8 = (size_t)z*H*256;

    // one-shot loads
    #pragma unroll
    for (int i = 0; i < 4; ++i) {                     // A fp16: 2048 x16B
        int idx = tid + i*512;
        int r = idx >> 4, seg = (idx & 15)*8;
        cpa16(Ah + r*QKS + seg, Agh + (size_t)r*H + seg);
    }
    #pragma unroll
    for (int i = 0; i < 4; ++i) {                     // A fp8: 2048 x16B
        int idx = tid + i*512;
        int r = idx >> 4, seg = (idx & 15)*16;
        cpa16(Ac + r*AS8 + seg, Agc + (size_t)r*256 + seg);
    }
    #pragma unroll
    for (int i = 0; i < 8; ++i) {                     // B fp16: 4096 x16B
        int idx = tid + i*512;
        int n = idx >> 4, seg = (idx & 15)*8;
        const __half* src = (n < 128) ? (ckh + wkb + (size_t)n*H)
                                      : (vwh + wkb + (size_t)(n-128)*H);
        cpa16(Bh + n*QKS + seg, src + seg);
    }
    #pragma unroll
    for (int i = 0; i < 8; ++i) {                     // B fp8: 4096 x16B
        int idx = tid + i*512;
        int n = idx >> 4, seg = (idx & 15)*16;
        const unsigned char* src = (n < 128) ? (ckc + wkb8 + (size_t)n*256)
                                             : (vwc + wkb8 + (size_t)(n-128)*256);
        cpa16(Bc + n*AS8 + seg, src + seg);
    }
    cp_commit(); cp_wait0();
    __syncthreads();

    int w = tid >> 5, lane = tid & 31, gid = lane >> 2, tig = lane & 3;
    int wm = (w & 3)*32, wn = (w >> 2)*64;
    int arow = lane & 15;
    int acol = (lane & 16) ? 8 : 0;                 // fp16: halves
    int acol8 = (lane & 16) ? 16 : 0;               // fp8: bytes
    int bn = (lane & 7) + ((lane & 16) ? 8 : 0);
    int bk = (lane & 8) ? 8 : 0;                    // fp16 halves
    int bk8 = (lane & 8) ? 16 : 0;                  // fp8 bytes
    unsigned aAh = s2u(Ah), aBh = s2u(Bh), aAc = s2u(Ac), aBc = s2u(Bc);

    float acc[2][8][4];
    #pragma unroll
    for (int i = 0; i < 2; ++i)
        #pragma unroll
        for (int j = 0; j < 8; ++j)
            #pragma unroll
            for (int e = 0; e < 4; ++e) acc[i][j][e] = 0.f;

    // ---- correction pass: e4m3 stacked K'=256, 8 k32 steps ----
    #pragma unroll
    for (int kk = 0; kk < 8; ++kk) {
        int kb = kk*32;   // bytes
        unsigned af[2][4];
        #pragma unroll
        for (int mi = 0; mi < 2; ++mi) {
            unsigned off = (unsigned)((wm + mi*16 + arow)*AS8 + kb + acol8);
            ldsm4(af[mi][0], af[mi][1], af[mi][2], af[mi][3], aAc + off);
        }
        unsigned bf[8][2];
        #pragma unroll
        for (int nj = 0; nj < 4; ++nj) {
            unsigned off = (unsigned)((wn + nj*16 + bn)*AS8 + kb + bk8);
            ldsm4(bf[nj*2][0], bf[nj*2][1], bf[nj*2+1][0], bf[nj*2+1][1], aBc + off);
        }
        #pragma unroll
        for (int ni = 0; ni < 8; ++ni)
            #pragma unroll
            for (int mi = 0; mi < 2; ++mi)
                mma_e4m3(acc[mi][ni], af[mi], bf[ni]);
    }
    // scale corrections by 2^-11
    #pragma unroll
    for (int i = 0; i < 2; ++i)
        #pragma unroll
        for (int j = 0; j < 8; ++j)
            #pragma unroll
            for (int e = 0; e < 4; ++e) acc[i][j][e] *= SCALE_LO;

    // ---- main pass: fp16 K=128, 8 k16 steps ----
    #pragma unroll
    for (int kk = 0; kk < 8; ++kk) {
        int kb = kk*16;   // halves
        unsigned ah[2][4];
        #pragma unroll
        for (int mi = 0; mi < 2; ++mi) {
            unsigned off = (unsigned)(((wm + mi*16 + arow)*QKS + kb + acol)*2);
            ldsm4(ah[mi][0], ah[mi][1], ah[mi][2], ah[mi][3], aAh + off);
        }
        unsigned bh[8][2];
        #pragma unroll
        for (int nj = 0; nj < 4; ++nj) {
            unsigned off = (unsigned)(((wn + nj*16 + bn)*QKS + kb + bk)*2);
            ldsm4(bh[nj*2][0], bh[nj*2][1], bh[nj*2+1][0], bh[nj*2+1][1], aBh + off);
        }
        #pragma unroll
        for (int ni = 0; ni < 8; ++ni)
            #pragma unroll
            for (int mi = 0; mi < 2; ++mi)
                mma_f16(acc[mi][ni], ah[mi], bh[ni]);
    }
    __syncthreads();   // smem reads done before epilogue aliasing

    float* SP  = sm;                 // [128][132]  h1 (lrelu+bias)
    float* SV  = SP + 128*132;       // [128][132]  vh (+bias)
    float* SW  = SV + 128*132;       // [8][128]    wh2 rows
    float* SSC = SW + 8*128;         // [128] scores
    float* SE  = SSC + 128;          // [128] softmax weights

    #pragma unroll
    for (int mi = 0; mi < 2; ++mi)
        #pragma unroll
        for (int ni = 0; ni < 8; ++ni)
            #pragma unroll
            for (int e = 0; e < 4; ++e) {
                int r = wm + mi*16 + gid + ((e >= 2) ? 8 : 0);
                int c = wn + ni*8 + 2*tig + (e & 1);
                float v = acc[mi][ni][e];
                if (c < 128) SP[r*132 + c] = lrelu_f(v + ckb[z*H + c]);
                else         SV[r*132 + (c-128)] = v + vb[z*H + (c-128)];
            }
    #pragma unroll
    for (int t = 0; t < 2; ++t) {
        int idx = tid + t*512;
        int bl = idx >> 7, o = idx & 127;
        SW[idx] = wh2[((size_t)z*Bq + mt*8 + bl)*H + o];
    }
    __syncthreads();

    #pragma unroll
    for (int i = 0; i < 8; ++i) {
        int rr = w*8 + i;
        const float* wrow = SW + (rr >> 4)*128;
        float p = 0.f;
        #pragma unroll
        for (int o = 0; o < 128; o += 32) p += SP[rr*132 + o + lane]*wrow[o + lane];
        #pragma unroll
        for (int d_ = 16; d_ > 0; d_ >>= 1) p += __shfl_xor_sync(0xffffffffu, p, d_);
        if (lane == 0) SSC[rr] = p;
    }
    __syncthreads();
    if (tid < 8) {
        float mx = -1e30f;
        #pragma unroll
        for (int m = 0; m < M; ++m) mx = fmaxf(mx, SSC[tid*M + m]);
        float es[M], sum = 0.f;
        #pragma unroll
        for (int m = 0; m < M; ++m) { es[m] = expf(SSC[tid*M + m] - mx); sum += es[m]; }
        float inv = 1.f/sum;
        #pragma unroll
        for (int m = 0; m < M; ++m) SE[tid*M + m] = es[m]*inv;
    }
    __syncthreads();

    int s = z/HN, hh = z%HN;
    #pragma unroll
    for (int t = 0; t < 2; ++t) {
        int idx = tid + t*512;
        int bl = idx >> 7, o = idx & 127;
        float a = 0.f;
        #pragma unroll
        for (int m = 0; m < M; ++m) {
            float v = SV[(bl*M + m)*132 + o]*SE[bl*M + m];
            a += (v >= 0.f) ? v : ALPHA*v;
        }
        int b = mt*8 + bl;
        sout[((size_t)s*Bq + b)*D + hh*H + o] =
            0.5f*(xsh[((size_t)z*Bq + b)*H + o] + a);
    }
}

// ---------------- semantic attention ----------------
template<int P>
__global__ __launch_bounds__(128) void semantic(
    const float* __restrict__ zin, const float* __restrict__ p1w,
    const float* __restrict__ p1b, const float* __restrict__ p2w,
    float* __restrict__ outp, int in_pstride, int in_bstride, int out_bstride)
{
    int b0 = blockIdx.x*4, tid = threadIdx.x;
    __shared__ float zs[4][P][D];
    int tot = 4*P*D;
    for (int idx = tid; idx < tot; idx += 128) {
        int d = idx % D; int rp = idx / D; int p = rp % P; int bl = rp / P;
        zs[bl][p][d] = zin[(size_t)(b0+bl)*in_bstride + (size_t)p*in_pstride + d];
    }
    __syncthreads();
    float acc[4][P];
    #pragma unroll
    for (int bl = 0; bl < 4; ++bl)
        #pragma unroll
        for (int p = 0; p < P; ++p) acc[bl][p] = 0.f;
    const float* wrow = p1w + (size_t)tid*D;
    for (int d = 0; d < D; ++d) {
        float wv = wrow[d];
        #pragma unroll
        for (int bl = 0; bl < 4; ++bl)
            #pragma unroll
            for (int p = 0; p < P; ++p) acc[bl][p] += wv*zs[bl][p][d];
    }
    float bias = p1b[tid], p2 = p2w[tid];
    __shared__ float sred[4*P][132];
    __shared__ float ssc[4*P];
    #pragma unroll
    for (int bl = 0; bl < 4; ++bl)
        #pragma unroll
        for (int p = 0; p < P; ++p)
            sred[bl*P+p][tid] = tanhf(acc[bl][p] + bias)*p2;
    __syncthreads();
    if (tid < 4*P) {
        float s_ = 0.f;
        for (int o = 0; o < H; ++o) s_ += sred[tid][o];
        ssc[tid] = s_;
    }
    __syncthreads();
    #pragma unroll
    for (int bl = 0; bl < 4; ++bl) {
        float mx = -1e30f;
        #pragma unroll
        for (int p = 0; p < P; ++p) mx = fmaxf(mx, ssc[bl*P+p]);
        float e[P]; float esum = 0.f;
        #pragma unroll
        for (int p = 0; p < P; ++p) { e[p] = expf(ssc[bl*P+p] - mx); esum += e[p]; }
        float inv = 1.f/esum;
        for (int d = tid; d < D; d += 128) {
            float o_ = 0.f;
            #pragma unroll
            for (int p = 0; p < P; ++p) o_ += e[p]*zs[bl][p][d];
            outp[(size_t)(b0+bl)*out_bstride + d] = o_*inv;
        }
    }
}

extern "C" void kernel_launch(void* const* d_in, const int* in_sizes, int n_in,
                              void* d_out, int out_size)
{
    const float* x     = (const float*)d_in[0];
    const int*   tgt   = (const int*)  d_in[1];
    const int*   neigh = (const int*)  d_in[2];
    const float* fc_w  = (const float*)d_in[3];
    const float* fc_b  = (const float*)d_in[4];
    const float* q_w   = (const float*)d_in[5];
    const float* q_b   = (const float*)d_in[6];
    const float* k_w   = (const float*)d_in[7];
    const float* k_b   = (const float*)d_in[8];
    const float* v_w   = (const float*)d_in[9];
    const float* v_b   = (const float*)d_in[10];
    const float* att_W = (const float*)d_in[11];
    const float* a1w   = (const float*)d_in[12];
    const float* a1b   = (const float*)d_in[13];
    const float* a2w   = (const float*)d_in[14];
    const float* a2b   = (const float*)d_in[15];
    const float* ip1w  = (const float*)d_in[16];
    const float* ip1b  = (const float*)d_in[17];
    const float* ip2w  = (const float*)d_in[18];
    const float* bp1w  = (const float*)d_in[19];
    const float* bp1b  = (const float*)d_in[20];
    const float* bp2w  = (const float*)d_in[21];
    float* out = (float*)d_out;

    __nv_bfloat16 *xhi,*xlo,*fwh,*fwl,*awh,*awl,*cqwh,*cqwl,*xshh,*xshl;
    __half *vwh,*ckh,*yhf;
    unsigned char *vwc,*ckc,*yc;
    float *ckb,*cqb,*xsh,*wh2,*sout,*mp;
    cudaGetSymbolAddress((void**)&xhi,  g_xhi);
    cudaGetSymbolAddress((void**)&xlo,  g_xlo);
    cudaGetSymbolAddress((void**)&fwh,  g_fwh);
    cudaGetSymbolAddress((void**)&fwl,  g_fwl);
    cudaGetSymbolAddress((void**)&vwh,  g_vwh);
    cudaGetSymbolAddress((void**)&vwc,  g_vwc);
    cudaGetSymbolAddress((void**)&awh,  g_awh);
    cudaGetSymbolAddress((void**)&awl,  g_awl);
    cudaGetSymbolAddress((void**)&ckh,  g_ckh);
    cudaGetSymbolAddress((void**)&ckc,  g_ckc);
    cudaGetSymbolAddress((void**)&ckb,  g_ckb);
    cudaGetSymbolAddress((void**)&cqwh, g_cqwh);
    cudaGetSymbolAddress((void**)&cqwl, g_cqwl);
    cudaGetSymbolAddress((void**)&cqb,  g_cqb);
    cudaGetSymbolAddress((void**)&xsh,  g_xsh);
    cudaGetSymbolAddress((void**)&xshh, g_xshh);
    cudaGetSymbolAddress((void**)&xshl, g_xshl);
    cudaGetSymbolAddress((void**)&yhf,  g_yhf);
    cudaGetSymbolAddress((void**)&yc,   g_yc);
    cudaGetSymbolAddress((void**)&wh2,  g_wh2);
    cudaGetSymbolAddress((void**)&sout, g_sout);
    cudaGetSymbolAddress((void**)&mp,   g_mp);

    static int smem_set = 0;
    if (!smem_set) {
        cudaFuncSetAttribute(fc_bf16,    cudaFuncAttributeMaxDynamicSharedMemorySize, FC2_SMEM);
        cudaFuncSetAttribute(qk_fused,   cudaFuncAttributeMaxDynamicSharedMemorySize, QK_SMEM);
        cudaFuncSetAttribute(fused_attn, cudaFuncAttributeMaxDynamicSharedMemorySize, FU_SMEM);
        smem_set = 1;
    }

    // 0. operand prep (bf16 splits + fp16/fp8 for v_w)
    split_all<<<(SPL_TOT + 255)/256, 256>>>(x, xhi, xlo, fc_w, fwh, fwl,
                                            v_w, vwh, vwc, att_W, awh, awl);

    // 1. fold attention-layer weights into k/q projections
    combine_gemm<<<dim3(4, PAIRS, 2), 256>>>(a1w, a1b, k_w, k_b, ckh, ckc, ckb,
                                             a2w, a2b, q_w, q_b, cqwh, cqwl, cqb);

    // 2. shared fc + leakyrelu on gathered neighbors + targets (bf16-split)
    fc_bf16<<<dim3(R_/128, 4, S), 256, FC2_SMEM>>>(xhi, xlo, neigh, tgt, fwh, fwl,
                                                   fc_b, yhf, yc, xsh, xshh, xshl);

    // 3. wh2 = (lrelu(xsh@cq^T + cqb)) @ attW^T (bf16-split)
    qk_fused<<<dim3(Bq/128, PAIRS), 256, QK_SMEM>>>(xshh, xshl, cqwh, cqwl, cqb,
                                                    awh, awl, wh2);

    // 4. fused h1/vh GEMM + neighbor attention + residual (fp16 + fp8 corr)
    fused_attn<<<dim3(BM_/128, PAIRS), 512, FU_SMEM>>>(yhf, yc, ckh, ckc, ckb,
                                                       vwh, vwc, v_b, wh2, xsh, sout);

    // 5. semantic attention within each metapath
    semantic<2><<<Bq/4, 128>>>(sout,          ip1w,       ip1b,     ip2w,     mp,     Bq*D, D, KM*D);
    semantic<3><<<Bq/4, 128>>>(sout + 2*Bq*D, ip1w + H*D, ip1b + H, ip2w + H, mp + D, Bq*D, D, KM*D);

    // 6. semantic attention between metapaths -> final output
    semantic<2><<<Bq/4, 128>>>(mp, bp1w, bp1b, bp2w, out, D, KM*D, D);
}

// round 10
// speedup vs baseline: 1.1919x; 1.1919x over previous
#include <cuda_runtime.h>
#include <cuda_bf16.h>
#include <math.h>

#define NN    20000
#define IN_F  256
#define H     128
#define HN    4
#define S     5
#define KM    2
#define Bq    1024
#define M     16
#define D     512
#define ALPHA 0.2f
#define BM_   (Bq*M)      /* 16384 */
#define R_    (BM_ + Bq)  /* 17408 */
#define PAIRS (S*HN)      /* 20 */

#define KC    32          /* K halves per pipeline stage (fc) */
#define HS    40          /* fc smem row stride in halves */
#define QKS   136         /* full-K smem row stride in halves */

__constant__ int c_kofs[S] = {0,0,1,1,1};

// ---------------- scratch ----------------
__device__ __nv_bfloat16 g_xhi[NN*IN_F];
__device__ __nv_bfloat16 g_xlo[NN*IN_F];
__device__ __nv_bfloat16 g_fwh[S*4*H*IN_F];
__device__ __nv_bfloat16 g_fwl[S*4*H*IN_F];
__device__ __nv_bfloat16 g_vwh[PAIRS*H*H];
__device__ __nv_bfloat16 g_vwl[PAIRS*H*H];
__device__ __nv_bfloat16 g_awh[KM*HN*H*H];
__device__ __nv_bfloat16 g_awl[KM*HN*H*H];
__device__ __nv_bfloat16 g_ckwh[PAIRS*H*H];
__device__ __nv_bfloat16 g_ckwl[PAIRS*H*H];
__device__ float g_ckb[PAIRS*H];
__device__ __nv_bfloat16 g_cqwh[PAIRS*H*H];
__device__ __nv_bfloat16 g_cqwl[PAIRS*H*H];
__device__ float g_cqb[PAIRS*H];
__device__ float g_xsh[PAIRS*Bq*H];
__device__ __nv_bfloat16 g_xshh[PAIRS*Bq*H];
__device__ __nv_bfloat16 g_xshl[PAIRS*Bq*H];
__device__ __nv_bfloat16 g_yh[(size_t)PAIRS*BM_*H];
__device__ __nv_bfloat16 g_yl[(size_t)PAIRS*BM_*H];
__device__ float g_wh2[PAIRS*Bq*H];
__device__ float g_sout[S*Bq*D];
__device__ float g_mp[Bq*KM*D];

// ---------------- helpers ----------------
__device__ __forceinline__ void mma_bf16(float* d, const unsigned* a, const unsigned* b) {
    asm volatile(
      "mma.sync.aligned.m16n8k16.row.col.f32.bf16.bf16.f32 "
      "{%0,%1,%2,%3}, {%4,%5,%6,%7}, {%8,%9}, {%0,%1,%2,%3};\n"
      : "+f"(d[0]), "+f"(d[1]), "+f"(d[2]), "+f"(d[3])
      : "r"(a[0]), "r"(a[1]), "r"(a[2]), "r"(a[3]), "r"(b[0]), "r"(b[1]));
}
__device__ __forceinline__ void ldsm4(unsigned& r0, unsigned& r1, unsigned& r2, unsigned& r3,
                                      unsigned addr) {
    asm volatile("ldmatrix.sync.aligned.m8n8.x4.shared.b16 {%0,%1,%2,%3}, [%4];\n"
      : "=r"(r0), "=r"(r1), "=r"(r2), "=r"(r3) : "r"(addr));
}
__device__ __forceinline__ unsigned s2u(const void* p) {
    return (unsigned)__cvta_generic_to_shared(p);
}
__device__ __forceinline__ void split_bf(float x, __nv_bfloat16& h, __nv_bfloat16& l) {
    h = __float2bfloat16_rn(x);
    l = __float2bfloat16_rn(x - __bfloat162float(h));
}
__device__ __forceinline__ void cpa16(void* dst, const void* src) {
    unsigned d = (unsigned)__cvta_generic_to_shared(dst);
    asm volatile("cp.async.cg.shared.global [%0], [%1], 16;\n" :: "r"(d), "l"(src));
}
__device__ __forceinline__ void cp_commit() { asm volatile("cp.async.commit_group;\n"); }
__device__ __forceinline__ void cp_wait1() { asm volatile("cp.async.wait_group 1;\n"); }
__device__ __forceinline__ void cp_wait0() { asm volatile("cp.async.wait_group 0;\n"); }
__device__ __forceinline__ float lrelu_f(float v) { return v >= 0.f ? v : ALPHA*v; }

// term-major triple: 16 independent MMAs between acc reuses
#define MMA_TRIPLE(acc, ah, al, bh, bl)                         \
    _Pragma("unroll")                                           \
    for (int ni = 0; ni < 8; ++ni)                              \
        _Pragma("unroll")                                       \
        for (int mi = 0; mi < 2; ++mi)                          \
            mma_bf16(acc[mi][ni], ah[mi], bl[ni]);              \
    _Pragma("unroll")                                           \
    for (int ni = 0; ni < 8; ++ni)                              \
        _Pragma("unroll")                                       \
        for (int mi = 0; mi < 2; ++mi)                          \
            mma_bf16(acc[mi][ni], al[mi], bh[ni]);              \
    _Pragma("unroll")                                           \
    for (int ni = 0; ni < 8; ++ni)                              \
        _Pragma("unroll")                                       \
        for (int mi = 0; mi < 2; ++mi)                          \
            mma_bf16(acc[mi][ni], ah[mi], bh[ni]);

// ---------------- all fp32 -> bf16 hi/lo splits in ONE launch ----------------
#define SPL_N1 (NN*IN_F)
#define SPL_N2 (S*4*H*IN_F)
#define SPL_N3 (PAIRS*H*H)
#define SPL_N4 (KM*HN*H*H)
#define SPL_TOT (SPL_N1 + SPL_N2 + SPL_N3 + SPL_N4)
__global__ void split_all(
    const float* __restrict__ x,    __nv_bfloat16* __restrict__ xhi, __nv_bfloat16* __restrict__ xlo,
    const float* __restrict__ fcw,  __nv_bfloat16* __restrict__ fwh, __nv_bfloat16* __restrict__ fwl,
    const float* __restrict__ vw,   __nv_bfloat16* __restrict__ vwh, __nv_bfloat16* __restrict__ vwl,
    const float* __restrict__ attw, __nv_bfloat16* __restrict__ awh, __nv_bfloat16* __restrict__ awl)
{
    int i = blockIdx.x*256 + threadIdx.x;
    const float* in; __nv_bfloat16 *hi, *lo; int j;
    if (i < SPL_N1)                      { in = x;    hi = xhi; lo = xlo; j = i; }
    else if (i < SPL_N1+SPL_N2)          { in = fcw;  hi = fwh; lo = fwl; j = i - SPL_N1; }
    else if (i < SPL_N1+SPL_N2+SPL_N3)   { in = vw;   hi = vwh; lo = vwl; j = i - SPL_N1 - SPL_N2; }
    else if (i < SPL_TOT)                { in = attw; hi = awh; lo = awl; j = i - SPL_N1 - SPL_N2 - SPL_N3; }
    else return;
    split_bf(in[j], hi[j], lo[j]);
}

// ---------------- combined weights (both k and q in one launch, grid.z) -------
__global__ __launch_bounds__(256) void combine_gemm(
    const float* __restrict__ a1w, const float* __restrict__ a1b,
    const float* __restrict__ k_w, const float* __restrict__ k_b,
    __nv_bfloat16* __restrict__ ckh, __nv_bfloat16* __restrict__ ckl, float* __restrict__ ckb,
    const float* __restrict__ a2w, const float* __restrict__ a2b,
    const float* __restrict__ q_w, const float* __restrict__ q_b,
    __nv_bfloat16* __restrict__ cqh, __nv_bfloat16* __restrict__ cql, float* __restrict__ cqb)
{
    int ot = blockIdx.x, z = blockIdx.y, which = blockIdx.z, tid = threadIdx.x;
    const float* aw = which ? a2w : a1w;
    const float* ab = which ? a2b : a1b;
    const float* w  = which ? q_w : k_w;
    const float* wb = which ? q_b : k_b;
    __nv_bfloat16* cwh = which ? cqh : ckh;
    __nv_bfloat16* cwl = which ? cql : ckl;
    float* cb = which ? cqb : ckb;
    int kz = c_kofs[z/HN]*HN + (z % HN);
    const float* A = aw + ((size_t)kz*H + ot*32)*H;
    const float* W = w + (size_t)z*H*H;
    __shared__ float sa[32][36];
    __shared__ float sw[32][132];
    int tx = tid & 15, ty = tid >> 4;
    float acc[2][8];
    #pragma unroll
    for (int r = 0; r < 2; ++r)
        #pragma unroll
        for (int c = 0; c < 8; ++c) acc[r][c] = 0.f;
    for (int kc = 0; kc < 4; ++kc) {
        {
            int r = tid >> 3, c4 = (tid & 7)*4;
            *(float4*)&sa[r][c4] = *(const float4*)(A + r*H + kc*32 + c4);
        }
        #pragma unroll
        for (int i = 0; i < 4; ++i) {
            int idx = tid + i*256;
            int r = idx >> 5, c4 = (idx & 31)*4;
            *(float4*)&sw[r][c4] = *(const float4*)(W + (kc*32 + r)*H + c4);
        }
        __syncthreads();
        #pragma unroll 8
        for (int j = 0; j < 32; ++j) {
            float a0 = sa[ty*2][j], a1 = sa[ty*2+1][j];
            #pragma unroll
            for (int c = 0; c < 8; ++c) {
                float wv = sw[j][tx*8 + c];
                acc[0][c] += a0*wv;
                acc[1][c] += a1*wv;
            }
        }
        __syncthreads();
    }
    #pragma unroll
    for (int r = 0; r < 2; ++r)
        #pragma unroll
        for (int c = 0; c < 8; ++c) {
            size_t idx = ((size_t)z*H + ot*32 + ty*2 + r)*H + tx*8 + c;
            split_bf(acc[r][c], cwh[idx], cwl[idx]);
        }
    if (tid < 32) {
        int o = ot*32 + tid;
        float bacc = ab[kz*H + o];
        const float* arow = aw + ((size_t)kz*H + o)*H;
        const float* brow = wb + z*H;
        for (int j = 0; j < H; ++j) bacc += arow[j]*brow[j];
        cb[z*H + o] = bacc;
    }
}

// ================= fc GEMM (bf16-split TC, ldmatrix, gather) =================
#define FC2_SMEM (8*128*HS*2 + 512)
__global__ __launch_bounds__(256,2) void fc_bf16(
    const __nv_bfloat16* __restrict__ xh, const __nv_bfloat16* __restrict__ xl,
    const int* __restrict__ neigh, const int* __restrict__ tgt,
    const __nv_bfloat16* __restrict__ fwh, const __nv_bfloat16* __restrict__ fwl,
    const float* __restrict__ fcb,
    __nv_bfloat16* __restrict__ yh, __nv_bfloat16* __restrict__ yl,
    float* __restrict__ xsh,
    __nv_bfloat16* __restrict__ xshh, __nv_bfloat16* __restrict__ xshl)
{
    extern __shared__ __align__(16) char smc[];
    __nv_bfloat16* Ah = (__nv_bfloat16*)smc;
    __nv_bfloat16* Al = Ah + 2*128*HS;
    __nv_bfloat16* Bh = Al + 2*128*HS;
    __nv_bfloat16* Bl = Bh + 2*128*HS;
    int* rows = (int*)(Bl + 2*128*HS);
    int mt = blockIdx.x, nt = blockIdx.y, s = blockIdx.z;
    int tid = threadIdx.x;
    if (tid < 128) {
        int r = mt*128 + tid;
        rows[tid] = (r < BM_) ? neigh[s*BM_ + r] : tgt[r - BM_];
    }
    __syncthreads();
    size_t wb = ((size_t)s*512 + nt*128)*IN_F;

    auto prefetch = [&](int kc, int buf) {
        #pragma unroll
        for (int i = 0; i < 2; ++i) {
            int idx = tid + i*256;
            int r = idx >> 2, seg = (idx & 3)*8;
            int so = buf*128*HS + r*HS + seg;
            size_t ga = (size_t)rows[r]*IN_F + kc*KC + seg;
            size_t gb = wb + (size_t)r*IN_F + kc*KC + seg;
            cpa16(Ah + so, xh + ga);
            cpa16(Al + so, xl + ga);
            cpa16(Bh + so, fwh + gb);
            cpa16(Bl + so, fwl + gb);
        }
    };

    int w = tid >> 5, lane = tid & 31;
    int wm = (w & 3)*32, wn = (w >> 2)*64;
    int arow = lane & 15, acol = (lane & 16) ? 8 : 0;
    int bn = (lane & 7) + ((lane & 16) ? 8 : 0), bk = (lane & 8) ? 8 : 0;
    unsigned aAh = s2u(Ah), aAl = s2u(Al), aBh = s2u(Bh), aBl = s2u(Bl);

    float acc[2][8][4];
    #pragma unroll
    for (int i = 0; i < 2; ++i)
        #pragma unroll
        for (int j = 0; j < 8; ++j)
            #pragma unroll
            for (int e = 0; e < 4; ++e) acc[i][j][e] = 0.f;

    prefetch(0, 0); cp_commit();
    const int NCH = IN_F/KC;  // 8
    for (int kc = 0; kc < NCH; ++kc) {
        if (kc+1 < NCH) { prefetch(kc+1, (kc+1)&1); cp_commit(); cp_wait1(); }
        else            { cp_wait0(); }
        __syncthreads();
        unsigned bufo = (unsigned)((kc&1)*128*HS*2);
        #pragma unroll
        for (int kk = 0; kk < 2; ++kk) {
            int kb = kk*16;
            unsigned ah[2][4], al[2][4];
            #pragma unroll
            for (int mi = 0; mi < 2; ++mi) {
                unsigned off = bufo + (unsigned)(((wm + mi*16 + arow)*HS + kb + acol)*2);
                ldsm4(ah[mi][0], ah[mi][1], ah[mi][2], ah[mi][3], aAh + off);
                ldsm4(al[mi][0], al[mi][1], al[mi][2], al[mi][3], aAl + off);
            }
            unsigned bh[8][2], bl[8][2];
            #pragma unroll
            for (int nj = 0; nj < 4; ++nj) {
                unsigned off = bufo + (unsigned)(((wn + nj*16 + bn)*HS + kb + bk)*2);
                ldsm4(bh[nj*2][0], bh[nj*2][1], bh[nj*2+1][0], bh[nj*2+1][1], aBh + off);
                ldsm4(bl[nj*2][0], bl[nj*2][1], bl[nj*2+1][0], bl[nj*2+1][1], aBl + off);
            }
            MMA_TRIPLE(acc, ah, al, bh, bl);
        }
        __syncthreads();
    }

    int zp = s*HN + nt;
    int gid = lane >> 2, tig = lane & 3;
    float* Cs = (float*)smc;  // 128x132
    #pragma unroll
    for (int mi = 0; mi < 2; ++mi)
        #pragma unroll
        for (int ni = 0; ni < 8; ++ni)
            #pragma unroll
            for (int e = 0; e < 4; ++e) {
                int r = wm + mi*16 + gid + ((e >= 2) ? 8 : 0);
                int c = wn + ni*8 + 2*tig + (e & 1);
                Cs[r*132 + c] = lrelu_f(acc[mi][ni][e] + fcb[zp*H + c]);
            }
    __syncthreads();
    #pragma unroll
    for (int t = 0; t < 16; ++t) {
        int idx = tid + t*256;
        int rr = idx >> 5, c4 = (idx & 31)*4;
        float4 v = *(const float4*)(Cs + rr*132 + c4);
        int gr = mt*128 + rr;
        __nv_bfloat16 h0,h1,h2_,h3,l0,l1,l2,l3;
        split_bf(v.x,h0,l0); split_bf(v.y,h1,l1);
        split_bf(v.z,h2_,l2); split_bf(v.w,h3,l3);
        __nv_bfloat162 ph0 = {h0,h1}, ph1 = {h2_,h3};
        __nv_bfloat162 pl0 = {l0,l1}, pl1 = {l2,l3};
        uint2 uh, ul;
        uh.x = *(unsigned*)&ph0; uh.y = *(unsigned*)&ph1;
        ul.x = *(unsigned*)&pl0; ul.y = *(unsigned*)&pl1;
        if (gr < BM_) {
            size_t base = ((size_t)zp*BM_ + gr)*H + c4;
            *(uint2*)(yh + base) = uh;
            *(uint2*)(yl + base) = ul;
        } else {
            size_t base = ((size_t)zp*Bq + (gr - BM_))*H + c4;
            *(float4*)(xsh + base) = v;
            *(uint2*)(xshh + base) = uh;
            *(uint2*)(xshl + base) = ul;
        }
    }
}

// ================= qk_fused (mma.sync + ldmatrix) =================
#define QK_SMEM (4*128*QKS*2)
__global__ __launch_bounds__(256,1) void qk_fused(
    const __nv_bfloat16* __restrict__ xshh, const __nv_bfloat16* __restrict__ xshl,
    const __nv_bfloat16* __restrict__ cqh, const __nv_bfloat16* __restrict__ cql,
    const float* __restrict__ cqb,
    const __nv_bfloat16* __restrict__ awh, const __nv_bfloat16* __restrict__ awl,
    float* __restrict__ wh2)
{
    extern __shared__ __align__(16) char smc[];
    __nv_bfloat16* Axh = (__nv_bfloat16*)smc;
    __nv_bfloat16* Axl = Axh + 128*QKS;
    __nv_bfloat16* Bh  = Axl + 128*QKS;
    __nv_bfloat16* Bl  = Bh + 128*QKS;
    int mt = blockIdx.x, z = blockIdx.y;
    int tid = threadIdx.x;
    int kz = c_kofs[z/HN]*HN + (z % HN);

    const __nv_bfloat16* Agh = xshh + ((size_t)z*Bq + mt*128)*H;
    const __nv_bfloat16* Agl = xshl + ((size_t)z*Bq + mt*128)*H;
    const __nv_bfloat16* Bgh = cqh + (size_t)z*H*H;
    const __nv_bfloat16* Bgl = cql + (size_t)z*H*H;

    #pragma unroll
    for (int i = 0; i < 8; ++i) {
        int idx = tid + i*256;
        int r = idx >> 4, seg = (idx & 15)*8;
        cpa16(Axh + r*QKS + seg, Agh + (size_t)r*H + seg);
        cpa16(Axl + r*QKS + seg, Agl + (size_t)r*H + seg);
        cpa16(Bh + r*QKS + seg, Bgh + (size_t)r*H + seg);
        cpa16(Bl + r*QKS + seg, Bgl + (size_t)r*H + seg);
    }
    cp_commit(); cp_wait0();
    __syncthreads();

    int w = tid >> 5, lane = tid & 31, gid = lane >> 2, tig = lane & 3;
    int wm = (w & 3)*32, wn = (w >> 2)*64;
    int arow = lane & 15, acol = (lane & 16) ? 8 : 0;
    int bn = (lane & 7) + ((lane & 16) ? 8 : 0), bk = (lane & 8) ? 8 : 0;
    unsigned aAh = s2u(Axh), aAl = s2u(Axl), aBh = s2u(Bh), aBl = s2u(Bl);
    float acc[2][8][4];

    auto run_gemm = [&]() {
        #pragma unroll
        for (int i = 0; i < 2; ++i)
            #pragma unroll
            for (int j = 0; j < 8; ++j)
                #pragma unroll
                for (int e = 0; e < 4; ++e) acc[i][j][e] = 0.f;
        #pragma unroll
        for (int kk = 0; kk < 8; ++kk) {
            int kb = kk*16;
            unsigned ah[2][4], al[2][4];
            #pragma unroll
            for (int mi = 0; mi < 2; ++mi) {
                unsigned off = (unsigned)(((wm + mi*16 + arow)*QKS + kb + acol)*2);
                ldsm4(ah[mi][0], ah[mi][1], ah[mi][2], ah[mi][3], aAh + off);
                ldsm4(al[mi][0], al[mi][1], al[mi][2], al[mi][3], aAl + off);
            }
            unsigned bh[8][2], bl[8][2];
            #pragma unroll
            for (int nj = 0; nj < 4; ++nj) {
                unsigned off = (unsigned)(((wn + nj*16 + bn)*QKS + kb + bk)*2);
                ldsm4(bh[nj*2][0], bh[nj*2][1], bh[nj*2+1][0], bh[nj*2+1][1], aBh + off);
                ldsm4(bl[nj*2][0], bl[nj*2][1], bl[nj*2+1][0], bl[nj*2+1][1], aBl + off);
            }
            MMA_TRIPLE(acc, ah, al, bh, bl);
        }
    };

    run_gemm();
    __syncthreads();
    #pragma unroll
    for (int mi = 0; mi < 2; ++mi)
        #pragma unroll
        for (int ni = 0; ni < 8; ++ni)
            #pragma unroll
            for (int e = 0; e < 4; ++e) {
                int r = wm + mi*16 + gid + ((e >= 2) ? 8 : 0);
                int c = wn + ni*8 + 2*tig + (e & 1);
                float v = lrelu_f(acc[mi][ni][e] + cqb[z*H + c]);
                __nv_bfloat16 hh, ll;
                split_bf(v, hh, ll);
                Axh[r*QKS + c] = hh;
                Axl[r*QKS + c] = ll;
            }
    const __nv_bfloat16* Wgh = awh + (size_t)kz*H*H;
    const __nv_bfloat16* Wgl = awl + (size_t)kz*H*H;
    #pragma unroll
    for (int i = 0; i < 8; ++i) {
        int idx = tid + i*256;
        int r = idx >> 4, seg = (idx & 15)*8;
        cpa16(Bh + r*QKS + seg, Wgh + (size_t)r*H + seg);
        cpa16(Bl + r*QKS + seg, Wgl + (size_t)r*H + seg);
    }
    cp_commit(); cp_wait0();
    __syncthreads();

    run_gemm();
    #pragma unroll
    for (int mi = 0; mi < 2; ++mi)
        #pragma unroll
        for (int ni = 0; ni < 8; ++ni)
            #pragma unroll
            for (int e = 0; e < 4; ++e) {
                int r = wm + mi*16 + gid + ((e >= 2) ? 8 : 0);
                int c = wn + ni*8 + 2*tig + (e & 1);
                wh2[((size_t)z*Bq + mt*128 + r)*H + c] = acc[mi][ni][e];
            }
}

// ================= fused h1/vh GEMM + attention (single-shot K) =================
#define FU_A_BYTES (128*QKS*2)
#define FU_B_BYTES (256*QKS*2)
#define FU_SMEM    (2*FU_A_BYTES + 2*FU_B_BYTES)   /* 208896 */
__global__ __launch_bounds__(512,1) void fused_attn(
    const __nv_bfloat16* __restrict__ yhg, const __nv_bfloat16* __restrict__ ylg,
    const __nv_bfloat16* __restrict__ ckh, const __nv_bfloat16* __restrict__ ckl,
    const float* __restrict__ ckb,
    const __nv_bfloat16* __restrict__ vwh, const __nv_bfloat16* __restrict__ vwl,
    const float* __restrict__ vb,  const float* __restrict__ wh2,
    const float* __restrict__ xsh, float* __restrict__ sout)
{
    extern __shared__ __align__(16) char smc[];
    float* sm = (float*)smc;
    __nv_bfloat16* Ah = (__nv_bfloat16*)smc;       // [128*QKS]
    __nv_bfloat16* Al = Ah + 128*QKS;
    __nv_bfloat16* Bh = Al + 128*QKS;              // [256*QKS]
    __nv_bfloat16* Bl = Bh + 256*QKS;
    int mt = blockIdx.x, z = blockIdx.y;
    int tid = threadIdx.x;

    const __nv_bfloat16* Agh = yhg + ((size_t)z*BM_ + mt*128)*H;
    const __nv_bfloat16* Agl = ylg + ((size_t)z*BM_ + mt*128)*H;
    size_t wkb = (size_t)z*H*H;

    #pragma unroll
    for (int i = 0; i < 4; ++i) {
        int idx = tid + i*512;
        int r = idx >> 4, seg = (idx & 15)*8;
        cpa16(Ah + r*QKS + seg, Agh + (size_t)r*H + seg);
        cpa16(Al + r*QKS + seg, Agl + (size_t)r*H + seg);
    }
    #pragma unroll
    for (int i = 0; i < 8; ++i) {
        int idx = tid + i*512;
        int n = idx >> 4, seg = (idx & 15)*8;
        const __nv_bfloat16* sh = (n < 128) ? (ckh + wkb + (size_t)n*H)
                                            : (vwh + wkb + (size_t)(n-128)*H);
        const __nv_bfloat16* sl = (n < 128) ? (ckl + wkb + (size_t)n*H)
                                            : (vwl + wkb + (size_t)(n-128)*H);
        cpa16(Bh + n*QKS + seg, sh + seg);
        cpa16(Bl + n*QKS + seg, sl + seg);
    }
    cp_commit(); cp_wait0();
    __syncthreads();

    int w = tid >> 5, lane = tid & 31, gid = lane >> 2, tig = lane & 3;
    int wm = (w & 3)*32, wn = (w >> 2)*64;
    int arow = lane & 15, acol = (lane & 16) ? 8 : 0;
    int bn = (lane & 7) + ((lane & 16) ? 8 : 0), bk = (lane & 8) ? 8 : 0;
    unsigned aAh = s2u(Ah), aAl = s2u(Al), aBh = s2u(Bh), aBl = s2u(Bl);

    float acc[2][8][4];
    #pragma unroll
    for (int i = 0; i < 2; ++i)
        #pragma unroll
        for (int j = 0; j < 8; ++j)
            #pragma unroll
            for (int e = 0; e < 4; ++e) acc[i][j][e] = 0.f;

    #pragma unroll
    for (int kk = 0; kk < 8; ++kk) {
        int kb = kk*16;
        unsigned ah[2][4], al[2][4];
        #pragma unroll
        for (int mi = 0; mi < 2; ++mi) {
            unsigned off = (unsigned)(((wm + mi*16 + arow)*QKS + kb + acol)*2);
            ldsm4(ah[mi][0], ah[mi][1], ah[mi][2], ah[mi][3], aAh + off);
            ldsm4(al[mi][0], al[mi][1], al[mi][2], al[mi][3], aAl + off);
        }
        unsigned bh[8][2], bl[8][2];
        #pragma unroll
        for (int nj = 0; nj < 4; ++nj) {
            unsigned off = (unsigned)(((wn + nj*16 + bn)*QKS + kb + bk)*2);
            ldsm4(bh[nj*2][0], bh[nj*2][1], bh[nj*2+1][0], bh[nj*2+1][1], aBh + off);
            ldsm4(bl[nj*2][0], bl[nj*2][1], bl[nj*2+1][0], bl[nj*2+1][1], aBl + off);
        }
        MMA_TRIPLE(acc, ah, al, bh, bl);
    }
    __syncthreads();   // all smem reads done before epilogue aliasing

    float* SP  = sm;                 // [128][132]  h1 (lrelu+bias)
    float* SV  = SP + 128*132;       // [128][132]  vh (+bias)
    float* SW  = SV + 128*132;       // [8][128]    wh2 rows
    float* SSC = SW + 8*128;         // [128] scores
    float* SE  = SSC + 128;          // [128] softmax weights

    #pragma unroll
    for (int mi = 0; mi < 2; ++mi)
        #pragma unroll
        for (int ni = 0; ni < 8; ++ni)
            #pragma unroll
            for (int e = 0; e < 4; ++e) {
                int r = wm + mi*16 + gid + ((e >= 2) ? 8 : 0);
                int c = wn + ni*8 + 2*tig + (e & 1);
                float v = acc[mi][ni][e];
                if (c < 128) SP[r*132 + c] = lrelu_f(v + ckb[z*H + c]);
                else         SV[r*132 + (c-128)] = v + vb[z*H + (c-128)];
            }
    #pragma unroll
    for (int t = 0; t < 2; ++t) {
        int idx = tid + t*512;
        int bl = idx >> 7, o = idx & 127;
        SW[idx] = wh2[((size_t)z*Bq + mt*8 + bl)*H + o];
    }
    __syncthreads();

    #pragma unroll
    for (int i = 0; i < 8; ++i) {
        int rr = w*8 + i;
        const float* wrow = SW + (rr >> 4)*128;
        float p = 0.f;
        #pragma unroll
        for (int o = 0; o < 128; o += 32) p += SP[rr*132 + o + lane]*wrow[o + lane];
        #pragma unroll
        for (int d_ = 16; d_ > 0; d_ >>= 1) p += __shfl_xor_sync(0xffffffffu, p, d_);
        if (lane == 0) SSC[rr] = p;
    }
    __syncthreads();
    if (tid < 8) {
        float mx = -1e30f;
        #pragma unroll
        for (int m = 0; m < M; ++m) mx = fmaxf(mx, SSC[tid*M + m]);
        float es[M], sum = 0.f;
        #pragma unroll
        for (int m = 0; m < M; ++m) { es[m] = expf(SSC[tid*M + m] - mx); sum += es[m]; }
        float inv = 1.f/sum;
        #pragma unroll
        for (int m = 0; m < M; ++m) SE[tid*M + m] = es[m]*inv;
    }
    __syncthreads();

    int s = z/HN, hh = z%HN;
    #pragma unroll
    for (int t = 0; t < 2; ++t) {
        int idx = tid + t*512;
        int bl = idx >> 7, o = idx & 127;
        float a = 0.f;
        #pragma unroll
        for (int m = 0; m < M; ++m) {
            float v = SV[(bl*M + m)*132 + o]*SE[bl*M + m];
            a += (v >= 0.f) ? v : ALPHA*v;
        }
        int b = mt*8 + bl;
        sout[((size_t)s*Bq + b)*D + hh*H + o] =
            0.5f*(xsh[((size_t)z*Bq + b)*H + o] + a);
    }
}

// ---------------- semantic attention (smem-tiled weights, 8 targets/block) -----
#define SEM_SMEM(P) ((8*(P)*D + 64*132 + 8*(P)*132 + 32)*4)
template<int P>
__global__ __launch_bounds__(128) void semantic(
    const float* __restrict__ zin, const float* __restrict__ p1w,
    const float* __restrict__ p1b, const float* __restrict__ p2w,
    float* __restrict__ outp, int in_pstride, int in_bstride, int out_bstride)
{
    extern __shared__ __align__(16) float sem[];
    float* zs   = sem;                         // [8P][512]
    float* pwT  = sem + 8*P*D;                 // [64][132] transposed chunk
    float* sred = pwT + 64*132;                // [8P][132]
    float* ssc  = sred + 8*P*132;              // [8P]
    int b0 = blockIdx.x*8, tid = threadIdx.x;

    for (int idx = tid; idx < 8*P*(D/4); idx += 128) {
        int d4 = idx & (D/4 - 1); int rp = idx / (D/4);
        int p = rp % P, bl = rp / P;
        *(float4*)&zs[(bl*P+p)*D + d4*4] =
            *(const float4*)(zin + (size_t)(b0+bl)*in_bstride + (size_t)p*in_pstride + d4*4);
    }
    __syncthreads();

    float acc[8][P];
    #pragma unroll
    for (int bl = 0; bl < 8; ++bl)
        #pragma unroll
        for (int p = 0; p < P; ++p) acc[bl][p] = 0.f;

    for (int d0 = 0; d0 < D; d0 += 64) {
        #pragma unroll
        for (int i = 0; i < 16; ++i) {         // 2048 f4 loads of p1w chunk
            int idx = tid + i*128;
            int r = idx >> 4, c4 = (idx & 15)*4;
            float4 v = *(const float4*)(p1w + (size_t)r*D + d0 + c4);
            pwT[c4*132 + r]     = v.x;
            pwT[(c4+1)*132 + r] = v.y;
            pwT[(c4+2)*132 + r] = v.z;
            pwT[(c4+3)*132 + r] = v.w;
        }
        __syncthreads();
        #pragma unroll 4
        for (int dd = 0; dd < 64; dd += 4) {
            float w0 = pwT[dd*132 + tid],     w1 = pwT[(dd+1)*132 + tid];
            float w2 = pwT[(dd+2)*132 + tid], w3 = pwT[(dd+3)*132 + tid];
            #pragma unroll
            for (int bl = 0; bl < 8; ++bl)
                #pragma unroll
                for (int p = 0; p < P; ++p) {
                    float4 zv = *(const float4*)&zs[(bl*P+p)*D + d0 + dd];
                    acc[bl][p] += w0*zv.x + w1*zv.y + w2*zv.z + w3*zv.w;
                }
        }
        __syncthreads();
    }

    float bias = p1b[tid], p2 = p2w[tid];
    #pragma unroll
    for (int bl = 0; bl < 8; ++bl)
        #pragma unroll
        for (int p = 0; p < P; ++p)
            sred[(bl*P+p)*132 + tid] = tanhf(acc[bl][p] + bias)*p2;
    __syncthreads();
    if (tid < 8*P) {
        float s_ = 0.f;
        for (int o = 0; o < H; ++o) s_ += sred[tid*132 + o];
        ssc[tid] = s_;
    }
    __syncthreads();
    if (tid < 8) {
        float mx = -1e30f;
        #pragma unroll
        for (int p = 0; p < P; ++p) mx = fmaxf(mx, ssc[tid*P + p]);
        float e[P]; float esum = 0.f;
        #pragma unroll
        for (int p = 0; p < P; ++p) { e[p] = expf(ssc[tid*P + p] - mx); esum += e[p]; }
        float inv = 1.f/esum;
        #pragma unroll
        for (int p = 0; p < P; ++p) ssc[tid*P + p] = e[p]*inv;
    }
    __syncthreads();
    for (int idx = tid; idx < 8*(D/4); idx += 128) {
        int d4 = (idx & (D/4 - 1))*4; int bl = idx / (D/4);
        float4 o = {0.f, 0.f, 0.f, 0.f};
        #pragma unroll
        for (int p = 0; p < P; ++p) {
            float e = ssc[bl*P + p];
            float4 zv = *(const float4*)&zs[(bl*P+p)*D + d4];
            o.x += e*zv.x; o.y += e*zv.y; o.z += e*zv.z; o.w += e*zv.w;
        }
        *(float4*)(outp + (size_t)(b0+bl)*out_bstride + d4) = o;
    }
}

extern "C" void kernel_launch(void* const* d_in, const int* in_sizes, int n_in,
                              void* d_out, int out_size)
{
    const float* x     = (const float*)d_in[0];
    const int*   tgt   = (const int*)  d_in[1];
    const int*   neigh = (const int*)  d_in[2];
    const float* fc_w  = (const float*)d_in[3];
    const float* fc_b  = (const float*)d_in[4];
    const float* q_w   = (const float*)d_in[5];
    const float* q_b   = (const float*)d_in[6];
    const float* k_w   = (const float*)d_in[7];
    const float* k_b   = (const float*)d_in[8];
    const float* v_w   = (const float*)d_in[9];
    const float* v_b   = (const float*)d_in[10];
    const float* att_W = (const float*)d_in[11];
    const float* a1w   = (const float*)d_in[12];
    const float* a1b   = (const float*)d_in[13];
    const float* a2w   = (const float*)d_in[14];
    const float* a2b   = (const float*)d_in[15];
    const float* ip1w  = (const float*)d_in[16];
    const float* ip1b  = (const float*)d_in[17];
    const float* ip2w  = (const float*)d_in[18];
    const float* bp1w  = (const float*)d_in[19];
    const float* bp1b  = (const float*)d_in[20];
    const float* bp2w  = (const float*)d_in[21];
    float* out = (float*)d_out;

    __nv_bfloat16 *xhi,*xlo,*fwh,*fwl,*vwh,*vwl,*awh,*awl,*ckwh,*ckwl,*cqwh,*cqwl,*yh,*yl,*xshh,*xshl;
    float *ckb,*cqb,*xsh,*wh2,*sout,*mp;
    cudaGetSymbolAddress((void**)&xhi,  g_xhi);
    cudaGetSymbolAddress((void**)&xlo,  g_xlo);
    cudaGetSymbolAddress((void**)&fwh,  g_fwh);
    cudaGetSymbolAddress((void**)&fwl,  g_fwl);
    cudaGetSymbolAddress((void**)&vwh,  g_vwh);
    cudaGetSymbolAddress((void**)&vwl,  g_vwl);
    cudaGetSymbolAddress((void**)&awh,  g_awh);
    cudaGetSymbolAddress((void**)&awl,  g_awl);
    cudaGetSymbolAddress((void**)&ckwh, g_ckwh);
    cudaGetSymbolAddress((void**)&ckwl, g_ckwl);
    cudaGetSymbolAddress((void**)&ckb,  g_ckb);
    cudaGetSymbolAddress((void**)&cqwh, g_cqwh);
    cudaGetSymbolAddress((void**)&cqwl, g_cqwl);
    cudaGetSymbolAddress((void**)&cqb,  g_cqb);
    cudaGetSymbolAddress((void**)&xsh,  g_xsh);
    cudaGetSymbolAddress((void**)&xshh, g_xshh);
    cudaGetSymbolAddress((void**)&xshl, g_xshl);
    cudaGetSymbolAddress((void**)&yh,   g_yh);
    cudaGetSymbolAddress((void**)&yl,   g_yl);
    cudaGetSymbolAddress((void**)&wh2,  g_wh2);
    cudaGetSymbolAddress((void**)&sout, g_sout);
    cudaGetSymbolAddress((void**)&mp,   g_mp);

    static int smem_set = 0;
    if (!smem_set) {
        cudaFuncSetAttribute(fc_bf16,     cudaFuncAttributeMaxDynamicSharedMemorySize, FC2_SMEM);
        cudaFuncSetAttribute(qk_fused,    cudaFuncAttributeMaxDynamicSharedMemorySize, QK_SMEM);
        cudaFuncSetAttribute(fused_attn,  cudaFuncAttributeMaxDynamicSharedMemorySize, FU_SMEM);
        cudaFuncSetAttribute(semantic<2>, cudaFuncAttributeMaxDynamicSharedMemorySize, SEM_SMEM(2));
        cudaFuncSetAttribute(semantic<3>, cudaFuncAttributeMaxDynamicSharedMemorySize, SEM_SMEM(3));
        smem_set = 1;
    }

    // 0. precompute all bf16 hi/lo splits in one launch
    split_all<<<(SPL_TOT + 255)/256, 256>>>(x, xhi, xlo, fc_w, fwh, fwl,
                                            v_w, vwh, vwl, att_W, awh, awl);

    // 1. fold attention-layer weights into k/q projections (one launch, grid.z=2)
    combine_gemm<<<dim3(4, PAIRS, 2), 256>>>(a1w, a1b, k_w, k_b, ckwh, ckwl, ckb,
                                             a2w, a2b, q_w, q_b, cqwh, cqwl, cqb);

    // 2. shared fc + leakyrelu on gathered neighbors + targets
    fc_bf16<<<dim3(R_/128, 4, S), 256, FC2_SMEM>>>(xhi, xlo, neigh, tgt, fwh, fwl,
                                                   fc_b, yh, yl, xsh, xshh, xshl);

    // 3. wh2 = (lrelu(xsh@cq^T + cqb)) @ attW^T
    qk_fused<<<dim3(Bq/128, PAIRS), 256, QK_SMEM>>>(xshh, xshl, cqwh, cqwl, cqb,
                                                    awh, awl, wh2);

    // 4. fused h1/vh GEMM + neighbor attention + residual
    fused_attn<<<dim3(BM_/128, PAIRS), 512, FU_SMEM>>>(yh, yl, ckwh, ckwl, ckb,
                                                       vwh, vwl, v_b, wh2, xsh, sout);

    // 5. semantic attention within each metapath
    semantic<2><<<Bq/8, 128, SEM_SMEM(2)>>>(sout,          ip1w,       ip1b,     ip2w,     mp,     Bq*D, D, KM*D);
    semantic<3><<<Bq/8, 128, SEM_SMEM(3)>>>(sout + 2*Bq*D, ip1w + H*D, ip1b + H, ip2w + H, mp + D, Bq*D, D, KM*D);

    // 6. semantic attention between metapaths -> final output
    semantic<2><<<Bq/8, 128, SEM_SMEM(2)>>>(mp, bp1w, bp1b, bp2w, out, D, KM*D, D);
}

// round 11
// speedup vs baseline: 1.1946x; 1.0023x over previous
#include <cuda_runtime.h>
#include <cuda_bf16.h>
#include <math.h>

#define NN    20000
#define IN_F  256
#define H     128
#define HN    4
#define S     5
#define KM    2
#define Bq    1024
#define M     16
#define D     512
#define ALPHA 0.2f
#define BM_   (Bq*M)      /* 16384 */
#define R_    (BM_ + Bq)  /* 17408 */
#define PAIRS (S*HN)      /* 20 */

#define KC    32          /* K halves per pipeline stage (fc) */
#define HS    40          /* fc smem row stride in halves */
#define QKS   136         /* full-K smem row stride in halves */

__constant__ int c_kofs[S] = {0,0,1,1,1};

// ---------------- scratch ----------------
__device__ __nv_bfloat16 g_xhi[NN*IN_F];
__device__ __nv_bfloat16 g_xlo[NN*IN_F];
__device__ __nv_bfloat16 g_fwh[S*4*H*IN_F];
__device__ __nv_bfloat16 g_fwl[S*4*H*IN_F];
__device__ __nv_bfloat16 g_vwh[PAIRS*H*H];
__device__ __nv_bfloat16 g_vwl[PAIRS*H*H];
__device__ __nv_bfloat16 g_awh[KM*HN*H*H];
__device__ __nv_bfloat16 g_awl[KM*HN*H*H];
__device__ __nv_bfloat16 g_ckwh[PAIRS*H*H];
__device__ __nv_bfloat16 g_ckwl[PAIRS*H*H];
__device__ float g_ckb[PAIRS*H];
__device__ __nv_bfloat16 g_cqwh[PAIRS*H*H];
__device__ __nv_bfloat16 g_cqwl[PAIRS*H*H];
__device__ float g_cqb[PAIRS*H];
__device__ float g_xsh[PAIRS*Bq*H];
__device__ __nv_bfloat16 g_xshh[PAIRS*Bq*H];
__device__ __nv_bfloat16 g_xshl[PAIRS*Bq*H];
__device__ __nv_bfloat16 g_yh[(size_t)PAIRS*BM_*H];
__device__ __nv_bfloat16 g_yl[(size_t)PAIRS*BM_*H];
__device__ float g_wh2[PAIRS*Bq*H];
__device__ float g_sout[S*Bq*D];
__device__ float g_mp[Bq*KM*D];

// ---------------- helpers ----------------
__device__ __forceinline__ void mma_bf16(float* d, const unsigned* a, const unsigned* b) {
    asm volatile(
      "mma.sync.aligned.m16n8k16.row.col.f32.bf16.bf16.f32 "
      "{%0,%1,%2,%3}, {%4,%5,%6,%7}, {%8,%9}, {%0,%1,%2,%3};\n"
      : "+f"(d[0]), "+f"(d[1]), "+f"(d[2]), "+f"(d[3])
      : "r"(a[0]), "r"(a[1]), "r"(a[2]), "r"(a[3]), "r"(b[0]), "r"(b[1]));
}
__device__ __forceinline__ void ldsm4(unsigned& r0, unsigned& r1, unsigned& r2, unsigned& r3,
                                      unsigned addr) {
    asm volatile("ldmatrix.sync.aligned.m8n8.x4.shared.b16 {%0,%1,%2,%3}, [%4];\n"
      : "=r"(r0), "=r"(r1), "=r"(r2), "=r"(r3) : "r"(addr));
}
__device__ __forceinline__ unsigned s2u(const void* p) {
    return (unsigned)__cvta_generic_to_shared(p);
}
__device__ __forceinline__ void split_bf(float x, __nv_bfloat16& h, __nv_bfloat16& l) {
    h = __float2bfloat16_rn(x);
    l = __float2bfloat16_rn(x - __bfloat162float(h));
}
__device__ __forceinline__ void cpa16(void* dst, const void* src) {
    unsigned d = (unsigned)__cvta_generic_to_shared(dst);
    asm volatile("cp.async.cg.shared.global [%0], [%1], 16;\n" :: "r"(d), "l"(src));
}
__device__ __forceinline__ void cp_commit() { asm volatile("cp.async.commit_group;\n"); }
__device__ __forceinline__ void cp_wait1() { asm volatile("cp.async.wait_group 1;\n"); }
__device__ __forceinline__ void cp_wait0() { asm volatile("cp.async.wait_group 0;\n"); }
__device__ __forceinline__ float lrelu_f(float v) { return v >= 0.f ? v : ALPHA*v; }

// half-N term-major step: B frags for 32 cols live at a time (reg pressure < 128)
// acc: [2][8][4]; ah/al: [2][4]; STRIDE in halves; kb in halves; nh in {0,1}
#define MMA_HALF_STEP(acc, ah, al, aBh, aBl, STRIDE, kb, bkv, bnv, wnv, nh)       \
    {                                                                             \
        unsigned bh_[4][2], bl_[4][2];                                            \
        _Pragma("unroll")                                                         \
        for (int nj = 0; nj < 2; ++nj) {                                          \
            unsigned off_ = (unsigned)((((wnv) + (nh)*32 + nj*16 + (bnv))*(STRIDE) + (kb) + (bkv))*2); \
            ldsm4(bh_[nj*2][0], bh_[nj*2][1], bh_[nj*2+1][0], bh_[nj*2+1][1], (aBh) + off_); \
            ldsm4(bl_[nj*2][0], bl_[nj*2][1], bl_[nj*2+1][0], bl_[nj*2+1][1], (aBl) + off_); \
        }                                                                         \
        _Pragma("unroll")                                                         \
        for (int ni = 0; ni < 4; ++ni)                                            \
            _Pragma("unroll")                                                     \
            for (int mi = 0; mi < 2; ++mi)                                        \
                mma_bf16(acc[mi][(nh)*4+ni], ah[mi], bl_[ni]);                    \
        _Pragma("unroll")                                                         \
        for (int ni = 0; ni < 4; ++ni)                                            \
            _Pragma("unroll")                                                     \
            for (int mi = 0; mi < 2; ++mi)                                        \
                mma_bf16(acc[mi][(nh)*4+ni], al[mi], bh_[ni]);                    \
        _Pragma("unroll")                                                         \
        for (int ni = 0; ni < 4; ++ni)                                            \
            _Pragma("unroll")                                                     \
            for (int mi = 0; mi < 2; ++mi)                                        \
                mma_bf16(acc[mi][(nh)*4+ni], ah[mi], bh_[ni]);                    \
    }

// ---------------- all fp32 -> bf16 hi/lo splits in ONE launch ----------------
#define SPL_N1 (NN*IN_F)
#define SPL_N2 (S*4*H*IN_F)
#define SPL_N3 (PAIRS*H*H)
#define SPL_N4 (KM*HN*H*H)
#define SPL_TOT (SPL_N1 + SPL_N2 + SPL_N3 + SPL_N4)
__global__ void split_all(
    const float* __restrict__ x,    __nv_bfloat16* __restrict__ xhi, __nv_bfloat16* __restrict__ xlo,
    const float* __restrict__ fcw,  __nv_bfloat16* __restrict__ fwh, __nv_bfloat16* __restrict__ fwl,
    const float* __restrict__ vw,   __nv_bfloat16* __restrict__ vwh, __nv_bfloat16* __restrict__ vwl,
    const float* __restrict__ attw, __nv_bfloat16* __restrict__ awh, __nv_bfloat16* __restrict__ awl)
{
    int i = blockIdx.x*256 + threadIdx.x;
    const float* in; __nv_bfloat16 *hi, *lo; int j;
    if (i < SPL_N1)                      { in = x;    hi = xhi; lo = xlo; j = i; }
    else if (i < SPL_N1+SPL_N2)          { in = fcw;  hi = fwh; lo = fwl; j = i - SPL_N1; }
    else if (i < SPL_N1+SPL_N2+SPL_N3)   { in = vw;   hi = vwh; lo = vwl; j = i - SPL_N1 - SPL_N2; }
    else if (i < SPL_TOT)                { in = attw; hi = awh; lo = awl; j = i - SPL_N1 - SPL_N2 - SPL_N3; }
    else return;
    split_bf(in[j], hi[j], lo[j]);
}

// ---------------- combined weights (both k and q in one launch, grid.z) -------
__global__ __launch_bounds__(256) void combine_gemm(
    const float* __restrict__ a1w, const float* __restrict__ a1b,
    const float* __restrict__ k_w, const float* __restrict__ k_b,
    __nv_bfloat16* __restrict__ ckh, __nv_bfloat16* __restrict__ ckl, float* __restrict__ ckb,
    const float* __restrict__ a2w, const float* __restrict__ a2b,
    const float* __restrict__ q_w, const float* __restrict__ q_b,
    __nv_bfloat16* __restrict__ cqh, __nv_bfloat16* __restrict__ cql, float* __restrict__ cqb)
{
    int ot = blockIdx.x, z = blockIdx.y, which = blockIdx.z, tid = threadIdx.x;
    const float* aw = which ? a2w : a1w;
    const float* ab = which ? a2b : a1b;
    const float* w  = which ? q_w : k_w;
    const float* wb = which ? q_b : k_b;
    __nv_bfloat16* cwh = which ? cqh : ckh;
    __nv_bfloat16* cwl = which ? cql : ckl;
    float* cb = which ? cqb : ckb;
    int kz = c_kofs[z/HN]*HN + (z % HN);
    const float* A = aw + ((size_t)kz*H + ot*32)*H;
    const float* W = w + (size_t)z*H*H;
    __shared__ float sa[32][36];
    __shared__ float sw[32][132];
    int tx = tid & 15, ty = tid >> 4;
    float acc[2][8];
    #pragma unroll
    for (int r = 0; r < 2; ++r)
        #pragma unroll
        for (int c = 0; c < 8; ++c) acc[r][c] = 0.f;
    for (int kc = 0; kc < 4; ++kc) {
        {
            int r = tid >> 3, c4 = (tid & 7)*4;
            *(float4*)&sa[r][c4] = *(const float4*)(A + r*H + kc*32 + c4);
        }
        #pragma unroll
        for (int i = 0; i < 4; ++i) {
            int idx = tid + i*256;
            int r = idx >> 5, c4 = (idx & 31)*4;
            *(float4*)&sw[r][c4] = *(const float4*)(W + (kc*32 + r)*H + c4);
        }
        __syncthreads();
        #pragma unroll 8
        for (int j = 0; j < 32; ++j) {
            float a0 = sa[ty*2][j], a1 = sa[ty*2+1][j];
            #pragma unroll
            for (int c = 0; c < 8; ++c) {
                float wv = sw[j][tx*8 + c];
                acc[0][c] += a0*wv;
                acc[1][c] += a1*wv;
            }
        }
        __syncthreads();
    }
    #pragma unroll
    for (int r = 0; r < 2; ++r)
        #pragma unroll
        for (int c = 0; c < 8; ++c) {
            size_t idx = ((size_t)z*H + ot*32 + ty*2 + r)*H + tx*8 + c;
            split_bf(acc[r][c], cwh[idx], cwl[idx]);
        }
    if (tid < 32) {
        int o = ot*32 + tid;
        float bacc = ab[kz*H + o];
        const float* arow = aw + ((size_t)kz*H + o)*H;
        const float* brow = wb + z*H;
        for (int j = 0; j < H; ++j) bacc += arow[j]*brow[j];
        cb[z*H + o] = bacc;
    }
}

// ================= fc GEMM (bf16-split TC, ldmatrix, gather) =================
#define FC2_SMEM (8*128*HS*2 + 512)
__global__ __launch_bounds__(256,2) void fc_bf16(
    const __nv_bfloat16* __restrict__ xh, const __nv_bfloat16* __restrict__ xl,
    const int* __restrict__ neigh, const int* __restrict__ tgt,
    const __nv_bfloat16* __restrict__ fwh, const __nv_bfloat16* __restrict__ fwl,
    const float* __restrict__ fcb,
    __nv_bfloat16* __restrict__ yh, __nv_bfloat16* __restrict__ yl,
    float* __restrict__ xsh,
    __nv_bfloat16* __restrict__ xshh, __nv_bfloat16* __restrict__ xshl)
{
    extern __shared__ __align__(16) char smc[];
    __nv_bfloat16* Ah = (__nv_bfloat16*)smc;
    __nv_bfloat16* Al = Ah + 2*128*HS;
    __nv_bfloat16* Bh = Al + 2*128*HS;
    __nv_bfloat16* Bl = Bh + 2*128*HS;
    int* rows = (int*)(Bl + 2*128*HS);
    int mt = blockIdx.x, nt = blockIdx.y, s = blockIdx.z;
    int tid = threadIdx.x;
    if (tid < 128) {
        int r = mt*128 + tid;
        rows[tid] = (r < BM_) ? neigh[s*BM_ + r] : tgt[r - BM_];
    }
    __syncthreads();
    size_t wb = ((size_t)s*512 + nt*128)*IN_F;

    auto prefetch = [&](int kc, int buf) {
        #pragma unroll
        for (int i = 0; i < 2; ++i) {
            int idx = tid + i*256;
            int r = idx >> 2, seg = (idx & 3)*8;
            int so = buf*128*HS + r*HS + seg;
            size_t ga = (size_t)rows[r]*IN_F + kc*KC + seg;
            size_t gb = wb + (size_t)r*IN_F + kc*KC + seg;
            cpa16(Ah + so, xh + ga);
            cpa16(Al + so, xl + ga);
            cpa16(Bh + so, fwh + gb);
            cpa16(Bl + so, fwl + gb);
        }
    };

    int w = tid >> 5, lane = tid & 31;
    int wm = (w & 3)*32, wn = (w >> 2)*64;
    int arow = lane & 15, acol = (lane & 16) ? 8 : 0;
    int bn = (lane & 7) + ((lane & 16) ? 8 : 0), bk = (lane & 8) ? 8 : 0;
    unsigned aAh = s2u(Ah), aAl = s2u(Al), aBh = s2u(Bh), aBl = s2u(Bl);

    float acc[2][8][4];
    #pragma unroll
    for (int i = 0; i < 2; ++i)
        #pragma unroll
        for (int j = 0; j < 8; ++j)
            #pragma unroll
            for (int e = 0; e < 4; ++e) acc[i][j][e] = 0.f;

    prefetch(0, 0); cp_commit();
    const int NCH = IN_F/KC;  // 8
    for (int kc = 0; kc < NCH; ++kc) {
        if (kc+1 < NCH) { prefetch(kc+1, (kc+1)&1); cp_commit(); cp_wait1(); }
        else            { cp_wait0(); }
        __syncthreads();
        unsigned bufo = (unsigned)((kc&1)*128*HS);
        #pragma unroll
        for (int kk = 0; kk < 2; ++kk) {
            int kb = kk*16;
            unsigned ah[2][4], al[2][4];
            #pragma unroll
            for (int mi = 0; mi < 2; ++mi) {
                unsigned off = (unsigned)((bufo + (wm + mi*16 + arow)*HS + kb + acol)*2);
                ldsm4(ah[mi][0], ah[mi][1], ah[mi][2], ah[mi][3], aAh + off);
                ldsm4(al[mi][0], al[mi][1], al[mi][2], al[mi][3], aAl + off);
            }
            #pragma unroll
            for (int nh = 0; nh < 2; ++nh) {
                unsigned bh_[4][2], bl_[4][2];
                #pragma unroll
                for (int nj = 0; nj < 2; ++nj) {
                    unsigned off_ = (unsigned)((bufo + (wn + nh*32 + nj*16 + bn)*HS + kb + bk)*2);
                    ldsm4(bh_[nj*2][0], bh_[nj*2][1], bh_[nj*2+1][0], bh_[nj*2+1][1], aBh + off_);
                    ldsm4(bl_[nj*2][0], bl_[nj*2][1], bl_[nj*2+1][0], bl_[nj*2+1][1], aBl + off_);
                }
                #pragma unroll
                for (int ni = 0; ni < 4; ++ni)
                    #pragma unroll
                    for (int mi = 0; mi < 2; ++mi)
                        mma_bf16(acc[mi][nh*4+ni], ah[mi], bl_[ni]);
                #pragma unroll
                for (int ni = 0; ni < 4; ++ni)
                    #pragma unroll
                    for (int mi = 0; mi < 2; ++mi)
                        mma_bf16(acc[mi][nh*4+ni], al[mi], bh_[ni]);
                #pragma unroll
                for (int ni = 0; ni < 4; ++ni)
                    #pragma unroll
                    for (int mi = 0; mi < 2; ++mi)
                        mma_bf16(acc[mi][nh*4+ni], ah[mi], bh_[ni]);
            }
        }
        __syncthreads();
    }

    int zp = s*HN + nt;
    int gid = lane >> 2, tig = lane & 3;
    float* Cs = (float*)smc;  // 128x132
    #pragma unroll
    for (int mi = 0; mi < 2; ++mi)
        #pragma unroll
        for (int ni = 0; ni < 8; ++ni)
            #pragma unroll
            for (int e = 0; e < 4; ++e) {
                int r = wm + mi*16 + gid + ((e >= 2) ? 8 : 0);
                int c = wn + ni*8 + 2*tig + (e & 1);
                Cs[r*132 + c] = lrelu_f(acc[mi][ni][e] + fcb[zp*H + c]);
            }
    __syncthreads();
    #pragma unroll
    for (int t = 0; t < 16; ++t) {
        int idx = tid + t*256;
        int rr = idx >> 5, c4 = (idx & 31)*4;
        float4 v = *(const float4*)(Cs + rr*132 + c4);
        int gr = mt*128 + rr;
        __nv_bfloat16 h0,h1,h2_,h3,l0,l1,l2,l3;
        split_bf(v.x,h0,l0); split_bf(v.y,h1,l1);
        split_bf(v.z,h2_,l2); split_bf(v.w,h3,l3);
        __nv_bfloat162 ph0 = {h0,h1}, ph1 = {h2_,h3};
        __nv_bfloat162 pl0 = {l0,l1}, pl1 = {l2,l3};
        uint2 uh, ul;
        uh.x = *(unsigned*)&ph0; uh.y = *(unsigned*)&ph1;
        ul.x = *(unsigned*)&pl0; ul.y = *(unsigned*)&pl1;
        if (gr < BM_) {
            size_t base = ((size_t)zp*BM_ + gr)*H + c4;
            *(uint2*)(yh + base) = uh;
            *(uint2*)(yl + base) = ul;
        } else {
            size_t base = ((size_t)zp*Bq + (gr - BM_))*H + c4;
            *(float4*)(xsh + base) = v;
            *(uint2*)(xshh + base) = uh;
            *(uint2*)(xshl + base) = ul;
        }
    }
}

// ================= qk_fused (mma.sync + ldmatrix) =================
#define QK_SMEM (4*128*QKS*2)
__global__ __launch_bounds__(256,1) void qk_fused(
    const __nv_bfloat16* __restrict__ xshh, const __nv_bfloat16* __restrict__ xshl,
    const __nv_bfloat16* __restrict__ cqh, const __nv_bfloat16* __restrict__ cql,
    const float* __restrict__ cqb,
    const __nv_bfloat16* __restrict__ awh, const __nv_bfloat16* __restrict__ awl,
    float* __restrict__ wh2)
{
    extern __shared__ __align__(16) char smc[];
    __nv_bfloat16* Axh = (__nv_bfloat16*)smc;
    __nv_bfloat16* Axl = Axh + 128*QKS;
    __nv_bfloat16* Bh  = Axl + 128*QKS;
    __nv_bfloat16* Bl  = Bh + 128*QKS;
    int mt = blockIdx.x, z = blockIdx.y;
    int tid = threadIdx.x;
    int kz = c_kofs[z/HN]*HN + (z % HN);

    const __nv_bfloat16* Agh = xshh + ((size_t)z*Bq + mt*128)*H;
    const __nv_bfloat16* Agl = xshl + ((size_t)z*Bq + mt*128)*H;
    const __nv_bfloat16* Bgh = cqh + (size_t)z*H*H;
    const __nv_bfloat16* Bgl = cql + (size_t)z*H*H;

    #pragma unroll
    for (int i = 0; i < 8; ++i) {
        int idx = tid + i*256;
        int r = idx >> 4, seg = (idx & 15)*8;
        cpa16(Axh + r*QKS + seg, Agh + (size_t)r*H + seg);
        cpa16(Axl + r*QKS + seg, Agl + (size_t)r*H + seg);
        cpa16(Bh + r*QKS + seg, Bgh + (size_t)r*H + seg);
        cpa16(Bl + r*QKS + seg, Bgl + (size_t)r*H + seg);
    }
    cp_commit(); cp_wait0();
    __syncthreads();

    int w = tid >> 5, lane = tid & 31, gid = lane >> 2, tig = lane & 3;
    int wm = (w & 3)*32, wn = (w >> 2)*64;
    int arow = lane & 15, acol = (lane & 16) ? 8 : 0;
    int bn = (lane & 7) + ((lane & 16) ? 8 : 0), bk = (lane & 8) ? 8 : 0;
    unsigned aAh = s2u(Axh), aAl = s2u(Axl), aBh = s2u(Bh), aBl = s2u(Bl);
    float acc[2][8][4];

    auto run_gemm = [&]() {
        #pragma unroll
        for (int i = 0; i < 2; ++i)
            #pragma unroll
            for (int j = 0; j < 8; ++j)
                #pragma unroll
                for (int e = 0; e < 4; ++e) acc[i][j][e] = 0.f;
        #pragma unroll
        for (int kk = 0; kk < 8; ++kk) {
            int kb = kk*16;
            unsigned ah[2][4], al[2][4];
            #pragma unroll
            for (int mi = 0; mi < 2; ++mi) {
                unsigned off = (unsigned)(((wm + mi*16 + arow)*QKS + kb + acol)*2);
                ldsm4(ah[mi][0], ah[mi][1], ah[mi][2], ah[mi][3], aAh + off);
                ldsm4(al[mi][0], al[mi][1], al[mi][2], al[mi][3], aAl + off);
            }
            #pragma unroll
            for (int nh = 0; nh < 2; ++nh)
                MMA_HALF_STEP(acc, ah, al, aBh, aBl, QKS, kb, bk, bn, wn, nh);
        }
    };

    run_gemm();
    __syncthreads();
    #pragma unroll
    for (int mi = 0; mi < 2; ++mi)
        #pragma unroll
        for (int ni = 0; ni < 8; ++ni)
            #pragma unroll
            for (int e = 0; e < 4; ++e) {
                int r = wm + mi*16 + gid + ((e >= 2) ? 8 : 0);
                int c = wn + ni*8 + 2*tig + (e & 1);
                float v = lrelu_f(acc[mi][ni][e] + cqb[z*H + c]);
                __nv_bfloat16 hh, ll;
                split_bf(v, hh, ll);
                Axh[r*QKS + c] = hh;
                Axl[r*QKS + c] = ll;
            }
    const __nv_bfloat16* Wgh = awh + (size_t)kz*H*H;
    const __nv_bfloat16* Wgl = awl + (size_t)kz*H*H;
    #pragma unroll
    for (int i = 0; i < 8; ++i) {
        int idx = tid + i*256;
        int r = idx >> 4, seg = (idx & 15)*8;
        cpa16(Bh + r*QKS + seg, Wgh + (size_t)r*H + seg);
        cpa16(Bl + r*QKS + seg, Wgl + (size_t)r*H + seg);
    }
    cp_commit(); cp_wait0();
    __syncthreads();

    run_gemm();
    #pragma unroll
    for (int mi = 0; mi < 2; ++mi)
        #pragma unroll
        for (int ni = 0; ni < 8; ++ni)
            #pragma unroll
            for (int e = 0; e < 4; ++e) {
                int r = wm + mi*16 + gid + ((e >= 2) ? 8 : 0);
                int c = wn + ni*8 + 2*tig + (e & 1);
                wh2[((size_t)z*Bq + mt*128 + r)*H + c] = acc[mi][ni][e];
            }
}

// ================= fused h1/vh GEMM + attention (single-shot K) =================
#define FU_A_BYTES (128*QKS*2)
#define FU_B_BYTES (256*QKS*2)
#define FU_SMEM    (2*FU_A_BYTES + 2*FU_B_BYTES)   /* 208896 */
__global__ __launch_bounds__(512,1) void fused_attn(
    const __nv_bfloat16* __restrict__ yhg, const __nv_bfloat16* __restrict__ ylg,
    const __nv_bfloat16* __restrict__ ckh, const __nv_bfloat16* __restrict__ ckl,
    const float* __restrict__ ckb,
    const __nv_bfloat16* __restrict__ vwh, const __nv_bfloat16* __restrict__ vwl,
    const float* __restrict__ vb,  const float* __restrict__ wh2,
    const float* __restrict__ xsh, float* __restrict__ sout)
{
    extern __shared__ __align__(16) char smc[];
    float* sm = (float*)smc;
    __nv_bfloat16* Ah = (__nv_bfloat16*)smc;       // [128*QKS]
    __nv_bfloat16* Al = Ah + 128*QKS;
    __nv_bfloat16* Bh = Al + 128*QKS;              // [256*QKS]
    __nv_bfloat16* Bl = Bh + 256*QKS;
    int mt = blockIdx.x, z = blockIdx.y;
    int tid = threadIdx.x;

    const __nv_bfloat16* Agh = yhg + ((size_t)z*BM_ + mt*128)*H;
    const __nv_bfloat16* Agl = ylg + ((size_t)z*BM_ + mt*128)*H;
    size_t wkb = (size_t)z*H*H;

    #pragma unroll
    for (int i = 0; i < 4; ++i) {
        int idx = tid + i*512;
        int r = idx >> 4, seg = (idx & 15)*8;
        cpa16(Ah + r*QKS + seg, Agh + (size_t)r*H + seg);
        cpa16(Al + r*QKS + seg, Agl + (size_t)r*H + seg);
    }
    #pragma unroll
    for (int i = 0; i < 8; ++i) {
        int idx = tid + i*512;
        int n = idx >> 4, seg = (idx & 15)*8;
        const __nv_bfloat16* sh = (n < 128) ? (ckh + wkb + (size_t)n*H)
                                            : (vwh + wkb + (size_t)(n-128)*H);
        const __nv_bfloat16* sl = (n < 128) ? (ckl + wkb + (size_t)n*H)
                                            : (vwl + wkb + (size_t)(n-128)*H);
        cpa16(Bh + n*QKS + seg, sh + seg);
        cpa16(Bl + n*QKS + seg, sl + seg);
    }
    cp_commit(); cp_wait0();
    __syncthreads();

    int w = tid >> 5, lane = tid & 31, gid = lane >> 2, tig = lane & 3;
    int wm = (w & 3)*32, wn = (w >> 2)*64;
    int arow = lane & 15, acol = (lane & 16) ? 8 : 0;
    int bn = (lane & 7) + ((lane & 16) ? 8 : 0), bk = (lane & 8) ? 8 : 0;
    unsigned aAh = s2u(Ah), aAl = s2u(Al), aBh = s2u(Bh), aBl = s2u(Bl);

    float acc[2][8][4];
    #pragma unroll
    for (int i = 0; i < 2; ++i)
        #pragma unroll
        for (int j = 0; j < 8; ++j)
            #pragma unroll
            for (int e = 0; e < 4; ++e) acc[i][j][e] = 0.f;

    #pragma unroll
    for (int kk = 0; kk < 8; ++kk) {
        int kb = kk*16;
        unsigned ah[2][4], al[2][4];
        #pragma unroll
        for (int mi = 0; mi < 2; ++mi) {
            unsigned off = (unsigned)(((wm + mi*16 + arow)*QKS + kb + acol)*2);
            ldsm4(ah[mi][0], ah[mi][1], ah[mi][2], ah[mi][3], aAh + off);
            ldsm4(al[mi][0], al[mi][1], al[mi][2], al[mi][3], aAl + off);
        }
        #pragma unroll
        for (int nh = 0; nh < 2; ++nh)
            MMA_HALF_STEP(acc, ah, al, aBh, aBl, QKS, kb, bk, bn, wn, nh);
    }
    __syncthreads();   // all smem reads done before epilogue aliasing

    float* SP  = sm;                 // [128][132]  h1 (lrelu+bias)
    float* SV  = SP + 128*132;       // [128][132]  vh (+bias)
    float* SW  = SV + 128*132;       // [8][128]    wh2 rows
    float* SSC = SW + 8*128;         // [128] scores
    float* SE  = SSC + 128;          // [128] softmax weights

    #pragma unroll
    for (int mi = 0; mi < 2; ++mi)
        #pragma unroll
        for (int ni = 0; ni < 8; ++ni)
            #pragma unroll
            for (int e = 0; e < 4; ++e) {
                int r = wm + mi*16 + gid + ((e >= 2) ? 8 : 0);
                int c = wn + ni*8 + 2*tig + (e & 1);
                float v = acc[mi][ni][e];
                if (c < 128) SP[r*132 + c] = lrelu_f(v + ckb[z*H + c]);
                else         SV[r*132 + (c-128)] = v + vb[z*H + (c-128)];
            }
    #pragma unroll
    for (int t = 0; t < 2; ++t) {
        int idx = tid + t*512;
        int bl = idx >> 7, o = idx & 127;
        SW[idx] = wh2[((size_t)z*Bq + mt*8 + bl)*H + o];
    }
    __syncthreads();

    #pragma unroll
    for (int i = 0; i < 8; ++i) {
        int rr = w*8 + i;
        const float* wrow = SW + (rr >> 4)*128;
        float p = 0.f;
        #pragma unroll
        for (int o = 0; o < 128; o += 32) p += SP[rr*132 + o + lane]*wrow[o + lane];
        #pragma unroll
        for (int d_ = 16; d_ > 0; d_ >>= 1) p += __shfl_xor_sync(0xffffffffu, p, d_);
        if (lane == 0) SSC[rr] = p;
    }
    __syncthreads();
    if (tid < 8) {
        float mx = -1e30f;
        #pragma unroll
        for (int m = 0; m < M; ++m) mx = fmaxf(mx, SSC[tid*M + m]);
        float es[M], sum = 0.f;
        #pragma unroll
        for (int m = 0; m < M; ++m) { es[m] = expf(SSC[tid*M + m] - mx); sum += es[m]; }
        float inv = 1.f/sum;
        #pragma unroll
        for (int m = 0; m < M; ++m) SE[tid*M + m] = es[m]*inv;
    }
    __syncthreads();

    int s = z/HN, hh = z%HN;
    #pragma unroll
    for (int t = 0; t < 2; ++t) {
        int idx = tid + t*512;
        int bl = idx >> 7, o = idx & 127;
        float a = 0.f;
        #pragma unroll
        for (int m = 0; m < M; ++m) {
            float v = SV[(bl*M + m)*132 + o]*SE[bl*M + m];
            a += (v >= 0.f) ? v : ALPHA*v;
        }
        int b = mt*8 + bl;
        sout[((size_t)s*Bq + b)*D + hh*H + o] =
            0.5f*(xsh[((size_t)z*Bq + b)*H + o] + a);
    }
}

// ---------------- semantic attention (smem-tiled weights, 8 targets/block) -----
#define SEM_SMEM(P) ((8*(P)*D + 64*132 + 8*(P)*132 + 32)*4)
template<int P>
__global__ __launch_bounds__(128) void semantic(
    const float* __restrict__ zin, const float* __restrict__ p1w,
    const float* __restrict__ p1b, const float* __restrict__ p2w,
    float* __restrict__ outp, int in_pstride, int in_bstride, int out_bstride)
{
    extern __shared__ __align__(16) float sem[];
    float* zs   = sem;                         // [8P][512]
    float* pwT  = sem + 8*P*D;                 // [64][132] transposed chunk
    float* sred = pwT + 64*132;                // [8P][132]
    float* ssc  = sred + 8*P*132;              // [8P]
    int b0 = blockIdx.x*8, tid = threadIdx.x;

    for (int idx = tid; idx < 8*P*(D/4); idx += 128) {
        int d4 = idx & (D/4 - 1); int rp = idx / (D/4);
        int p = rp % P, bl = rp / P;
        *(float4*)&zs[(bl*P+p)*D + d4*4] =
            *(const float4*)(zin + (size_t)(b0+bl)*in_bstride + (size_t)p*in_pstride + d4*4);
    }
    __syncthreads();

    float acc[8][P];
    #pragma unroll
    for (int bl = 0; bl < 8; ++bl)
        #pragma unroll
        for (int p = 0; p < P; ++p) acc[bl][p] = 0.f;

    for (int d0 = 0; d0 < D; d0 += 64) {
        #pragma unroll
        for (int i = 0; i < 16; ++i) {
            int idx = tid + i*128;
            int r = idx >> 4, c4 = (idx & 15)*4;
            float4 v = *(const float4*)(p1w + (size_t)r*D + d0 + c4);
            pwT[c4*132 + r]     = v.x;
            pwT[(c4+1)*132 + r] = v.y;
            pwT[(c4+2)*132 + r] = v.z;
            pwT[(c4+3)*132 + r] = v.w;
        }
        __syncthreads();
        #pragma unroll 4
        for (int dd = 0; dd < 64; dd += 4) {
            float w0 = pwT[dd*132 + tid],     w1 = pwT[(dd+1)*132 + tid];
            float w2 = pwT[(dd+2)*132 + tid], w3 = pwT[(dd+3)*132 + tid];
            #pragma unroll
            for (int bl = 0; bl < 8; ++bl)
                #pragma unroll
                for (int p = 0; p < P; ++p) {
                    float4 zv = *(const float4*)&zs[(bl*P+p)*D + d0 + dd];
                    acc[bl][p] += w0*zv.x + w1*zv.y + w2*zv.z + w3*zv.w;
                }
        }
        __syncthreads();
    }

    float bias = p1b[tid], p2 = p2w[tid];
    #pragma unroll
    for (int bl = 0; bl < 8; ++bl)
        #pragma unroll
        for (int p = 0; p < P; ++p)
            sred[(bl*P+p)*132 + tid] = tanhf(acc[bl][p] + bias)*p2;
    __syncthreads();
    if (tid < 8*P) {
        float s_ = 0.f;
        for (int o = 0; o < H; ++o) s_ += sred[tid*132 + o];
        ssc[tid] = s_;
    }
    __syncthreads();
    if (tid < 8) {
        float mx = -1e30f;
        #pragma unroll
        for (int p = 0; p < P; ++p) mx = fmaxf(mx, ssc[tid*P + p]);
        float e[P]; float esum = 0.f;
        #pragma unroll
        for (int p = 0; p < P; ++p) { e[p] = expf(ssc[tid*P + p] - mx); esum += e[p]; }
        float inv = 1.f/esum;
        #pragma unroll
        for (int p = 0; p < P; ++p) ssc[tid*P + p] = e[p]*inv;
    }
    __syncthreads();
    for (int idx = tid; idx < 8*(D/4); idx += 128) {
        int d4 = (idx & (D/4 - 1))*4; int bl = idx / (D/4);
        float4 o = {0.f, 0.f, 0.f, 0.f};
        #pragma unroll
        for (int p = 0; p < P; ++p) {
            float e = ssc[bl*P + p];
            float4 zv = *(const float4*)&zs[(bl*P+p)*D + d4];
            o.x += e*zv.x; o.y += e*zv.y; o.z += e*zv.z; o.w += e*zv.w;
        }
        *(float4*)(outp + (size_t)(b0+bl)*out_bstride + d4) = o;
    }
}

extern "C" void kernel_launch(void* const* d_in, const int* in_sizes, int n_in,
                              void* d_out, int out_size)
{
    const float* x     = (const float*)d_in[0];
    const int*   tgt   = (const int*)  d_in[1];
    const int*   neigh = (const int*)  d_in[2];
    const float* fc_w  = (const float*)d_in[3];
    const float* fc_b  = (const float*)d_in[4];
    const float* q_w   = (const float*)d_in[5];
    const float* q_b   = (const float*)d_in[6];
    const float* k_w   = (const float*)d_in[7];
    const float* k_b   = (const float*)d_in[8];
    const float* v_w   = (const float*)d_in[9];
    const float* v_b   = (const float*)d_in[10];
    const float* att_W = (const float*)d_in[11];
    const float* a1w   = (const float*)d_in[12];
    const float* a1b   = (const float*)d_in[13];
    const float* a2w   = (const float*)d_in[14];
    const float* a2b   = (const float*)d_in[15];
    const float* ip1w  = (const float*)d_in[16];
    const float* ip1b  = (const float*)d_in[17];
    const float* ip2w  = (const float*)d_in[18];
    const float* bp1w  = (const float*)d_in[19];
    const float* bp1b  = (const float*)d_in[20];
    const float* bp2w  = (const float*)d_in[21];
    float* out = (float*)d_out;

    __nv_bfloat16 *xhi,*xlo,*fwh,*fwl,*vwh,*vwl,*awh,*awl,*ckwh,*ckwl,*cqwh,*cqwl,*yh,*yl,*xshh,*xshl;
    float *ckb,*cqb,*xsh,*wh2,*sout,*mp;
    cudaGetSymbolAddress((void**)&xhi,  g_xhi);
    cudaGetSymbolAddress((void**)&xlo,  g_xlo);
    cudaGetSymbolAddress((void**)&fwh,  g_fwh);
    cudaGetSymbolAddress((void**)&fwl,  g_fwl);
    cudaGetSymbolAddress((void**)&vwh,  g_vwh);
    cudaGetSymbolAddress((void**)&vwl,  g_vwl);
    cudaGetSymbolAddress((void**)&awh,  g_awh);
    cudaGetSymbolAddress((void**)&awl,  g_awl);
    cudaGetSymbolAddress((void**)&ckwh, g_ckwh);
    cudaGetSymbolAddress((void**)&ckwl, g_ckwl);
    cudaGetSymbolAddress((void**)&ckb,  g_ckb);
    cudaGetSymbolAddress((void**)&cqwh, g_cqwh);
    cudaGetSymbolAddress((void**)&cqwl, g_cqwl);
    cudaGetSymbolAddress((void**)&cqb,  g_cqb);
    cudaGetSymbolAddress((void**)&xsh,  g_xsh);
    cudaGetSymbolAddress((void**)&xshh, g_xshh);
    cudaGetSymbolAddress((void**)&xshl, g_xshl);
    cudaGetSymbolAddress((void**)&yh,   g_yh);
    cudaGetSymbolAddress((void**)&yl,   g_yl);
    cudaGetSymbolAddress((void**)&wh2,  g_wh2);
    cudaGetSymbolAddress((void**)&sout, g_sout);
    cudaGetSymbolAddress((void**)&mp,   g_mp);

    static int smem_set = 0;
    if (!smem_set) {
        cudaFuncSetAttribute(fc_bf16,     cudaFuncAttributeMaxDynamicSharedMemorySize, FC2_SMEM);
        cudaFuncSetAttribute(qk_fused,    cudaFuncAttributeMaxDynamicSharedMemorySize, QK_SMEM);
        cudaFuncSetAttribute(fused_attn,  cudaFuncAttributeMaxDynamicSharedMemorySize, FU_SMEM);
        cudaFuncSetAttribute(semantic<2>, cudaFuncAttributeMaxDynamicSharedMemorySize, SEM_SMEM(2));
        cudaFuncSetAttribute(semantic<3>, cudaFuncAttributeMaxDynamicSharedMemorySize, SEM_SMEM(3));
        smem_set = 1;
    }

    // 0. precompute all bf16 hi/lo splits in one launch
    split_all<<<(SPL_TOT + 255)/256, 256>>>(x, xhi, xlo, fc_w, fwh, fwl,
                                            v_w, vwh, vwl, att_W, awh, awl);

    // 1. fold attention-layer weights into k/q projections (one launch, grid.z=2)
    combine_gemm<<<dim3(4, PAIRS, 2), 256>>>(a1w, a1b, k_w, k_b, ckwh, ckwl, ckb,
                                             a2w, a2b, q_w, q_b, cqwh, cqwl, cqb);

    // 2. shared fc + leakyrelu on gathered neighbors + targets
    fc_bf16<<<dim3(R_/128, 4, S), 256, FC2_SMEM>>>(xhi, xlo, neigh, tgt, fwh, fwl,
                                                   fc_b, yh, yl, xsh, xshh, xshl);

    // 3. wh2 = (lrelu(xsh@cq^T + cqb)) @ attW^T
    qk_fused<<<dim3(Bq/128, PAIRS), 256, QK_SMEM>>>(xshh, xshl, cqwh, cqwl, cqb,
                                                    awh, awl, wh2);

    // 4. fused h1/vh GEMM + neighbor attention + residual
    fused_attn<<<dim3(BM_/128, PAIRS), 512, FU_SMEM>>>(yh, yl, ckwh, ckwl, ckb,
                                                       vwh, vwl, v_b, wh2, xsh, sout);

    // 5. semantic attention within each metapath
    semantic<2><<<Bq/8, 128, SEM_SMEM(2)>>>(sout,          ip1w,       ip1b,     ip2w,     mp,     Bq*D, D, KM*D);
    semantic<3><<<Bq/8, 128, SEM_SMEM(3)>>>(sout + 2*Bq*D, ip1w + H*D, ip1b + H, ip2w + H, mp + D, Bq*D, D, KM*D);

    // 6. semantic attention between metapaths -> final output
    semantic<2><<<Bq/8, 128, SEM_SMEM(2)>>>(mp, bp1w, bp1b, bp2w, out, D, KM*D, D);
}

// round 12
// speedup vs baseline: 1.2920x; 1.0815x over previous
#include <cuda_runtime.h>
#include <cuda_bf16.h>
#include <cuda_fp16.h>
#include <math.h>

#define NN    20000
#define IN_F  256
#define H     128
#define HN    4
#define S     5
#define KM    2
#define Bq    1024
#define M     16
#define D     512
#define ALPHA 0.2f
#define BM_   (Bq*M)      /* 16384 */
#define R_    (BM_ + Bq)  /* 17408 */
#define PAIRS (S*HN)      /* 20 */

#define KC    32          /* K halves per pipeline stage (fc) */
#define HS    40          /* fc smem row stride in halves */
#define QKS   136         /* full-K smem row stride in halves */

__constant__ int c_kofs[S] = {0,0,1,1,1};

// ---------------- scratch ----------------
__device__ __nv_bfloat16 g_xhi[NN*IN_F];
__device__ __nv_bfloat16 g_xlo[NN*IN_F];
__device__ __nv_bfloat16 g_fwh[S*4*H*IN_F];
__device__ __nv_bfloat16 g_fwl[S*4*H*IN_F];
__device__ __half        g_vwh[PAIRS*H*H];          /* single fp16 */
__device__ __nv_bfloat16 g_awh[KM*HN*H*H];
__device__ __nv_bfloat16 g_awl[KM*HN*H*H];
__device__ __half        g_ckh[PAIRS*H*H];          /* single fp16 */
__device__ float g_ckb[PAIRS*H];
__device__ __nv_bfloat16 g_cqwh[PAIRS*H*H];
__device__ __nv_bfloat16 g_cqwl[PAIRS*H*H];
__device__ float g_cqb[PAIRS*H];
__device__ float g_xsh[PAIRS*Bq*H];
__device__ __nv_bfloat16 g_xshh[PAIRS*Bq*H];
__device__ __nv_bfloat16 g_xshl[PAIRS*Bq*H];
__device__ __half g_yh[(size_t)PAIRS*BM_*H];        /* fp16 hi */
__device__ __half g_yl[(size_t)PAIRS*BM_*H];        /* fp16 lo */
__device__ float g_wh2[PAIRS*Bq*H];
__device__ float g_sout[S*Bq*D];
__device__ float g_mp[Bq*KM*D];

// ---------------- helpers ----------------
__device__ __forceinline__ void mma_bf16(float* d, const unsigned* a, const unsigned* b) {
    asm volatile(
      "mma.sync.aligned.m16n8k16.row.col.f32.bf16.bf16.f32 "
      "{%0,%1,%2,%3}, {%4,%5,%6,%7}, {%8,%9}, {%0,%1,%2,%3};\n"
      : "+f"(d[0]), "+f"(d[1]), "+f"(d[2]), "+f"(d[3])
      : "r"(a[0]), "r"(a[1]), "r"(a[2]), "r"(a[3]), "r"(b[0]), "r"(b[1]));
}
__device__ __forceinline__ void mma_f16(float* d, const unsigned* a, const unsigned* b) {
    asm volatile(
      "mma.sync.aligned.m16n8k16.row.col.f32.f16.f16.f32 "
      "{%0,%1,%2,%3}, {%4,%5,%6,%7}, {%8,%9}, {%0,%1,%2,%3};\n"
      : "+f"(d[0]), "+f"(d[1]), "+f"(d[2]), "+f"(d[3])
      : "r"(a[0]), "r"(a[1]), "r"(a[2]), "r"(a[3]), "r"(b[0]), "r"(b[1]));
}
__device__ __forceinline__ void ldsm4(unsigned& r0, unsigned& r1, unsigned& r2, unsigned& r3,
                                      unsigned addr) {
    asm volatile("ldmatrix.sync.aligned.m8n8.x4.shared.b16 {%0,%1,%2,%3}, [%4];\n"
      : "=r"(r0), "=r"(r1), "=r"(r2), "=r"(r3) : "r"(addr));
}
__device__ __forceinline__ unsigned s2u(const void* p) {
    return (unsigned)__cvta_generic_to_shared(p);
}
__device__ __forceinline__ void split_bf(float x, __nv_bfloat16& h, __nv_bfloat16& l) {
    h = __float2bfloat16_rn(x);
    l = __float2bfloat16_rn(x - __bfloat162float(h));
}
__device__ __forceinline__ void split_h(float x, __half& h, __half& l) {
    h = __float2half_rn(x);
    l = __float2half_rn(x - __half2float(h));
}
__device__ __forceinline__ void cpa16(void* dst, const void* src) {
    unsigned d = (unsigned)__cvta_generic_to_shared(dst);
    asm volatile("cp.async.cg.shared.global [%0], [%1], 16;\n" :: "r"(d), "l"(src));
}
__device__ __forceinline__ void cp_commit() { asm volatile("cp.async.commit_group;\n"); }
__device__ __forceinline__ void cp_wait1() { asm volatile("cp.async.wait_group 1;\n"); }
__device__ __forceinline__ void cp_wait0() { asm volatile("cp.async.wait_group 0;\n"); }
__device__ __forceinline__ float lrelu_f(float v) { return v >= 0.f ? v : ALPHA*v; }

// half-N term-major step (bf16 3-term)
#define MMA_HALF_STEP(acc, ah, al, aBh, aBl, STRIDE, kb, bkv, bnv, wnv, nh)       \
    {                                                                             \
        unsigned bh_[4][2], bl_[4][2];                                            \
        _Pragma("unroll")                                                         \
        for (int nj = 0; nj < 2; ++nj) {                                          \
            unsigned off_ = (unsigned)((((wnv) + (nh)*32 + nj*16 + (bnv))*(STRIDE) + (kb) + (bkv))*2); \
            ldsm4(bh_[nj*2][0], bh_[nj*2][1], bh_[nj*2+1][0], bh_[nj*2+1][1], (aBh) + off_); \
            ldsm4(bl_[nj*2][0], bl_[nj*2][1], bl_[nj*2+1][0], bl_[nj*2+1][1], (aBl) + off_); \
        }                                                                         \
        _Pragma("unroll")                                                         \
        for (int ni = 0; ni < 4; ++ni)                                            \
            _Pragma("unroll")                                                     \
            for (int mi = 0; mi < 2; ++mi)                                        \
                mma_bf16(acc[mi][(nh)*4+ni], ah[mi], bl_[ni]);                    \
        _Pragma("unroll")                                                         \
        for (int ni = 0; ni < 4; ++ni)                                            \
            _Pragma("unroll")                                                     \
            for (int mi = 0; mi < 2; ++mi)                                        \
                mma_bf16(acc[mi][(nh)*4+ni], al[mi], bh_[ni]);                    \
        _Pragma("unroll")                                                         \
        for (int ni = 0; ni < 4; ++ni)                                            \
            _Pragma("unroll")                                                     \
            for (int mi = 0; mi < 2; ++mi)                                        \
                mma_bf16(acc[mi][(nh)*4+ni], ah[mi], bh_[ni]);                    \
    }

// ---------------- all operand-prep splits in ONE launch ----------------
#define SPL_N1 (NN*IN_F)
#define SPL_N2 (S*4*H*IN_F)
#define SPL_N3 (PAIRS*H*H)
#define SPL_N4 (KM*HN*H*H)
#define SPL_TOT (SPL_N1 + SPL_N2 + SPL_N3 + SPL_N4)
__global__ void split_all(
    const float* __restrict__ x,    __nv_bfloat16* __restrict__ xhi, __nv_bfloat16* __restrict__ xlo,
    const float* __restrict__ fcw,  __nv_bfloat16* __restrict__ fwh, __nv_bfloat16* __restrict__ fwl,
    const float* __restrict__ vw,   __half* __restrict__ vwh,
    const float* __restrict__ attw, __nv_bfloat16* __restrict__ awh, __nv_bfloat16* __restrict__ awl)
{
    int i = blockIdx.x*256 + threadIdx.x;
    if (i < SPL_N1) { split_bf(x[i], xhi[i], xlo[i]); return; }
    if (i < SPL_N1+SPL_N2) { int j = i - SPL_N1; split_bf(fcw[j], fwh[j], fwl[j]); return; }
    if (i < SPL_N1+SPL_N2+SPL_N3) {
        int j = i - SPL_N1 - SPL_N2;
        vwh[j] = __float2half_rn(vw[j]);
        return;
    }
    if (i < SPL_TOT) { int j = i - SPL_N1 - SPL_N2 - SPL_N3; split_bf(attw[j], awh[j], awl[j]); }
}

// ---------------- combined weights (ck -> single fp16; cq -> bf16 split) -------
__global__ __launch_bounds__(256) void combine_gemm(
    const float* __restrict__ a1w, const float* __restrict__ a1b,
    const float* __restrict__ k_w, const float* __restrict__ k_b,
    __half* __restrict__ ckh, float* __restrict__ ckb,
    const float* __restrict__ a2w, const float* __restrict__ a2b,
    const float* __restrict__ q_w, const float* __restrict__ q_b,
    __nv_bfloat16* __restrict__ cqh, __nv_bfloat16* __restrict__ cql, float* __restrict__ cqb)
{
    int ot = blockIdx.x, z = blockIdx.y, which = blockIdx.z, tid = threadIdx.x;
    const float* aw = which ? a2w : a1w;
    const float* ab = which ? a2b : a1b;
    const float* w  = which ? q_w : k_w;
    const float* wb = which ? q_b : k_b;
    float* cb = which ? cqb : ckb;
    int kz = c_kofs[z/HN]*HN + (z % HN);
    const float* A = aw + ((size_t)kz*H + ot*32)*H;
    const float* W = w + (size_t)z*H*H;
    __shared__ float sa[32][36];
    __shared__ float sw[32][132];
    int tx = tid & 15, ty = tid >> 4;
    float acc[2][8];
    #pragma unroll
    for (int r = 0; r < 2; ++r)
        #pragma unroll
        for (int c = 0; c < 8; ++c) acc[r][c] = 0.f;
    for (int kc = 0; kc < 4; ++kc) {
        {
            int r = tid >> 3, c4 = (tid & 7)*4;
            *(float4*)&sa[r][c4] = *(const float4*)(A + r*H + kc*32 + c4);
        }
        #pragma unroll
        for (int i = 0; i < 4; ++i) {
            int idx = tid + i*256;
            int r = idx >> 5, c4 = (idx & 31)*4;
            *(float4*)&sw[r][c4] = *(const float4*)(W + (kc*32 + r)*H + c4);
        }
        __syncthreads();
        #pragma unroll 8
        for (int j = 0; j < 32; ++j) {
            float a0 = sa[ty*2][j], a1 = sa[ty*2+1][j];
            #pragma unroll
            for (int c = 0; c < 8; ++c) {
                float wv = sw[j][tx*8 + c];
                acc[0][c] += a0*wv;
                acc[1][c] += a1*wv;
            }
        }
        __syncthreads();
    }
    #pragma unroll
    for (int r = 0; r < 2; ++r)
        #pragma unroll
        for (int c = 0; c < 8; ++c) {
            size_t idx = ((size_t)z*H + ot*32 + ty*2 + r)*H + tx*8 + c;
            if (which) split_bf(acc[r][c], cqh[idx], cql[idx]);
            else       ckh[idx] = __float2half_rn(acc[r][c]);
        }
    if (tid < 32) {
        int o = ot*32 + tid;
        float bacc = ab[kz*H + o];
        const float* arow = aw + ((size_t)kz*H + o)*H;
        const float* brow = wb + z*H;
        for (int j = 0; j < H; ++j) bacc += arow[j]*brow[j];
        cb[z*H + o] = bacc;
    }
}

// ================= fc GEMM (bf16-split TC, ldmatrix, gather) =================
#define FC2_SMEM (8*128*HS*2 + 512)
__global__ __launch_bounds__(256,2) void fc_bf16(
    const __nv_bfloat16* __restrict__ xh, const __nv_bfloat16* __restrict__ xl,
    const int* __restrict__ neigh, const int* __restrict__ tgt,
    const __nv_bfloat16* __restrict__ fwh, const __nv_bfloat16* __restrict__ fwl,
    const float* __restrict__ fcb,
    __half* __restrict__ yh, __half* __restrict__ yl,
    float* __restrict__ xsh,
    __nv_bfloat16* __restrict__ xshh, __nv_bfloat16* __restrict__ xshl)
{
    extern __shared__ __align__(16) char smc[];
    __nv_bfloat16* Ah = (__nv_bfloat16*)smc;
    __nv_bfloat16* Al = Ah + 2*128*HS;
    __nv_bfloat16* Bh = Al + 2*128*HS;
    __nv_bfloat16* Bl = Bh + 2*128*HS;
    int* rows = (int*)(Bl + 2*128*HS);
    int mt = blockIdx.x, nt = blockIdx.y, s = blockIdx.z;
    int tid = threadIdx.x;
    if (tid < 128) {
        int r = mt*128 + tid;
        rows[tid] = (r < BM_) ? neigh[s*BM_ + r] : tgt[r - BM_];
    }
    __syncthreads();
    size_t wb = ((size_t)s*512 + nt*128)*IN_F;

    auto prefetch = [&](int kc, int buf) {
        #pragma unroll
        for (int i = 0; i < 2; ++i) {
            int idx = tid + i*256;
            int r = idx >> 2, seg = (idx & 3)*8;
            int so = buf*128*HS + r*HS + seg;
            size_t ga = (size_t)rows[r]*IN_F + kc*KC + seg;
            size_t gb = wb + (size_t)r*IN_F + kc*KC + seg;
            cpa16(Ah + so, xh + ga);
            cpa16(Al + so, xl + ga);
            cpa16(Bh + so, fwh + gb);
            cpa16(Bl + so, fwl + gb);
        }
    };

    int w = tid >> 5, lane = tid & 31;
    int wm = (w & 3)*32, wn = (w >> 2)*64;
    int arow = lane & 15, acol = (lane & 16) ? 8 : 0;
    int bn = (lane & 7) + ((lane & 16) ? 8 : 0), bk = (lane & 8) ? 8 : 0;
    unsigned aAh = s2u(Ah), aAl = s2u(Al), aBh = s2u(Bh), aBl = s2u(Bl);

    float acc[2][8][4];
    #pragma unroll
    for (int i = 0; i < 2; ++i)
        #pragma unroll
        for (int j = 0; j < 8; ++j)
            #pragma unroll
            for (int e = 0; e < 4; ++e) acc[i][j][e] = 0.f;

    prefetch(0, 0); cp_commit();
    const int NCH = IN_F/KC;  // 8
    for (int kc = 0; kc < NCH; ++kc) {
        if (kc+1 < NCH) { prefetch(kc+1, (kc+1)&1); cp_commit(); cp_wait1(); }
        else            { cp_wait0(); }
        __syncthreads();
        unsigned bufo = (unsigned)((kc&1)*128*HS);
        #pragma unroll
        for (int kk = 0; kk < 2; ++kk) {
            int kb = kk*16;
            unsigned ah[2][4], al[2][4];
            #pragma unroll
            for (int mi = 0; mi < 2; ++mi) {
                unsigned off = (unsigned)((bufo + (wm + mi*16 + arow)*HS + kb + acol)*2);
                ldsm4(ah[mi][0], ah[mi][1], ah[mi][2], ah[mi][3], aAh + off);
                ldsm4(al[mi][0], al[mi][1], al[mi][2], al[mi][3], aAl + off);
            }
            #pragma unroll
            for (int nh = 0; nh < 2; ++nh) {
                unsigned bh_[4][2], bl_[4][2];
                #pragma unroll
                for (int nj = 0; nj < 2; ++nj) {
                    unsigned off_ = (unsigned)((bufo + (wn + nh*32 + nj*16 + bn)*HS + kb + bk)*2);
                    ldsm4(bh_[nj*2][0], bh_[nj*2][1], bh_[nj*2+1][0], bh_[nj*2+1][1], aBh + off_);
                    ldsm4(bl_[nj*2][0], bl_[nj*2][1], bl_[nj*2+1][0], bl_[nj*2+1][1], aBl + off_);
                }
                #pragma unroll
                for (int ni = 0; ni < 4; ++ni)
                    #pragma unroll
                    for (int mi = 0; mi < 2; ++mi)
                        mma_bf16(acc[mi][nh*4+ni], ah[mi], bl_[ni]);
                #pragma unroll
                for (int ni = 0; ni < 4; ++ni)
                    #pragma unroll
                    for (int mi = 0; mi < 2; ++mi)
                        mma_bf16(acc[mi][nh*4+ni], al[mi], bh_[ni]);
                #pragma unroll
                for (int ni = 0; ni < 4; ++ni)
                    #pragma unroll
                    for (int mi = 0; mi < 2; ++mi)
                        mma_bf16(acc[mi][nh*4+ni], ah[mi], bh_[ni]);
            }
        }
        __syncthreads();
    }

    int zp = s*HN + nt;
    int gid = lane >> 2, tig = lane & 3;
    float* Cs = (float*)smc;  // 128x132
    #pragma unroll
    for (int mi = 0; mi < 2; ++mi)
        #pragma unroll
        for (int ni = 0; ni < 8; ++ni)
            #pragma unroll
            for (int e = 0; e < 4; ++e) {
                int r = wm + mi*16 + gid + ((e >= 2) ? 8 : 0);
                int c = wn + ni*8 + 2*tig + (e & 1);
                Cs[r*132 + c] = lrelu_f(acc[mi][ni][e] + fcb[zp*H + c]);
            }
    __syncthreads();
    #pragma unroll
    for (int t = 0; t < 16; ++t) {
        int idx = tid + t*256;
        int rr = idx >> 5, c4 = (idx & 31)*4;
        float4 v = *(const float4*)(Cs + rr*132 + c4);
        int gr = mt*128 + rr;
        if (gr < BM_) {
            __half h0,h1,h2_,h3,l0,l1,l2,l3;
            split_h(v.x,h0,l0); split_h(v.y,h1,l1);
            split_h(v.z,h2_,l2); split_h(v.w,h3,l3);
            __half2 ph0 = {h0,h1}, ph1 = {h2_,h3};
            __half2 pl0 = {l0,l1}, pl1 = {l2,l3};
            uint2 uh, ul;
            uh.x = *(unsigned*)&ph0; uh.y = *(unsigned*)&ph1;
            ul.x = *(unsigned*)&pl0; ul.y = *(unsigned*)&pl1;
            size_t base = ((size_t)zp*BM_ + gr)*H + c4;
            *(uint2*)(yh + base) = uh;
            *(uint2*)(yl + base) = ul;
        } else {
            size_t base = ((size_t)zp*Bq + (gr - BM_))*H + c4;
            *(float4*)(xsh + base) = v;
            __nv_bfloat16 h0,h1,h2_,h3,l0,l1,l2,l3;
            split_bf(v.x,h0,l0); split_bf(v.y,h1,l1);
            split_bf(v.z,h2_,l2); split_bf(v.w,h3,l3);
            __nv_bfloat162 ph0 = {h0,h1}, ph1 = {h2_,h3};
            __nv_bfloat162 pl0 = {l0,l1}, pl1 = {l2,l3};
            uint2 uh, ul;
            uh.x = *(unsigned*)&ph0; uh.y = *(unsigned*)&ph1;
            ul.x = *(unsigned*)&pl0; ul.y = *(unsigned*)&pl1;
            *(uint2*)(xshh + base) = uh;
            *(uint2*)(xshl + base) = ul;
        }
    }
}

// ================= qk_fused (bf16 3-term, unchanged) =================
#define QK_SMEM (4*128*QKS*2)
__global__ __launch_bounds__(256,1) void qk_fused(
    const __nv_bfloat16* __restrict__ xshh, const __nv_bfloat16* __restrict__ xshl,
    const __nv_bfloat16* __restrict__ cqh, const __nv_bfloat16* __restrict__ cql,
    const float* __restrict__ cqb,
    const __nv_bfloat16* __restrict__ awh, const __nv_bfloat16* __restrict__ awl,
    float* __restrict__ wh2)
{
    extern __shared__ __align__(16) char smc[];
    __nv_bfloat16* Axh = (__nv_bfloat16*)smc;
    __nv_bfloat16* Axl = Axh + 128*QKS;
    __nv_bfloat16* Bh  = Axl + 128*QKS;
    __nv_bfloat16* Bl  = Bh + 128*QKS;
    int mt = blockIdx.x, z = blockIdx.y;
    int tid = threadIdx.x;
    int kz = c_kofs[z/HN]*HN + (z % HN);

    const __nv_bfloat16* Agh = xshh + ((size_t)z*Bq + mt*128)*H;
    const __nv_bfloat16* Agl = xshl + ((size_t)z*Bq + mt*128)*H;
    const __nv_bfloat16* Bgh = cqh + (size_t)z*H*H;
    const __nv_bfloat16* Bgl = cql + (size_t)z*H*H;

    #pragma unroll
    for (int i = 0; i < 8; ++i) {
        int idx = tid + i*256;
        int r = idx >> 4, seg = (idx & 15)*8;
        cpa16(Axh + r*QKS + seg, Agh + (size_t)r*H + seg);
        cpa16(Axl + r*QKS + seg, Agl + (size_t)r*H + seg);
        cpa16(Bh + r*QKS + seg, Bgh + (size_t)r*H + seg);
        cpa16(Bl + r*QKS + seg, Bgl + (size_t)r*H + seg);
    }
    cp_commit(); cp_wait0();
    __syncthreads();

    int w = tid >> 5, lane = tid & 31, gid = lane >> 2, tig = lane & 3;
    int wm = (w & 3)*32, wn = (w >> 2)*64;
    int arow = lane & 15, acol = (lane & 16) ? 8 : 0;
    int bn = (lane & 7) + ((lane & 16) ? 8 : 0), bk = (lane & 8) ? 8 : 0;
    unsigned aAh = s2u(Axh), aAl = s2u(Axl), aBh = s2u(Bh), aBl = s2u(Bl);
    float acc[2][8][4];

    auto run_gemm = [&]() {
        #pragma unroll
        for (int i = 0; i < 2; ++i)
            #pragma unroll
            for (int j = 0; j < 8; ++j)
                #pragma unroll
                for (int e = 0; e < 4; ++e) acc[i][j][e] = 0.f;
        #pragma unroll
        for (int kk = 0; kk < 8; ++kk) {
            int kb = kk*16;
            unsigned ah[2][4], al[2][4];
            #pragma unroll
            for (int mi = 0; mi < 2; ++mi) {
                unsigned off = (unsigned)(((wm + mi*16 + arow)*QKS + kb + acol)*2);
                ldsm4(ah[mi][0], ah[mi][1], ah[mi][2], ah[mi][3], aAh + off);
                ldsm4(al[mi][0], al[mi][1], al[mi][2], al[mi][3], aAl + off);
            }
            #pragma unroll
            for (int nh = 0; nh < 2; ++nh)
                MMA_HALF_STEP(acc, ah, al, aBh, aBl, QKS, kb, bk, bn, wn, nh);
        }
    };

    run_gemm();
    __syncthreads();
    #pragma unroll
    for (int mi = 0; mi < 2; ++mi)
        #pragma unroll
        for (int ni = 0; ni < 8; ++ni)
            #pragma unroll
            for (int e = 0; e < 4; ++e) {
                int r = wm + mi*16 + gid + ((e >= 2) ? 8 : 0);
                int c = wn + ni*8 + 2*tig + (e & 1);
                float v = lrelu_f(acc[mi][ni][e] + cqb[z*H + c]);
                __nv_bfloat16 hh, ll;
                split_bf(v, hh, ll);
                Axh[r*QKS + c] = hh;
                Axl[r*QKS + c] = ll;
            }
    const __nv_bfloat16* Wgh = awh + (size_t)kz*H*H;
    const __nv_bfloat16* Wgl = awl + (size_t)kz*H*H;
    #pragma unroll
    for (int i = 0; i < 8; ++i) {
        int idx = tid + i*256;
        int r = idx >> 4, seg = (idx & 15)*8;
        cpa16(Bh + r*QKS + seg, Wgh + (size_t)r*H + seg);
        cpa16(Bl + r*QKS + seg, Wgl + (size_t)r*H + seg);
    }
    cp_commit(); cp_wait0();
    __syncthreads();

    run_gemm();
    #pragma unroll
    for (int mi = 0; mi < 2; ++mi)
        #pragma unroll
        for (int ni = 0; ni < 8; ++ni)
            #pragma unroll
            for (int e = 0; e < 4; ++e) {
                int r = wm + mi*16 + gid + ((e >= 2) ? 8 : 0);
                int c = wn + ni*8 + 2*tig + (e & 1);
                wh2[((size_t)z*Bq + mt*128 + r)*H + c] = acc[mi][ni][e];
            }
}

// ======== fused h1/vh GEMM + attention (one-sided fp16: 2 MMAs per k16) ========
#define FU_GEMM_BYTES ((2*128*QKS + 256*QKS)*2)
#define FU_EPI_BYTES  ((128*132 + 128*132 + 8*128 + 128 + 128)*4)
#define FU_SMEM       (FU_EPI_BYTES > FU_GEMM_BYTES ? FU_EPI_BYTES : FU_GEMM_BYTES)
__global__ __launch_bounds__(512,1) void fused_attn(
    const __half* __restrict__ yhg, const __half* __restrict__ ylg,
    const __half* __restrict__ ckh, const float* __restrict__ ckb,
    const __half* __restrict__ vwh, const float* __restrict__ vb,
    const float* __restrict__ wh2,
    const float* __restrict__ xsh, float* __restrict__ sout)
{
    extern __shared__ __align__(16) char smc[];
    float* sm = (float*)smc;
    __half* Ah = (__half*)smc;         // [128*QKS]
    __half* Al = Ah + 128*QKS;
    __half* Bs = Al + 128*QKS;         // [256*QKS] single fp16
    int mt = blockIdx.x, z = blockIdx.y;
    int tid = threadIdx.x;

    const __half* Agh = yhg + ((size_t)z*BM_ + mt*128)*H;
    const __half* Agl = ylg + ((size_t)z*BM_ + mt*128)*H;
    size_t wkb = (size_t)z*H*H;

    #pragma unroll
    for (int i = 0; i < 4; ++i) {
        int idx = tid + i*512;
        int r = idx >> 4, seg = (idx & 15)*8;
        cpa16(Ah + r*QKS + seg, Agh + (size_t)r*H + seg);
        cpa16(Al + r*QKS + seg, Agl + (size_t)r*H + seg);
    }
    #pragma unroll
    for (int i = 0; i < 8; ++i) {
        int idx = tid + i*512;
        int n = idx >> 4, seg = (idx & 15)*8;
        const __half* src = (n < 128) ? (ckh + wkb + (size_t)n*H)
                                      : (vwh + wkb + (size_t)(n-128)*H);
        cpa16(Bs + n*QKS + seg, src + seg);
    }
    cp_commit(); cp_wait0();
    __syncthreads();

    int w = tid >> 5, lane = tid & 31, gid = lane >> 2, tig = lane & 3;
    int wm = (w & 3)*32, wn = (w >> 2)*64;
    int arow = lane & 15, acol = (lane & 16) ? 8 : 0;
    int bn = (lane & 7) + ((lane & 16) ? 8 : 0), bk = (lane & 8) ? 8 : 0;
    unsigned aAh = s2u(Ah), aAl = s2u(Al), aB = s2u(Bs);

    float acc[2][8][4];
    #pragma unroll
    for (int i = 0; i < 2; ++i)
        #pragma unroll
        for (int j = 0; j < 8; ++j)
            #pragma unroll
            for (int e = 0; e < 4; ++e) acc[i][j][e] = 0.f;

    #pragma unroll
    for (int kk = 0; kk < 8; ++kk) {
        int kb = kk*16;
        unsigned ah[2][4], al[2][4];
        #pragma unroll
        for (int mi = 0; mi < 2; ++mi) {
            unsigned off = (unsigned)(((wm + mi*16 + arow)*QKS + kb + acol)*2);
            ldsm4(ah[mi][0], ah[mi][1], ah[mi][2], ah[mi][3], aAh + off);
            ldsm4(al[mi][0], al[mi][1], al[mi][2], al[mi][3], aAl + off);
        }
        #pragma unroll
        for (int nh = 0; nh < 2; ++nh) {
            unsigned b_[4][2];
            #pragma unroll
            for (int nj = 0; nj < 2; ++nj) {
                unsigned off_ = (unsigned)(((wn + nh*32 + nj*16 + bn)*QKS + kb + bk)*2);
                ldsm4(b_[nj*2][0], b_[nj*2][1], b_[nj*2+1][0], b_[nj*2+1][1], aB + off_);
            }
            #pragma unroll
            for (int ni = 0; ni < 4; ++ni)
                #pragma unroll
                for (int mi = 0; mi < 2; ++mi)
                    mma_f16(acc[mi][nh*4+ni], al[mi], b_[ni]);
            #pragma unroll
            for (int ni = 0; ni < 4; ++ni)
                #pragma unroll
                for (int mi = 0; mi < 2; ++mi)
                    mma_f16(acc[mi][nh*4+ni], ah[mi], b_[ni]);
        }
    }
    __syncthreads();   // all smem reads done before epilogue aliasing

    float* SP  = sm;                 // [128][132]  h1 (lrelu+bias)
    float* SV  = SP + 128*132;       // [128][132]  vh (+bias)
    float* SW  = SV + 128*132;       // [8][128]    wh2 rows
    float* SSC = SW + 8*128;         // [128] scores
    float* SE  = SSC + 128;          // [128] softmax weights

    #pragma unroll
    for (int mi = 0; mi < 2; ++mi)
        #pragma unroll
        for (int ni = 0; ni < 8; ++ni)
            #pragma unroll
            for (int e = 0; e < 4; ++e) {
                int r = wm + mi*16 + gid + ((e >= 2) ? 8 : 0);
                int c = wn + ni*8 + 2*tig + (e & 1);
                float v = acc[mi][ni][e];
                if (c < 128) SP[r*132 + c] = lrelu_f(v + ckb[z*H + c]);
                else         SV[r*132 + (c-128)] = v + vb[z*H + (c-128)];
            }
    #pragma unroll
    for (int t = 0; t < 2; ++t) {
        int idx = tid + t*512;
        int bl = idx >> 7, o = idx & 127;
        SW[idx] = wh2[((size_t)z*Bq + mt*8 + bl)*H + o];
    }
    __syncthreads();

    #pragma unroll
    for (int i = 0; i < 8; ++i) {
        int rr = w*8 + i;
        const float* wrow = SW + (rr >> 4)*128;
        float p = 0.f;
        #pragma unroll
        for (int o = 0; o < 128; o += 32) p += SP[rr*132 + o + lane]*wrow[o + lane];
        #pragma unroll
        for (int d_ = 16; d_ > 0; d_ >>= 1) p += __shfl_xor_sync(0xffffffffu, p, d_);
        if (lane == 0) SSC[rr] = p;
    }
    __syncthreads();
    if (tid < 8) {
        float mx = -1e30f;
        #pragma unroll
        for (int m = 0; m < M; ++m) mx = fmaxf(mx, SSC[tid*M + m]);
        float es[M], sum = 0.f;
        #pragma unroll
        for (int m = 0; m < M; ++m) { es[m] = expf(SSC[tid*M + m] - mx); sum += es[m]; }
        float inv = 1.f/sum;
        #pragma unroll
        for (int m = 0; m < M; ++m) SE[tid*M + m] = es[m]*inv;
    }
    __syncthreads();

    int s = z/HN, hh = z%HN;
    #pragma unroll
    for (int t = 0; t < 2; ++t) {
        int idx = tid + t*512;
        int bl = idx >> 7, o = idx & 127;
        float a = 0.f;
        #pragma unroll
        for (int m = 0; m < M; ++m) {
            float v = SV[(bl*M + m)*132 + o]*SE[bl*M + m];
            a += (v >= 0.f) ? v : ALPHA*v;
        }
        int b = mt*8 + bl;
        sout[((size_t)s*Bq + b)*D + hh*H + o] =
            0.5f*(xsh[((size_t)z*Bq + b)*H + o] + a);
    }
}

// ---------------- semantic attention (smem-tiled weights, 8 targets/block) -----
#define SEM_SMEM(P) ((8*(P)*D + 64*132 + 8*(P)*132 + 32)*4)
template<int P>
__global__ __launch_bounds__(128) void semantic(
    const float* __restrict__ zin, const float* __restrict__ p1w,
    const float* __restrict__ p1b, const float* __restrict__ p2w,
    float* __restrict__ outp, int in_pstride, int in_bstride, int out_bstride)
{
    extern __shared__ __align__(16) float sem[];
    float* zs   = sem;                         // [8P][512]
    float* pwT  = sem + 8*P*D;                 // [64][132] transposed chunk
    float* sred = pwT + 64*132;                // [8P][132]
    float* ssc  = sred + 8*P*132;              // [8P]
    int b0 = blockIdx.x*8, tid = threadIdx.x;

    for (int idx = tid; idx < 8*P*(D/4); idx += 128) {
        int d4 = idx & (D/4 - 1); int rp = idx / (D/4);
        int p = rp % P, bl = rp / P;
        *(float4*)&zs[(bl*P+p)*D + d4*4] =
            *(const float4*)(zin + (size_t)(b0+bl)*in_bstride + (size_t)p*in_pstride + d4*4);
    }
    __syncthreads();

    float acc[8][P];
    #pragma unroll
    for (int bl = 0; bl < 8; ++bl)
        #pragma unroll
        for (int p = 0; p < P; ++p) acc[bl][p] = 0.f;

    for (int d0 = 0; d0 < D; d0 += 64) {
        #pragma unroll
        for (int i = 0; i < 16; ++i) {
            int idx = tid + i*128;
            int r = idx >> 4, c4 = (idx & 15)*4;
            float4 v = *(const float4*)(p1w + (size_t)r*D + d0 + c4);
            pwT[c4*132 + r]     = v.x;
            pwT[(c4+1)*132 + r] = v.y;
            pwT[(c4+2)*132 + r] = v.z;
            pwT[(c4+3)*132 + r] = v.w;
        }
        __syncthreads();
        #pragma unroll 4
        for (int dd = 0; dd < 64; dd += 4) {
            float w0 = pwT[dd*132 + tid],     w1 = pwT[(dd+1)*132 + tid];
            float w2 = pwT[(dd+2)*132 + tid], w3 = pwT[(dd+3)*132 + tid];
            #pragma unroll
            for (int bl = 0; bl < 8; ++bl)
                #pragma unroll
                for (int p = 0; p < P; ++p) {
                    float4 zv = *(const float4*)&zs[(bl*P+p)*D + d0 + dd];
                    acc[bl][p] += w0*zv.x + w1*zv.y + w2*zv.z + w3*zv.w;
                }
        }
        __syncthreads();
    }

    float bias = p1b[tid], p2 = p2w[tid];
    #pragma unroll
    for (int bl = 0; bl < 8; ++bl)
        #pragma unroll
        for (int p = 0; p < P; ++p)
            sred[(bl*P+p)*132 + tid] = tanhf(acc[bl][p] + bias)*p2;
    __syncthreads();
    if (tid < 8*P) {
        float s_ = 0.f;
        for (int o = 0; o < H; ++o) s_ += sred[tid*132 + o];
        ssc[tid] = s_;
    }
    __syncthreads();
    if (tid < 8) {
        float mx = -1e30f;
        #pragma unroll
        for (int p = 0; p < P; ++p) mx = fmaxf(mx, ssc[tid*P + p]);
        float e[P]; float esum = 0.f;
        #pragma unroll
        for (int p = 0; p < P; ++p) { e[p] = expf(ssc[tid*P + p] - mx); esum += e[p]; }
        float inv = 1.f/esum;
        #pragma unroll
        for (int p = 0; p < P; ++p) ssc[tid*P + p] = e[p]*inv;
    }
    __syncthreads();
    for (int idx = tid; idx < 8*(D/4); idx += 128) {
        int d4 = (idx & (D/4 - 1))*4; int bl = idx / (D/4);
        float4 o = {0.f, 0.f, 0.f, 0.f};
        #pragma unroll
        for (int p = 0; p < P; ++p) {
            float e = ssc[bl*P + p];
            float4 zv = *(const float4*)&zs[(bl*P+p)*D + d4];
            o.x += e*zv.x; o.y += e*zv.y; o.z += e*zv.z; o.w += e*zv.w;
        }
        *(float4*)(outp + (size_t)(b0+bl)*out_bstride + d4) = o;
    }
}

extern "C" void kernel_launch(void* const* d_in, const int* in_sizes, int n_in,
                              void* d_out, int out_size)
{
    const float* x     = (const float*)d_in[0];
    const int*   tgt   = (const int*)  d_in[1];
    const int*   neigh = (const int*)  d_in[2];
    const float* fc_w  = (const float*)d_in[3];
    const float* fc_b  = (const float*)d_in[4];
    const float* q_w   = (const float*)d_in[5];
    const float* q_b   = (const float*)d_in[6];
    const float* k_w   = (const float*)d_in[7];
    const float* k_b   = (const float*)d_in[8];
    const float* v_w   = (const float*)d_in[9];
    const float* v_b   = (const float*)d_in[10];
    const float* att_W = (const float*)d_in[11];
    const float* a1w   = (const float*)d_in[12];
    const float* a1b   = (const float*)d_in[13];
    const float* a2w   = (const float*)d_in[14];
    const float* a2b   = (const float*)d_in[15];
    const float* ip1w  = (const float*)d_in[16];
    const float* ip1b  = (const float*)d_in[17];
    const float* ip2w  = (const float*)d_in[18];
    const float* bp1w  = (const float*)d_in[19];
    const float* bp1b  = (const float*)d_in[20];
    const float* bp2w  = (const float*)d_in[21];
    float* out = (float*)d_out;

    __nv_bfloat16 *xhi,*xlo,*fwh,*fwl,*awh,*awl,*cqwh,*cqwl,*xshh,*xshl;
    __half *vwh,*ckh,*yh,*yl;
    float *ckb,*cqb,*xsh,*wh2,*sout,*mp;
    cudaGetSymbolAddress((void**)&xhi,  g_xhi);
    cudaGetSymbolAddress((void**)&xlo,  g_xlo);
    cudaGetSymbolAddress((void**)&fwh,  g_fwh);
    cudaGetSymbolAddress((void**)&fwl,  g_fwl);
    cudaGetSymbolAddress((void**)&vwh,  g_vwh);
    cudaGetSymbolAddress((void**)&awh,  g_awh);
    cudaGetSymbolAddress((void**)&awl,  g_awl);
    cudaGetSymbolAddress((void**)&ckh,  g_ckh);
    cudaGetSymbolAddress((void**)&ckb,  g_ckb);
    cudaGetSymbolAddress((void**)&cqwh, g_cqwh);
    cudaGetSymbolAddress((void**)&cqwl, g_cqwl);
    cudaGetSymbolAddress((void**)&cqb,  g_cqb);
    cudaGetSymbolAddress((void**)&xsh,  g_xsh);
    cudaGetSymbolAddress((void**)&xshh, g_xshh);
    cudaGetSymbolAddress((void**)&xshl, g_xshl);
    cudaGetSymbolAddress((void**)&yh,   g_yh);
    cudaGetSymbolAddress((void**)&yl,   g_yl);
    cudaGetSymbolAddress((void**)&wh2,  g_wh2);
    cudaGetSymbolAddress((void**)&sout, g_sout);
    cudaGetSymbolAddress((void**)&mp,   g_mp);

    static int smem_set = 0;
    if (!smem_set) {
        cudaFuncSetAttribute(fc_bf16,     cudaFuncAttributeMaxDynamicSharedMemorySize, FC2_SMEM);
        cudaFuncSetAttribute(qk_fused,    cudaFuncAttributeMaxDynamicSharedMemorySize, QK_SMEM);
        cudaFuncSetAttribute(fused_attn,  cudaFuncAttributeMaxDynamicSharedMemorySize, FU_SMEM);
        cudaFuncSetAttribute(semantic<2>, cudaFuncAttributeMaxDynamicSharedMemorySize, SEM_SMEM(2));
        cudaFuncSetAttribute(semantic<3>, cudaFuncAttributeMaxDynamicSharedMemorySize, SEM_SMEM(3));
        smem_set = 1;
    }

    // 0. operand prep
    split_all<<<(SPL_TOT + 255)/256, 256>>>(x, xhi, xlo, fc_w, fwh, fwl,
                                            v_w, vwh, att_W, awh, awl);

    // 1. fold attention-layer weights into k/q projections
    combine_gemm<<<dim3(4, PAIRS, 2), 256>>>(a1w, a1b, k_w, k_b, ckh, ckb,
                                             a2w, a2b, q_w, q_b, cqwh, cqwl, cqb);

    // 2. shared fc + leakyrelu on gathered neighbors + targets (bf16 3-term)
    fc_bf16<<<dim3(R_/128, 4, S), 256, FC2_SMEM>>>(xhi, xlo, neigh, tgt, fwh, fwl,
                                                   fc_b, yh, yl, xsh, xshh, xshl);

    // 3. wh2 = (lrelu(xsh@cq^T + cqb)) @ attW^T (bf16 3-term)
    qk_fused<<<dim3(Bq/128, PAIRS), 256, QK_SMEM>>>(xshh, xshl, cqwh, cqwl, cqb,
                                                    awh, awl, wh2);

    // 4. fused h1/vh GEMM + neighbor attention + residual (one-sided fp16, 2-term)
    fused_attn<<<dim3(BM_/128, PAIRS), 512, FU_SMEM>>>(yh, yl, ckh, ckb,
                                                       vwh, v_b, wh2, xsh, sout);

    // 5. semantic attention within each metapath
    semantic<2><<<Bq/8, 128, SEM_SMEM(2)>>>(sout,          ip1w,       ip1b,     ip2w,     mp,     Bq*D, D, KM*D);
    semantic<3><<<Bq/8, 128, SEM_SMEM(3)>>>(sout + 2*Bq*D, ip1w + H*D, ip1b + H, ip2w + H, mp + D, Bq*D, D, KM*D);

    // 6. semantic attention between metapaths -> final output
    semantic<2><<<Bq/8, 128, SEM_SMEM(2)>>>(mp, bp1w, bp1b, bp2w, out, D, KM*D, D);
}

// round 14
// speedup vs baseline: 1.3956x; 1.0802x over previous
#include <cuda_runtime.h>
#include <cuda_bf16.h>
#include <cuda_fp16.h>
#include <math.h>

#define NN    20000
#define IN_F  256
#define H     128
#define HN    4
#define S     5
#define KM    2
#define Bq    1024
#define M     16
#define D     512
#define ALPHA 0.2f
#define BM_   (Bq*M)      /* 16384 */
#define R_    (BM_ + Bq)  /* 17408 */
#define PAIRS (S*HN)      /* 20 */

#define KC    32          /* K halves per pipeline stage (fc) */
#define HS    40          /* fc smem row stride in halves */
#define QKS   136         /* full-K smem row stride in halves */

__constant__ int c_kofs[S] = {0,0,1,1,1};

// ---------------- scratch ----------------
__device__ __half g_xhi[NN*IN_F];                   /* fp16 hi */
__device__ __half g_xlo[NN*IN_F];                   /* fp16 lo */
__device__ __half g_fwh[S*4*H*IN_F];                /* single fp16 */
__device__ __half g_vwh[PAIRS*H*H];                 /* single fp16 */
__device__ __nv_bfloat16 g_awh[KM*HN*H*H];
__device__ __nv_bfloat16 g_awl[KM*HN*H*H];
__device__ __half g_ckh[PAIRS*H*H];                 /* single fp16 */
__device__ float g_ckb[PAIRS*H];
__device__ __nv_bfloat16 g_cqwh[PAIRS*H*H];
__device__ __nv_bfloat16 g_cqwl[PAIRS*H*H];
__device__ float g_cqb[PAIRS*H];
__device__ float g_xsh[PAIRS*Bq*H];
__device__ __nv_bfloat16 g_xshh[PAIRS*Bq*H];
__device__ __nv_bfloat16 g_xshl[PAIRS*Bq*H];
__device__ __half g_yh[(size_t)PAIRS*BM_*H];        /* fp16 hi */
__device__ __half g_yl[(size_t)PAIRS*BM_*H];        /* fp16 lo */
__device__ float g_wh2[PAIRS*Bq*H];
__device__ float g_sout[S*Bq*D];
__device__ float g_mp[Bq*KM*D];

// ---------------- helpers ----------------
__device__ __forceinline__ void mma_bf16(float* d, const unsigned* a, const unsigned* b) {
    asm volatile(
      "mma.sync.aligned.m16n8k16.row.col.f32.bf16.bf16.f32 "
      "{%0,%1,%2,%3}, {%4,%5,%6,%7}, {%8,%9}, {%0,%1,%2,%3};\n"
      : "+f"(d[0]), "+f"(d[1]), "+f"(d[2]), "+f"(d[3])
      : "r"(a[0]), "r"(a[1]), "r"(a[2]), "r"(a[3]), "r"(b[0]), "r"(b[1]));
}
__device__ __forceinline__ void mma_f16(float* d, const unsigned* a, const unsigned* b) {
    asm volatile(
      "mma.sync.aligned.m16n8k16.row.col.f32.f16.f16.f32 "
      "{%0,%1,%2,%3}, {%4,%5,%6,%7}, {%8,%9}, {%0,%1,%2,%3};\n"
      : "+f"(d[0]), "+f"(d[1]), "+f"(d[2]), "+f"(d[3])
      : "r"(a[0]), "r"(a[1]), "r"(a[2]), "r"(a[3]), "r"(b[0]), "r"(b[1]));
}
__device__ __forceinline__ void ldsm4(unsigned& r0, unsigned& r1, unsigned& r2, unsigned& r3,
                                      unsigned addr) {
    asm volatile("ldmatrix.sync.aligned.m8n8.x4.shared.b16 {%0,%1,%2,%3}, [%4];\n"
      : "=r"(r0), "=r"(r1), "=r"(r2), "=r"(r3) : "r"(addr));
}
__device__ __forceinline__ unsigned s2u(const void* p) {
    return (unsigned)__cvta_generic_to_shared(p);
}
__device__ __forceinline__ void split_bf(float x, __nv_bfloat16& h, __nv_bfloat16& l) {
    h = __float2bfloat16_rn(x);
    l = __float2bfloat16_rn(x - __bfloat162float(h));
}
__device__ __forceinline__ void split_h(float x, __half& h, __half& l) {
    h = __float2half_rn(x);
    l = __float2half_rn(x - __half2float(h));
}
__device__ __forceinline__ void cpa16(void* dst, const void* src) {
    unsigned d = (unsigned)__cvta_generic_to_shared(dst);
    asm volatile("cp.async.cg.shared.global [%0], [%1], 16;\n" :: "r"(d), "l"(src));
}
__device__ __forceinline__ void cp_commit() { asm volatile("cp.async.commit_group;\n"); }
__device__ __forceinline__ void cp_wait1() { asm volatile("cp.async.wait_group 1;\n"); }
__device__ __forceinline__ void cp_wait0() { asm volatile("cp.async.wait_group 0;\n"); }
__device__ __forceinline__ float lrelu_f(float v) { return v >= 0.f ? v : ALPHA*v; }

// half-N term-major step (bf16 3-term) — used by qk only
#define MMA_HALF_STEP(acc, ah, al, aBh, aBl, STRIDE, kb, bkv, bnv, wnv, nh)       \
    {                                                                             \
        unsigned bh_[4][2], bl_[4][2];                                            \
        _Pragma("unroll")                                                         \
        for (int nj = 0; nj < 2; ++nj) {                                          \
            unsigned off_ = (unsigned)((((wnv) + (nh)*32 + nj*16 + (bnv))*(STRIDE) + (kb) + (bkv))*2); \
            ldsm4(bh_[nj*2][0], bh_[nj*2][1], bh_[nj*2+1][0], bh_[nj*2+1][1], (aBh) + off_); \
            ldsm4(bl_[nj*2][0], bl_[nj*2][1], bl_[nj*2+1][0], bl_[nj*2+1][1], (aBl) + off_); \
        }                                                                         \
        _Pragma("unroll")                                                         \
        for (int ni = 0; ni < 4; ++ni)                                            \
            _Pragma("unroll")                                                     \
            for (int mi = 0; mi < 2; ++mi)                                        \
                mma_bf16(acc[mi][(nh)*4+ni], ah[mi], bl_[ni]);                    \
        _Pragma("unroll")                                                         \
        for (int ni = 0; ni < 4; ++ni)                                            \
            _Pragma("unroll")                                                     \
            for (int mi = 0; mi < 2; ++mi)                                        \
                mma_bf16(acc[mi][(nh)*4+ni], al[mi], bh_[ni]);                    \
        _Pragma("unroll")                                                         \
        for (int ni = 0; ni < 4; ++ni)                                            \
            _Pragma("unroll")                                                     \
            for (int mi = 0; mi < 2; ++mi)                                        \
                mma_bf16(acc[mi][(nh)*4+ni], ah[mi], bh_[ni]);                    \
    }

// ---------------- all operand-prep splits in ONE launch ----------------
#define SPL_N1 (NN*IN_F)
#define SPL_N2 (S*4*H*IN_F)
#define SPL_N3 (PAIRS*H*H)
#define SPL_N4 (KM*HN*H*H)
#define SPL_TOT (SPL_N1 + SPL_N2 + SPL_N3 + SPL_N4)
__global__ void split_all(
    const float* __restrict__ x,    __half* __restrict__ xhi, __half* __restrict__ xlo,
    const float* __restrict__ fcw,  __half* __restrict__ fwh,
    const float* __restrict__ vw,   __half* __restrict__ vwh,
    const float* __restrict__ attw, __nv_bfloat16* __restrict__ awh, __nv_bfloat16* __restrict__ awl)
{
    int i = blockIdx.x*256 + threadIdx.x;
    if (i < SPL_N1) { split_h(x[i], xhi[i], xlo[i]); return; }
    if (i < SPL_N1+SPL_N2) { int j = i - SPL_N1; fwh[j] = __float2half_rn(fcw[j]); return; }
    if (i < SPL_N1+SPL_N2+SPL_N3) {
        int j = i - SPL_N1 - SPL_N2;
        vwh[j] = __float2half_rn(vw[j]);
        return;
    }
    if (i < SPL_TOT) { int j = i - SPL_N1 - SPL_N2 - SPL_N3; split_bf(attw[j], awh[j], awl[j]); }
}

// ---------------- combined weights (ck -> single fp16; cq -> bf16 split) -------
__global__ __launch_bounds__(256) void combine_gemm(
    const float* __restrict__ a1w, const float* __restrict__ a1b,
    const float* __restrict__ k_w, const float* __restrict__ k_b,
    __half* __restrict__ ckh, float* __restrict__ ckb,
    const float* __restrict__ a2w, const float* __restrict__ a2b,
    const float* __restrict__ q_w, const float* __restrict__ q_b,
    __nv_bfloat16* __restrict__ cqh, __nv_bfloat16* __restrict__ cql, float* __restrict__ cqb)
{
    int ot = blockIdx.x, z = blockIdx.y, which = blockIdx.z, tid = threadIdx.x;
    const float* aw = which ? a2w : a1w;
    const float* ab = which ? a2b : a1b;
    const float* w  = which ? q_w : k_w;
    const float* wb = which ? q_b : k_b;
    float* cb = which ? cqb : ckb;
    int kz = c_kofs[z/HN]*HN + (z % HN);
    const float* A = aw + ((size_t)kz*H + ot*32)*H;
    const float* W = w + (size_t)z*H*H;
    __shared__ float sa[32][36];
    __shared__ float sw[32][132];
    int tx = tid & 15, ty = tid >> 4;
    float acc[2][8];
    #pragma unroll
    for (int r = 0; r < 2; ++r)
        #pragma unroll
        for (int c = 0; c < 8; ++c) acc[r][c] = 0.f;
    for (int kc = 0; kc < 4; ++kc) {
        {
            int r = tid >> 3, c4 = (tid & 7)*4;
            *(float4*)&sa[r][c4] = *(const float4*)(A + r*H + kc*32 + c4);
        }
        #pragma unroll
        for (int i = 0; i < 4; ++i) {
            int idx = tid + i*256;
            int r = idx >> 5, c4 = (idx & 31)*4;
            *(float4*)&sw[r][c4] = *(const float4*)(W + (kc*32 + r)*H + c4);
        }
        __syncthreads();
        #pragma unroll 8
        for (int j = 0; j < 32; ++j) {
            float a0 = sa[ty*2][j], a1 = sa[ty*2+1][j];
            #pragma unroll
            for (int c = 0; c < 8; ++c) {
                float wv = sw[j][tx*8 + c];
                acc[0][c] += a0*wv;
                acc[1][c] += a1*wv;
            }
        }
        __syncthreads();
    }
    #pragma unroll
    for (int r = 0; r < 2; ++r)
        #pragma unroll
        for (int c = 0; c < 8; ++c) {
            size_t idx = ((size_t)z*H + ot*32 + ty*2 + r)*H + tx*8 + c;
            if (which) split_bf(acc[r][c], cqh[idx], cql[idx]);
            else       ckh[idx] = __float2half_rn(acc[r][c]);
        }
    if (tid < 32) {
        int o = ot*32 + tid;
        float bacc = ab[kz*H + o];
        const float* arow = aw + ((size_t)kz*H + o)*H;
        const float* brow = wb + z*H;
        for (int j = 0; j < H; ++j) bacc += arow[j]*brow[j];
        cb[z*H + o] = bacc;
    }
}

// ========= fc GEMM (one-sided fp16: A hi/lo, B single; 2 MMAs per k16) =========
// smem: GEMM phase uses 6*128*HS halves (61440 B) + rows; epilogue aliases as
// float[128][132] (67584 B) -> allocation must cover the max.
#define FC_GEMM_BYTES (6*128*HS*2)
#define FC_EPI_BYTES  (128*132*4)
#define FC_CORE_BYTES (FC_EPI_BYTES > FC_GEMM_BYTES ? FC_EPI_BYTES : FC_GEMM_BYTES)
#define FC2_SMEM      (FC_CORE_BYTES + 512)
__global__ __launch_bounds__(256,2) void fc_f16(
    const __half* __restrict__ xh, const __half* __restrict__ xl,
    const int* __restrict__ neigh, const int* __restrict__ tgt,
    const __half* __restrict__ fwh,
    const float* __restrict__ fcb,
    __half* __restrict__ yh, __half* __restrict__ yl,
    float* __restrict__ xsh,
    __nv_bfloat16* __restrict__ xshh, __nv_bfloat16* __restrict__ xshl)
{
    extern __shared__ __align__(16) char smc[];
    __half* Ah = (__half*)smc;          // [2][128*HS]
    __half* Al = Ah + 2*128*HS;
    __half* Bs = Al + 2*128*HS;         // [2][128*HS]
    int* rows = (int*)(smc + FC_CORE_BYTES);   // outside the aliased core region
    int mt = blockIdx.x, nt = blockIdx.y, s = blockIdx.z;
    int tid = threadIdx.x;
    if (tid < 128) {
        int r = mt*128 + tid;
        rows[tid] = (r < BM_) ? neigh[s*BM_ + r] : tgt[r - BM_];
    }
    __syncthreads();
    size_t wb = ((size_t)s*512 + nt*128)*IN_F;

    auto prefetch = [&](int kc, int buf) {
        #pragma unroll
        for (int i = 0; i < 2; ++i) {
            int idx = tid + i*256;
            int r = idx >> 2, seg = (idx & 3)*8;
            int so = buf*128*HS + r*HS + seg;
            size_t ga = (size_t)rows[r]*IN_F + kc*KC + seg;
            size_t gb = wb + (size_t)r*IN_F + kc*KC + seg;
            cpa16(Ah + so, xh + ga);
            cpa16(Al + so, xl + ga);
            cpa16(Bs + so, fwh + gb);
        }
    };

    int w = tid >> 5, lane = tid & 31;
    int wm = (w & 3)*32, wn = (w >> 2)*64;
    int arow = lane & 15, acol = (lane & 16) ? 8 : 0;
    int bn = (lane & 7) + ((lane & 16) ? 8 : 0), bk = (lane & 8) ? 8 : 0;
    unsigned aAh = s2u(Ah), aAl = s2u(Al), aB = s2u(Bs);

    float acc[2][8][4];
    #pragma unroll
    for (int i = 0; i < 2; ++i)
        #pragma unroll
        for (int j = 0; j < 8; ++j)
            #pragma unroll
            for (int e = 0; e < 4; ++e) acc[i][j][e] = 0.f;

    prefetch(0, 0); cp_commit();
    const int NCH = IN_F/KC;  // 8
    for (int kc = 0; kc < NCH; ++kc) {
        if (kc+1 < NCH) { prefetch(kc+1, (kc+1)&1); cp_commit(); cp_wait1(); }
        else            { cp_wait0(); }
        __syncthreads();
        unsigned bufo = (unsigned)((kc&1)*128*HS);
        #pragma unroll
        for (int kk = 0; kk < 2; ++kk) {
            int kb = kk*16;
            unsigned ah[2][4], al[2][4];
            #pragma unroll
            for (int mi = 0; mi < 2; ++mi) {
                unsigned off = (unsigned)((bufo + (wm + mi*16 + arow)*HS + kb + acol)*2);
                ldsm4(ah[mi][0], ah[mi][1], ah[mi][2], ah[mi][3], aAh + off);
                ldsm4(al[mi][0], al[mi][1], al[mi][2], al[mi][3], aAl + off);
            }
            #pragma unroll
            for (int nh = 0; nh < 2; ++nh) {
                unsigned b_[4][2];
                #pragma unroll
                for (int nj = 0; nj < 2; ++nj) {
                    unsigned off_ = (unsigned)((bufo + (wn + nh*32 + nj*16 + bn)*HS + kb + bk)*2);
                    ldsm4(b_[nj*2][0], b_[nj*2][1], b_[nj*2+1][0], b_[nj*2+1][1], aB + off_);
                }
                #pragma unroll
                for (int ni = 0; ni < 4; ++ni)
                    #pragma unroll
                    for (int mi = 0; mi < 2; ++mi)
                        mma_f16(acc[mi][nh*4+ni], al[mi], b_[ni]);
                #pragma unroll
                for (int ni = 0; ni < 4; ++ni)
                    #pragma unroll
                    for (int mi = 0; mi < 2; ++mi)
                        mma_f16(acc[mi][nh*4+ni], ah[mi], b_[ni]);
            }
        }
        __syncthreads();
    }

    int zp = s*HN + nt;
    int gid = lane >> 2, tig = lane & 3;
    float* Cs = (float*)smc;  // 128x132 (fits: FC_CORE_BYTES >= 67584)
    #pragma unroll
    for (int mi = 0; mi < 2; ++mi)
        #pragma unroll
        for (int ni = 0; ni < 8; ++ni)
            #pragma unroll
            for (int e = 0; e < 4; ++e) {
                int r = wm + mi*16 + gid + ((e >= 2) ? 8 : 0);
                int c = wn + ni*8 + 2*tig + (e & 1);
                Cs[r*132 + c] = lrelu_f(acc[mi][ni][e] + fcb[zp*H + c]);
            }
    __syncthreads();
    #pragma unroll
    for (int t = 0; t < 16; ++t) {
        int idx = tid + t*256;
        int rr = idx >> 5, c4 = (idx & 31)*4;
        float4 v = *(const float4*)(Cs + rr*132 + c4);
        int gr = mt*128 + rr;
        if (gr < BM_) {
            __half h0,h1,h2_,h3,l0,l1,l2,l3;
            split_h(v.x,h0,l0); split_h(v.y,h1,l1);
            split_h(v.z,h2_,l2); split_h(v.w,h3,l3);
            __half2 ph0 = {h0,h1}, ph1 = {h2_,h3};
            __half2 pl0 = {l0,l1}, pl1 = {l2,l3};
            uint2 uh, ul;
            uh.x = *(unsigned*)&ph0; uh.y = *(unsigned*)&ph1;
            ul.x = *(unsigned*)&pl0; ul.y = *(unsigned*)&pl1;
            size_t base = ((size_t)zp*BM_ + gr)*H + c4;
            *(uint2*)(yh + base) = uh;
            *(uint2*)(yl + base) = ul;
        } else {
            size_t base = ((size_t)zp*Bq + (gr - BM_))*H + c4;
            *(float4*)(xsh + base) = v;
            __nv_bfloat16 h0,h1,h2_,h3,l0,l1,l2,l3;
            split_bf(v.x,h0,l0); split_bf(v.y,h1,l1);
            split_bf(v.z,h2_,l2); split_bf(v.w,h3,l3);
            __nv_bfloat162 ph0 = {h0,h1}, ph1 = {h2_,h3};
            __nv_bfloat162 pl0 = {l0,l1}, pl1 = {l2,l3};
            uint2 uh, ul;
            uh.x = *(unsigned*)&ph0; uh.y = *(unsigned*)&ph1;
            ul.x = *(unsigned*)&pl0; ul.y = *(unsigned*)&pl1;
            *(uint2*)(xshh + base) = uh;
            *(uint2*)(xshl + base) = ul;
        }
    }
}

// ================= qk_fused (bf16 3-term, unchanged) =================
#define QK_SMEM (4*128*QKS*2)
__global__ __launch_bounds__(256,1) void qk_fused(
    const __nv_bfloat16* __restrict__ xshh, const __nv_bfloat16* __restrict__ xshl,
    const __nv_bfloat16* __restrict__ cqh, const __nv_bfloat16* __restrict__ cql,
    const float* __restrict__ cqb,
    const __nv_bfloat16* __restrict__ awh, const __nv_bfloat16* __restrict__ awl,
    float* __restrict__ wh2)
{
    extern __shared__ __align__(16) char smc[];
    __nv_bfloat16* Axh = (__nv_bfloat16*)smc;
    __nv_bfloat16* Axl = Axh + 128*QKS;
    __nv_bfloat16* Bh  = Axl + 128*QKS;
    __nv_bfloat16* Bl  = Bh + 128*QKS;
    int mt = blockIdx.x, z = blockIdx.y;
    int tid = threadIdx.x;
    int kz = c_kofs[z/HN]*HN + (z % HN);

    const __nv_bfloat16* Agh = xshh + ((size_t)z*Bq + mt*128)*H;
    const __nv_bfloat16* Agl = xshl + ((size_t)z*Bq + mt*128)*H;
    const __nv_bfloat16* Bgh = cqh + (size_t)z*H*H;
    const __nv_bfloat16* Bgl = cql + (size_t)z*H*H;

    #pragma unroll
    for (int i = 0; i < 8; ++i) {
        int idx = tid + i*256;
        int r = idx >> 4, seg = (idx & 15)*8;
        cpa16(Axh + r*QKS + seg, Agh + (size_t)r*H + seg);
        cpa16(Axl + r*QKS + seg, Agl + (size_t)r*H + seg);
        cpa16(Bh + r*QKS + seg, Bgh + (size_t)r*H + seg);
        cpa16(Bl + r*QKS + seg, Bgl + (size_t)r*H + seg);
    }
    cp_commit(); cp_wait0();
    __syncthreads();

    int w = tid >> 5, lane = tid & 31, gid = lane >> 2, tig = lane & 3;
    int wm = (w & 3)*32, wn = (w >> 2)*64;
    int arow = lane & 15, acol = (lane & 16) ? 8 : 0;
    int bn = (lane & 7) + ((lane & 16) ? 8 : 0), bk = (lane & 8) ? 8 : 0;
    unsigned aAh = s2u(Axh), aAl = s2u(Axl), aBh = s2u(Bh), aBl = s2u(Bl);
    float acc[2][8][4];

    auto run_gemm = [&]() {
        #pragma unroll
        for (int i = 0; i < 2; ++i)
            #pragma unroll
            for (int j = 0; j < 8; ++j)
                #pragma unroll
                for (int e = 0; e < 4; ++e) acc[i][j][e] = 0.f;
        #pragma unroll
        for (int kk = 0; kk < 8; ++kk) {
            int kb = kk*16;
            unsigned ah[2][4], al[2][4];
            #pragma unroll
            for (int mi = 0; mi < 2; ++mi) {
                unsigned off = (unsigned)(((wm + mi*16 + arow)*QKS + kb + acol)*2);
                ldsm4(ah[mi][0], ah[mi][1], ah[mi][2], ah[mi][3], aAh + off);
                ldsm4(al[mi][0], al[mi][1], al[mi][2], al[mi][3], aAl + off);
            }
            #pragma unroll
            for (int nh = 0; nh < 2; ++nh)
                MMA_HALF_STEP(acc, ah, al, aBh, aBl, QKS, kb, bk, bn, wn, nh);
        }
    };

    run_gemm();
    __syncthreads();
    #pragma unroll
    for (int mi = 0; mi < 2; ++mi)
        #pragma unroll
        for (int ni = 0; ni < 8; ++ni)
            #pragma unroll
            for (int e = 0; e < 4; ++e) {
                int r = wm + mi*16 + gid + ((e >= 2) ? 8 : 0);
                int c = wn + ni*8 + 2*tig + (e & 1);
                float v = lrelu_f(acc[mi][ni][e] + cqb[z*H + c]);
                __nv_bfloat16 hh, ll;
                split_bf(v, hh, ll);
                Axh[r*QKS + c] = hh;
                Axl[r*QKS + c] = ll;
            }
    const __nv_bfloat16* Wgh = awh + (size_t)kz*H*H;
    const __nv_bfloat16* Wgl = awl + (size_t)kz*H*H;
    #pragma unroll
    for (int i = 0; i < 8; ++i) {
        int idx = tid + i*256;
        int r = idx >> 4, seg = (idx & 15)*8;
        cpa16(Bh + r*QKS + seg, Wgh + (size_t)r*H + seg);
        cpa16(Bl + r*QKS + seg, Wgl + (size_t)r*H + seg);
    }
    cp_commit(); cp_wait0();
    __syncthreads();

    run_gemm();
    #pragma unroll
    for (int mi = 0; mi < 2; ++mi)
        #pragma unroll
        for (int ni = 0; ni < 8; ++ni)
            #pragma unroll
            for (int e = 0; e < 4; ++e) {
                int r = wm + mi*16 + gid + ((e >= 2) ? 8 : 0);
                int c = wn + ni*8 + 2*tig + (e & 1);
                wh2[((size_t)z*Bq + mt*128 + r)*H + c] = acc[mi][ni][e];
            }
}

// ======== fused h1/vh GEMM + attention (one-sided fp16: 2 MMAs per k16) ========
#define FU_GEMM_BYTES ((2*128*QKS + 256*QKS)*2)
#define FU_EPI_BYTES  ((128*132 + 128*132 + 8*128 + 128 + 128)*4)
#define FU_SMEM       (FU_EPI_BYTES > FU_GEMM_BYTES ? FU_EPI_BYTES : FU_GEMM_BYTES)
__global__ __launch_bounds__(512,1) void fused_attn(
    const __half* __restrict__ yhg, const __half* __restrict__ ylg,
    const __half* __restrict__ ckh, const float* __restrict__ ckb,
    const __half* __restrict__ vwh, const float* __restrict__ vb,
    const float* __restrict__ wh2,
    const float* __restrict__ xsh, float* __restrict__ sout)
{
    extern __shared__ __align__(16) char smc[];
    float* sm = (float*)smc;
    __half* Ah = (__half*)smc;         // [128*QKS]
    __half* Al = Ah + 128*QKS;
    __half* Bs = Al + 128*QKS;         // [256*QKS] single fp16
    int mt = blockIdx.x, z = blockIdx.y;
    int tid = threadIdx.x;

    const __half* Agh = yhg + ((size_t)z*BM_ + mt*128)*H;
    const __half* Agl = ylg + ((size_t)z*BM_ + mt*128)*H;
    size_t wkb = (size_t)z*H*H;

    #pragma unroll
    for (int i = 0; i < 4; ++i) {
        int idx = tid + i*512;
        int r = idx >> 4, seg = (idx & 15)*8;
        cpa16(Ah + r*QKS + seg, Agh + (size_t)r*H + seg);
        cpa16(Al + r*QKS + seg, Agl + (size_t)r*H + seg);
    }
    #pragma unroll
    for (int i = 0; i < 8; ++i) {
        int idx = tid + i*512;
        int n = idx >> 4, seg = (idx & 15)*8;
        const __half* src = (n < 128) ? (ckh + wkb + (size_t)n*H)
                                      : (vwh + wkb + (size_t)(n-128)*H);
        cpa16(Bs + n*QKS + seg, src + seg);
    }
    cp_commit(); cp_wait0();
    __syncthreads();

    int w = tid >> 5, lane = tid & 31, gid = lane >> 2, tig = lane & 3;
    int wm = (w & 3)*32, wn = (w >> 2)*64;
    int arow = lane & 15, acol = (lane & 16) ? 8 : 0;
    int bn = (lane & 7) + ((lane & 16) ? 8 : 0), bk = (lane & 8) ? 8 : 0;
    unsigned aAh = s2u(Ah), aAl = s2u(Al), aB = s2u(Bs);

    float acc[2][8][4];
    #pragma unroll
    for (int i = 0; i < 2; ++i)
        #pragma unroll
        for (int j = 0; j < 8; ++j)
            #pragma unroll
            for (int e = 0; e < 4; ++e) acc[i][j][e] = 0.f;

    #pragma unroll
    for (int kk = 0; kk < 8; ++kk) {
        int kb = kk*16;
        unsigned ah[2][4], al[2][4];
        #pragma unroll
        for (int mi = 0; mi < 2; ++mi) {
            unsigned off = (unsigned)(((wm + mi*16 + arow)*QKS + kb + acol)*2);
            ldsm4(ah[mi][0], ah[mi][1], ah[mi][2], ah[mi][3], aAh + off);
            ldsm4(al[mi][0], al[mi][1], al[mi][2], al[mi][3], aAl + off);
        }
        #pragma unroll
        for (int nh = 0; nh < 2; ++nh) {
            unsigned b_[4][2];
            #pragma unroll
            for (int nj = 0; nj < 2; ++nj) {
                unsigned off_ = (unsigned)(((wn + nh*32 + nj*16 + bn)*QKS + kb + bk)*2);
                ldsm4(b_[nj*2][0], b_[nj*2][1], b_[nj*2+1][0], b_[nj*2+1][1], aB + off_);
            }
            #pragma unroll
            for (int ni = 0; ni < 4; ++ni)
                #pragma unroll
                for (int mi = 0; mi < 2; ++mi)
                    mma_f16(acc[mi][nh*4+ni], al[mi], b_[ni]);
            #pragma unroll
            for (int ni = 0; ni < 4; ++ni)
                #pragma unroll
                for (int mi = 0; mi < 2; ++mi)
                    mma_f16(acc[mi][nh*4+ni], ah[mi], b_[ni]);
        }
    }
    __syncthreads();   // all smem reads done before epilogue aliasing

    float* SP  = sm;                 // [128][132]  h1 (lrelu+bias)
    float* SV  = SP + 128*132;       // [128][132]  vh (+bias)
    float* SW  = SV + 128*132;       // [8][128]    wh2 rows
    float* SSC = SW + 8*128;         // [128] scores
    float* SE  = SSC + 128;          // [128] softmax weights

    #pragma unroll
    for (int mi = 0; mi < 2; ++mi)
        #pragma unroll
        for (int ni = 0; ni < 8; ++ni)
            #pragma unroll
            for (int e = 0; e < 4; ++e) {
                int r = wm + mi*16 + gid + ((e >= 2) ? 8 : 0);
                int c = wn + ni*8 + 2*tig + (e & 1);
                float v = acc[mi][ni][e];
                if (c < 128) SP[r*132 + c] = lrelu_f(v + ckb[z*H + c]);
                else         SV[r*132 + (c-128)] = v + vb[z*H + (c-128)];
            }
    #pragma unroll
    for (int t = 0; t < 2; ++t) {
        int idx = tid + t*512;
        int bl = idx >> 7, o = idx & 127;
        SW[idx] = wh2[((size_t)z*Bq + mt*8 + bl)*H + o];
    }
    __syncthreads();

    #pragma unroll
    for (int i = 0; i < 8; ++i) {
        int rr = w*8 + i;
        const float* wrow = SW + (rr >> 4)*128;
        float p = 0.f;
        #pragma unroll
        for (int o = 0; o < 128; o += 32) p += SP[rr*132 + o + lane]*wrow[o + lane];
        #pragma unroll
        for (int d_ = 16; d_ > 0; d_ >>= 1) p += __shfl_xor_sync(0xffffffffu, p, d_);
        if (lane == 0) SSC[rr] = p;
    }
    __syncthreads();
    if (tid < 8) {
        float mx = -1e30f;
        #pragma unroll
        for (int m = 0; m < M; ++m) mx = fmaxf(mx, SSC[tid*M + m]);
        float es[M], sum = 0.f;
        #pragma unroll
        for (int m = 0; m < M; ++m) { es[m] = expf(SSC[tid*M + m] - mx); sum += es[m]; }
        float inv = 1.f/sum;
        #pragma unroll
        for (int m = 0; m < M; ++m) SE[tid*M + m] = es[m]*inv;
    }
    __syncthreads();

    int s = z/HN, hh = z%HN;
    #pragma unroll
    for (int t = 0; t < 2; ++t) {
        int idx = tid + t*512;
        int bl = idx >> 7, o = idx & 127;
        float a = 0.f;
        #pragma unroll
        for (int m = 0; m < M; ++m) {
            float v = SV[(bl*M + m)*132 + o]*SE[bl*M + m];
            a += (v >= 0.f) ? v : ALPHA*v;
        }
        int b = mt*8 + bl;
        sout[((size_t)s*Bq + b)*D + hh*H + o] =
            0.5f*(xsh[((size_t)z*Bq + b)*H + o] + a);
    }
}

// ---------------- semantic attention (smem-tiled weights, 8 targets/block) -----
#define SEM_SMEM(P) ((8*(P)*D + 64*132 + 8*(P)*132 + 32)*4)
template<int P>
__global__ __launch_bounds__(128) void semantic(
    const float* __restrict__ zin, const float* __restrict__ p1w,
    const float* __restrict__ p1b, const float* __restrict__ p2w,
    float* __restrict__ outp, int in_pstride, int in_bstride, int out_bstride)
{
    extern __shared__ __align__(16) float sem[];
    float* zs   = sem;                         // [8P][512]
    float* pwT  = sem + 8*P*D;                 // [64][132] transposed chunk
    float* sred = pwT + 64*132;                // [8P][132]
    float* ssc  = sred + 8*P*132;              // [8P]
    int b0 = blockIdx.x*8, tid = threadIdx.x;

    for (int idx = tid; idx < 8*P*(D/4); idx += 128) {
        int d4 = idx & (D/4 - 1); int rp = idx / (D/4);
        int p = rp % P, bl = rp / P;
        *(float4*)&zs[(bl*P+p)*D + d4*4] =
            *(const float4*)(zin + (size_t)(b0+bl)*in_bstride + (size_t)p*in_pstride + d4*4);
    }
    __syncthreads();

    float acc[8][P];
    #pragma unroll
    for (int bl = 0; bl < 8; ++bl)
        #pragma unroll
        for (int p = 0; p < P; ++p) acc[bl][p] = 0.f;

    for (int d0 = 0; d0 < D; d0 += 64) {
        #pragma unroll
        for (int i = 0; i < 16; ++i) {
            int idx = tid + i*128;
            int r = idx >> 4, c4 = (idx & 15)*4;
            float4 v = *(const float4*)(p1w + (size_t)r*D + d0 + c4);
            pwT[c4*132 + r]     = v.x;
            pwT[(c4+1)*132 + r] = v.y;
            pwT[(c4+2)*132 + r] = v.z;
            pwT[(c4+3)*132 + r] = v.w;
        }
        __syncthreads();
        #pragma unroll 4
        for (int dd = 0; dd < 64; dd += 4) {
            float w0 = pwT[dd*132 + tid],     w1 = pwT[(dd+1)*132 + tid];
            float w2 = pwT[(dd+2)*132 + tid], w3 = pwT[(dd+3)*132 + tid];
            #pragma unroll
            for (int bl = 0; bl < 8; ++bl)
                #pragma unroll
                for (int p = 0; p < P; ++p) {
                    float4 zv = *(const float4*)&zs[(bl*P+p)*D + d0 + dd];
                    acc[bl][p] += w0*zv.x + w1*zv.y + w2*zv.z + w3*zv.w;
                }
        }
        __syncthreads();
    }

    float bias = p1b[tid], p2 = p2w[tid];
    #pragma unroll
    for (int bl = 0; bl < 8; ++bl)
        #pragma unroll
        for (int p = 0; p < P; ++p)
            sred[(bl*P+p)*132 + tid] = tanhf(acc[bl][p] + bias)*p2;
    __syncthreads();
    if (tid < 8*P) {
        float s_ = 0.f;
        for (int o = 0; o < H; ++o) s_ += sred[tid*132 + o];
        ssc[tid] = s_;
    }
    __syncthreads();
    if (tid < 8) {
        float mx = -1e30f;
        #pragma unroll
        for (int p = 0; p < P; ++p) mx = fmaxf(mx, ssc[tid*P + p]);
        float e[P]; float esum = 0.f;
        #pragma unroll
        for (int p = 0; p < P; ++p) { e[p] = expf(ssc[tid*P + p] - mx); esum += e[p]; }
        float inv = 1.f/esum;
        #pragma unroll
        for (int p = 0; p < P; ++p) ssc[tid*P + p] = e[p]*inv;
    }
    __syncthreads();
    for (int idx = tid; idx < 8*(D/4); idx += 128) {
        int d4 = (idx & (D/4 - 1))*4; int bl = idx / (D/4);
        float4 o = {0.f, 0.f, 0.f, 0.f};
        #pragma unroll
        for (int p = 0; p < P; ++p) {
            float e = ssc[bl*P + p];
            float4 zv = *(const float4*)&zs[(bl*P+p)*D + d4];
            o.x += e*zv.x; o.y += e*zv.y; o.z += e*zv.z; o.w += e*zv.w;
        }
        *(float4*)(outp + (size_t)(b0+bl)*out_bstride + d4) = o;
    }
}

extern "C" void kernel_launch(void* const* d_in, const int* in_sizes, int n_in,
                              void* d_out, int out_size)
{
    const float* x     = (const float*)d_in[0];
    const int*   tgt   = (const int*)  d_in[1];
    const int*   neigh = (const int*)  d_in[2];
    const float* fc_w  = (const float*)d_in[3];
    const float* fc_b  = (const float*)d_in[4];
    const float* q_w   = (const float*)d_in[5];
    const float* q_b   = (const float*)d_in[6];
    const float* k_w   = (const float*)d_in[7];
    const float* k_b   = (const float*)d_in[8];
    const float* v_w   = (const float*)d_in[9];
    const float* v_b   = (const float*)d_in[10];
    const float* att_W = (const float*)d_in[11];
    const float* a1w   = (const float*)d_in[12];
    const float* a1b   = (const float*)d_in[13];
    const float* a2w   = (const float*)d_in[14];
    const float* a2b   = (const float*)d_in[15];
    const float* ip1w  = (const float*)d_in[16];
    const float* ip1b  = (const float*)d_in[17];
    const float* ip2w  = (const float*)d_in[18];
    const float* bp1w  = (const float*)d_in[19];
    const float* bp1b  = (const float*)d_in[20];
    const float* bp2w  = (const float*)d_in[21];
    float* out = (float*)d_out;

    __nv_bfloat16 *awh,*awl,*cqwh,*cqwl,*xshh,*xshl;
    __half *xhi,*xlo,*fwh,*vwh,*ckh,*yh,*yl;
    float *ckb,*cqb,*xsh,*wh2,*sout,*mp;
    cudaGetSymbolAddress((void**)&xhi,  g_xhi);
    cudaGetSymbolAddress((void**)&xlo,  g_xlo);
    cudaGetSymbolAddress((void**)&fwh,  g_fwh);
    cudaGetSymbolAddress((void**)&vwh,  g_vwh);
    cudaGetSymbolAddress((void**)&awh,  g_awh);
    cudaGetSymbolAddress((void**)&awl,  g_awl);
    cudaGetSymbolAddress((void**)&ckh,  g_ckh);
    cudaGetSymbolAddress((void**)&ckb,  g_ckb);
    cudaGetSymbolAddress((void**)&cqwh, g_cqwh);
    cudaGetSymbolAddress((void**)&cqwl, g_cqwl);
    cudaGetSymbolAddress((void**)&cqb,  g_cqb);
    cudaGetSymbolAddress((void**)&xsh,  g_xsh);
    cudaGetSymbolAddress((void**)&xshh, g_xshh);
    cudaGetSymbolAddress((void**)&xshl, g_xshl);
    cudaGetSymbolAddress((void**)&yh,   g_yh);
    cudaGetSymbolAddress((void**)&yl,   g_yl);
    cudaGetSymbolAddress((void**)&wh2,  g_wh2);
    cudaGetSymbolAddress((void**)&sout, g_sout);
    cudaGetSymbolAddress((void**)&mp,   g_mp);

    static int smem_set = 0;
    if (!smem_set) {
        cudaFuncSetAttribute(fc_f16,      cudaFuncAttributeMaxDynamicSharedMemorySize, FC2_SMEM);
        cudaFuncSetAttribute(qk_fused,    cudaFuncAttributeMaxDynamicSharedMemorySize, QK_SMEM);
        cudaFuncSetAttribute(fused_attn,  cudaFuncAttributeMaxDynamicSharedMemorySize, FU_SMEM);
        cudaFuncSetAttribute(semantic<2>, cudaFuncAttributeMaxDynamicSharedMemorySize, SEM_SMEM(2));
        cudaFuncSetAttribute(semantic<3>, cudaFuncAttributeMaxDynamicSharedMemorySize, SEM_SMEM(3));
        smem_set = 1;
    }

    // 0. operand prep
    split_all<<<(SPL_TOT + 255)/256, 256>>>(x, xhi, xlo, fc_w, fwh,
                                            v_w, vwh, att_W, awh, awl);

    // 1. fold attention-layer weights into k/q projections
    combine_gemm<<<dim3(4, PAIRS, 2), 256>>>(a1w, a1b, k_w, k_b, ckh, ckb,
                                             a2w, a2b, q_w, q_b, cqwh, cqwl, cqb);

    // 2. shared fc + leakyrelu on gathered neighbors + targets (one-sided fp16)
    fc_f16<<<dim3(R_/128, 4, S), 256, FC2_SMEM>>>(xhi, xlo, neigh, tgt, fwh,
                                                  fc_b, yh, yl, xsh, xshh, xshl);

    // 3. wh2 = (lrelu(xsh@cq^T + cqb)) @ attW^T (bf16 3-term)
    qk_fused<<<dim3(Bq/128, PAIRS), 256, QK_SMEM>>>(xshh, xshl, cqwh, cqwl, cqb,
                                                    awh, awl, wh2);

    // 4. fused h1/vh GEMM + neighbor attention + residual (one-sided fp16)
    fused_attn<<<dim3(BM_/128, PAIRS), 512, FU_SMEM>>>(yh, yl, ckh, ckb,
                                                       vwh, v_b, wh2, xsh, sout);

    // 5. semantic attention within each metapath
    semantic<2><<<Bq/8, 128, SEM_SMEM(2)>>>(sout,          ip1w,       ip1b,     ip2w,     mp,     Bq*D, D, KM*D);
    semantic<3><<<Bq/8, 128, SEM_SMEM(3)>>>(sout + 2*Bq*D, ip1w + H*D, ip1b + H, ip2w + H, mp + D, Bq*D, D, KM*D);

    // 6. semantic attention between metapaths -> final output
    semantic<2><<<Bq/8, 128, SEM_SMEM(2)>>>(mp, bp1w, bp1b, bp2w, out, D, KM*D, D);
}

// round 15
// speedup vs baseline: 1.6809x; 1.2044x over previous
#include <cuda_runtime.h>
#include <cuda_bf16.h>
#include <cuda_fp16.h>
#include <math.h>

#define NN    20000
#define IN_F  256
#define H     128
#define HN    4
#define S     5
#define KM    2
#define Bq    1024
#define M     16
#define D     512
#define ALPHA 0.2f
#define BM_   (Bq*M)      /* 16384 */
#define R_    (BM_ + Bq)  /* 17408 */
#define PAIRS (S*HN)      /* 20 */

#define KC    32          /* K halves per pipeline stage (fc) */
#define HS    40          /* fc smem row stride in halves */
#define QKS   136         /* full-K smem row stride in halves */

__constant__ int c_kofs[S] = {0,0,1,1,1};

// ---------------- scratch ----------------
__device__ __half g_xh [NN*IN_F];                   /* single fp16 */
__device__ __half g_fwh[S*4*H*IN_F];                /* single fp16 */
__device__ __half g_vwh[PAIRS*H*H];                 /* single fp16 */
__device__ __nv_bfloat16 g_awh[KM*HN*H*H];
__device__ __nv_bfloat16 g_awl[KM*HN*H*H];
__device__ __half g_ckh[PAIRS*H*H];                 /* single fp16 */
__device__ float g_ckb[PAIRS*H];
__device__ __nv_bfloat16 g_cqwh[PAIRS*H*H];
__device__ __nv_bfloat16 g_cqwl[PAIRS*H*H];
__device__ float g_cqb[PAIRS*H];
__device__ float g_xsh[PAIRS*Bq*H];
__device__ __nv_bfloat16 g_xshh[PAIRS*Bq*H];
__device__ __nv_bfloat16 g_xshl[PAIRS*Bq*H];
__device__ __half g_yh[(size_t)PAIRS*BM_*H];        /* single fp16 */
__device__ float g_wh2[PAIRS*Bq*H];
__device__ float g_sout[S*Bq*D];
__device__ float g_mp[Bq*KM*D];

// ---------------- helpers ----------------
__device__ __forceinline__ void mma_bf16(float* d, const unsigned* a, const unsigned* b) {
    asm volatile(
      "mma.sync.aligned.m16n8k16.row.col.f32.bf16.bf16.f32 "
      "{%0,%1,%2,%3}, {%4,%5,%6,%7}, {%8,%9}, {%0,%1,%2,%3};\n"
      : "+f"(d[0]), "+f"(d[1]), "+f"(d[2]), "+f"(d[3])
      : "r"(a[0]), "r"(a[1]), "r"(a[2]), "r"(a[3]), "r"(b[0]), "r"(b[1]));
}
__device__ __forceinline__ void mma_f16(float* d, const unsigned* a, const unsigned* b) {
    asm volatile(
      "mma.sync.aligned.m16n8k16.row.col.f32.f16.f16.f32 "
      "{%0,%1,%2,%3}, {%4,%5,%6,%7}, {%8,%9}, {%0,%1,%2,%3};\n"
      : "+f"(d[0]), "+f"(d[1]), "+f"(d[2]), "+f"(d[3])
      : "r"(a[0]), "r"(a[1]), "r"(a[2]), "r"(a[3]), "r"(b[0]), "r"(b[1]));
}
__device__ __forceinline__ void ldsm4(unsigned& r0, unsigned& r1, unsigned& r2, unsigned& r3,
                                      unsigned addr) {
    asm volatile("ldmatrix.sync.aligned.m8n8.x4.shared.b16 {%0,%1,%2,%3}, [%4];\n"
      : "=r"(r0), "=r"(r1), "=r"(r2), "=r"(r3) : "r"(addr));
}
__device__ __forceinline__ unsigned s2u(const void* p) {
    return (unsigned)__cvta_generic_to_shared(p);
}
__device__ __forceinline__ void split_bf(float x, __nv_bfloat16& h, __nv_bfloat16& l) {
    h = __float2bfloat16_rn(x);
    l = __float2bfloat16_rn(x - __bfloat162float(h));
}
__device__ __forceinline__ void cpa16(void* dst, const void* src) {
    unsigned d = (unsigned)__cvta_generic_to_shared(dst);
    asm volatile("cp.async.cg.shared.global [%0], [%1], 16;\n" :: "r"(d), "l"(src));
}
__device__ __forceinline__ void cp_commit() { asm volatile("cp.async.commit_group;\n"); }
__device__ __forceinline__ void cp_wait1() { asm volatile("cp.async.wait_group 1;\n"); }
__device__ __forceinline__ void cp_wait0() { asm volatile("cp.async.wait_group 0;\n"); }
__device__ __forceinline__ float lrelu_f(float v) { return v >= 0.f ? v : ALPHA*v; }

// half-N term-major step (bf16 3-term) — used by qk only
#define MMA_HALF_STEP(acc, ah, al, aBh, aBl, STRIDE, kb, bkv, bnv, wnv, nh)       \
    {                                                                             \
        unsigned bh_[4][2], bl_[4][2];                                            \
        _Pragma("unroll")                                                         \
        for (int nj = 0; nj < 2; ++nj) {                                          \
            unsigned off_ = (unsigned)((((wnv) + (nh)*32 + nj*16 + (bnv))*(STRIDE) + (kb) + (bkv))*2); \
            ldsm4(bh_[nj*2][0], bh_[nj*2][1], bh_[nj*2+1][0], bh_[nj*2+1][1], (aBh) + off_); \
            ldsm4(bl_[nj*2][0], bl_[nj*2][1], bl_[nj*2+1][0], bl_[nj*2+1][1], (aBl) + off_); \
        }                                                                         \
        _Pragma("unroll")                                                         \
        for (int ni = 0; ni < 4; ++ni)                                            \
            _Pragma("unroll")                                                     \
            for (int mi = 0; mi < 2; ++mi)                                        \
                mma_bf16(acc[mi][(nh)*4+ni], ah[mi], bl_[ni]);                    \
        _Pragma("unroll")                                                         \
        for (int ni = 0; ni < 4; ++ni)                                            \
            _Pragma("unroll")                                                     \
            for (int mi = 0; mi < 2; ++mi)                                        \
                mma_bf16(acc[mi][(nh)*4+ni], al[mi], bh_[ni]);                    \
        _Pragma("unroll")                                                         \
        for (int ni = 0; ni < 4; ++ni)                                            \
            _Pragma("unroll")                                                     \
            for (int mi = 0; mi < 2; ++mi)                                        \
                mma_bf16(acc[mi][(nh)*4+ni], ah[mi], bh_[ni]);                    \
    }

// ---------------- all operand-prep conversions in ONE launch ----------------
#define SPL_N1 (NN*IN_F)
#define SPL_N2 (S*4*H*IN_F)
#define SPL_N3 (PAIRS*H*H)
#define SPL_N4 (KM*HN*H*H)
#define SPL_TOT (SPL_N1 + SPL_N2 + SPL_N3 + SPL_N4)
__global__ void split_all(
    const float* __restrict__ x,    __half* __restrict__ xh,
    const float* __restrict__ fcw,  __half* __restrict__ fwh,
    const float* __restrict__ vw,   __half* __restrict__ vwh,
    const float* __restrict__ attw, __nv_bfloat16* __restrict__ awh, __nv_bfloat16* __restrict__ awl)
{
    int i = blockIdx.x*256 + threadIdx.x;
    if (i < SPL_N1) { xh[i] = __float2half_rn(x[i]); return; }
    if (i < SPL_N1+SPL_N2) { int j = i - SPL_N1; fwh[j] = __float2half_rn(fcw[j]); return; }
    if (i < SPL_N1+SPL_N2+SPL_N3) {
        int j = i - SPL_N1 - SPL_N2;
        vwh[j] = __float2half_rn(vw[j]);
        return;
    }
    if (i < SPL_TOT) { int j = i - SPL_N1 - SPL_N2 - SPL_N3; split_bf(attw[j], awh[j], awl[j]); }
}

// ---------------- combined weights (ck -> single fp16; cq -> bf16 split) -------
__global__ __launch_bounds__(256) void combine_gemm(
    const float* __restrict__ a1w, const float* __restrict__ a1b,
    const float* __restrict__ k_w, const float* __restrict__ k_b,
    __half* __restrict__ ckh, float* __restrict__ ckb,
    const float* __restrict__ a2w, const float* __restrict__ a2b,
    const float* __restrict__ q_w, const float* __restrict__ q_b,
    __nv_bfloat16* __restrict__ cqh, __nv_bfloat16* __restrict__ cql, float* __restrict__ cqb)
{
    int ot = blockIdx.x, z = blockIdx.y, which = blockIdx.z, tid = threadIdx.x;
    const float* aw = which ? a2w : a1w;
    const float* ab = which ? a2b : a1b;
    const float* w  = which ? q_w : k_w;
    const float* wb = which ? q_b : k_b;
    float* cb = which ? cqb : ckb;
    int kz = c_kofs[z/HN]*HN + (z % HN);
    const float* A = aw + ((size_t)kz*H + ot*32)*H;
    const float* W = w + (size_t)z*H*H;
    __shared__ float sa[32][36];
    __shared__ float sw[32][132];
    int tx = tid & 15, ty = tid >> 4;
    float acc[2][8];
    #pragma unroll
    for (int r = 0; r < 2; ++r)
        #pragma unroll
        for (int c = 0; c < 8; ++c) acc[r][c] = 0.f;
    for (int kc = 0; kc < 4; ++kc) {
        {
            int r = tid >> 3, c4 = (tid & 7)*4;
            *(float4*)&sa[r][c4] = *(const float4*)(A + r*H + kc*32 + c4);
        }
        #pragma unroll
        for (int i = 0; i < 4; ++i) {
            int idx = tid + i*256;
            int r = idx >> 5, c4 = (idx & 31)*4;
            *(float4*)&sw[r][c4] = *(const float4*)(W + (kc*32 + r)*H + c4);
        }
        __syncthreads();
        #pragma unroll 8
        for (int j = 0; j < 32; ++j) {
            float a0 = sa[ty*2][j], a1 = sa[ty*2+1][j];
            #pragma unroll
            for (int c = 0; c < 8; ++c) {
                float wv = sw[j][tx*8 + c];
                acc[0][c] += a0*wv;
                acc[1][c] += a1*wv;
            }
        }
        __syncthreads();
    }
    #pragma unroll
    for (int r = 0; r < 2; ++r)
        #pragma unroll
        for (int c = 0; c < 8; ++c) {
            size_t idx = ((size_t)z*H + ot*32 + ty*2 + r)*H + tx*8 + c;
            if (which) split_bf(acc[r][c], cqh[idx], cql[idx]);
            else       ckh[idx] = __float2half_rn(acc[r][c]);
        }
    if (tid < 32) {
        int o = ot*32 + tid;
        float bacc = ab[kz*H + o];
        const float* arow = aw + ((size_t)kz*H + o)*H;
        const float* brow = wb + z*H;
        for (int j = 0; j < H; ++j) bacc += arow[j]*brow[j];
        cb[z*H + o] = bacc;
    }
}

// ========= fc GEMM (pure fp16: 1 MMA per k16) =========
#define FC_GEMM_BYTES (4*128*HS*2)
#define FC_EPI_BYTES  (128*132*4)
#define FC_CORE_BYTES (FC_EPI_BYTES > FC_GEMM_BYTES ? FC_EPI_BYTES : FC_GEMM_BYTES)
#define FC2_SMEM      (FC_CORE_BYTES + 512)
__global__ __launch_bounds__(256,2) void fc_f16(
    const __half* __restrict__ xh,
    const int* __restrict__ neigh, const int* __restrict__ tgt,
    const __half* __restrict__ fwh,
    const float* __restrict__ fcb,
    __half* __restrict__ yh,
    float* __restrict__ xsh,
    __nv_bfloat16* __restrict__ xshh, __nv_bfloat16* __restrict__ xshl)
{
    extern __shared__ __align__(16) char smc[];
    __half* As = (__half*)smc;          // [2][128*HS]
    __half* Bs = As + 2*128*HS;         // [2][128*HS]
    int* rows = (int*)(smc + FC_CORE_BYTES);
    int mt = blockIdx.x, nt = blockIdx.y, s = blockIdx.z;
    int tid = threadIdx.x;
    if (tid < 128) {
        int r = mt*128 + tid;
        rows[tid] = (r < BM_) ? neigh[s*BM_ + r] : tgt[r - BM_];
    }
    __syncthreads();
    size_t wb = ((size_t)s*512 + nt*128)*IN_F;

    auto prefetch = [&](int kc, int buf) {
        #pragma unroll
        for (int i = 0; i < 2; ++i) {
            int idx = tid + i*256;
            int r = idx >> 2, seg = (idx & 3)*8;
            int so = buf*128*HS + r*HS + seg;
            size_t ga = (size_t)rows[r]*IN_F + kc*KC + seg;
            size_t gb = wb + (size_t)r*IN_F + kc*KC + seg;
            cpa16(As + so, xh + ga);
            cpa16(Bs + so, fwh + gb);
        }
    };

    int w = tid >> 5, lane = tid & 31;
    int wm = (w & 3)*32, wn = (w >> 2)*64;
    int arow = lane & 15, acol = (lane & 16) ? 8 : 0;
    int bn = (lane & 7) + ((lane & 16) ? 8 : 0), bk = (lane & 8) ? 8 : 0;
    unsigned aA = s2u(As), aB = s2u(Bs);

    float acc[2][8][4];
    #pragma unroll
    for (int i = 0; i < 2; ++i)
        #pragma unroll
        for (int j = 0; j < 8; ++j)
            #pragma unroll
            for (int e = 0; e < 4; ++e) acc[i][j][e] = 0.f;

    prefetch(0, 0); cp_commit();
    const int NCH = IN_F/KC;  // 8
    for (int kc = 0; kc < NCH; ++kc) {
        if (kc+1 < NCH) { prefetch(kc+1, (kc+1)&1); cp_commit(); cp_wait1(); }
        else            { cp_wait0(); }
        __syncthreads();
        unsigned bufo = (unsigned)((kc&1)*128*HS);
        #pragma unroll
        for (int kk = 0; kk < 2; ++kk) {
            int kb = kk*16;
            unsigned ah[2][4];
            #pragma unroll
            for (int mi = 0; mi < 2; ++mi) {
                unsigned off = (unsigned)((bufo + (wm + mi*16 + arow)*HS + kb + acol)*2);
                ldsm4(ah[mi][0], ah[mi][1], ah[mi][2], ah[mi][3], aA + off);
            }
            unsigned b_[8][2];
            #pragma unroll
            for (int nj = 0; nj < 4; ++nj) {
                unsigned off_ = (unsigned)((bufo + (wn + nj*16 + bn)*HS + kb + bk)*2);
                ldsm4(b_[nj*2][0], b_[nj*2][1], b_[nj*2+1][0], b_[nj*2+1][1], aB + off_);
            }
            #pragma unroll
            for (int ni = 0; ni < 8; ++ni)
                #pragma unroll
                for (int mi = 0; mi < 2; ++mi)
                    mma_f16(acc[mi][ni], ah[mi], b_[ni]);
        }
        __syncthreads();
    }

    int zp = s*HN + nt;
    int gid = lane >> 2, tig = lane & 3;
    float* Cs = (float*)smc;  // 128x132
    #pragma unroll
    for (int mi = 0; mi < 2; ++mi)
        #pragma unroll
        for (int ni = 0; ni < 8; ++ni)
            #pragma unroll
            for (int e = 0; e < 4; ++e) {
                int r = wm + mi*16 + gid + ((e >= 2) ? 8 : 0);
                int c = wn + ni*8 + 2*tig + (e & 1);
                Cs[r*132 + c] = lrelu_f(acc[mi][ni][e] + fcb[zp*H + c]);
            }
    __syncthreads();
    #pragma unroll
    for (int t = 0; t < 16; ++t) {
        int idx = tid + t*256;
        int rr = idx >> 5, c4 = (idx & 31)*4;
        float4 v = *(const float4*)(Cs + rr*132 + c4);
        int gr = mt*128 + rr;
        if (gr < BM_) {
            __half2 p0 = {__float2half_rn(v.x), __float2half_rn(v.y)};
            __half2 p1 = {__float2half_rn(v.z), __float2half_rn(v.w)};
            uint2 uh; uh.x = *(unsigned*)&p0; uh.y = *(unsigned*)&p1;
            *(uint2*)(yh + ((size_t)zp*BM_ + gr)*H + c4) = uh;
        } else {
            size_t base = ((size_t)zp*Bq + (gr - BM_))*H + c4;
            *(float4*)(xsh + base) = v;
            __nv_bfloat16 h0,h1,h2_,h3,l0,l1,l2,l3;
            split_bf(v.x,h0,l0); split_bf(v.y,h1,l1);
            split_bf(v.z,h2_,l2); split_bf(v.w,h3,l3);
            __nv_bfloat162 ph0 = {h0,h1}, ph1 = {h2_,h3};
            __nv_bfloat162 pl0 = {l0,l1}, pl1 = {l2,l3};
            uint2 uh, ul;
            uh.x = *(unsigned*)&ph0; uh.y = *(unsigned*)&ph1;
            ul.x = *(unsigned*)&pl0; ul.y = *(unsigned*)&pl1;
            *(uint2*)(xshh + base) = uh;
            *(uint2*)(xshl + base) = ul;
        }
    }
}

// ================= qk_fused (bf16 3-term, unchanged) =================
#define QK_SMEM (4*128*QKS*2)
__global__ __launch_bounds__(256,1) void qk_fused(
    const __nv_bfloat16* __restrict__ xshh, const __nv_bfloat16* __restrict__ xshl,
    const __nv_bfloat16* __restrict__ cqh, const __nv_bfloat16* __restrict__ cql,
    const float* __restrict__ cqb,
    const __nv_bfloat16* __restrict__ awh, const __nv_bfloat16* __restrict__ awl,
    float* __restrict__ wh2)
{
    extern __shared__ __align__(16) char smc[];
    __nv_bfloat16* Axh = (__nv_bfloat16*)smc;
    __nv_bfloat16* Axl = Axh + 128*QKS;
    __nv_bfloat16* Bh  = Axl + 128*QKS;
    __nv_bfloat16* Bl  = Bh + 128*QKS;
    int mt = blockIdx.x, z = blockIdx.y;
    int tid = threadIdx.x;
    int kz = c_kofs[z/HN]*HN + (z % HN);

    const __nv_bfloat16* Agh = xshh + ((size_t)z*Bq + mt*128)*H;
    const __nv_bfloat16* Agl = xshl + ((size_t)z*Bq + mt*128)*H;
    const __nv_bfloat16* Bgh = cqh + (size_t)z*H*H;
    const __nv_bfloat16* Bgl = cql + (size_t)z*H*H;

    #pragma unroll
    for (int i = 0; i < 8; ++i) {
        int idx = tid + i*256;
        int r = idx >> 4, seg = (idx & 15)*8;
        cpa16(Axh + r*QKS + seg, Agh + (size_t)r*H + seg);
        cpa16(Axl + r*QKS + seg, Agl + (size_t)r*H + seg);
        cpa16(Bh + r*QKS + seg, Bgh + (size_t)r*H + seg);
        cpa16(Bl + r*QKS + seg, Bgl + (size_t)r*H + seg);
    }
    cp_commit(); cp_wait0();
    __syncthreads();

    int w = tid >> 5, lane = tid & 31, gid = lane >> 2, tig = lane & 3;
    int wm = (w & 3)*32, wn = (w >> 2)*64;
    int arow = lane & 15, acol = (lane & 16) ? 8 : 0;
    int bn = (lane & 7) + ((lane & 16) ? 8 : 0), bk = (lane & 8) ? 8 : 0;
    unsigned aAh = s2u(Axh), aAl = s2u(Axl), aBh = s2u(Bh), aBl = s2u(Bl);
    float acc[2][8][4];

    auto run_gemm = [&]() {
        #pragma unroll
        for (int i = 0; i < 2; ++i)
            #pragma unroll
            for (int j = 0; j < 8; ++j)
                #pragma unroll
                for (int e = 0; e < 4; ++e) acc[i][j][e] = 0.f;
        #pragma unroll
        for (int kk = 0; kk < 8; ++kk) {
            int kb = kk*16;
            unsigned ah[2][4], al[2][4];
            #pragma unroll
            for (int mi = 0; mi < 2; ++mi) {
                unsigned off = (unsigned)(((wm + mi*16 + arow)*QKS + kb + acol)*2);
                ldsm4(ah[mi][0], ah[mi][1], ah[mi][2], ah[mi][3], aAh + off);
                ldsm4(al[mi][0], al[mi][1], al[mi][2], al[mi][3], aAl + off);
            }
            #pragma unroll
            for (int nh = 0; nh < 2; ++nh)
                MMA_HALF_STEP(acc, ah, al, aBh, aBl, QKS, kb, bk, bn, wn, nh);
        }
    };

    run_gemm();
    __syncthreads();
    #pragma unroll
    for (int mi = 0; mi < 2; ++mi)
        #pragma unroll
        for (int ni = 0; ni < 8; ++ni)
            #pragma unroll
            for (int e = 0; e < 4; ++e) {
                int r = wm + mi*16 + gid + ((e >= 2) ? 8 : 0);
                int c = wn + ni*8 + 2*tig + (e & 1);
                float v = lrelu_f(acc[mi][ni][e] + cqb[z*H + c]);
                __nv_bfloat16 hh, ll;
                split_bf(v, hh, ll);
                Axh[r*QKS + c] = hh;
                Axl[r*QKS + c] = ll;
            }
    const __nv_bfloat16* Wgh = awh + (size_t)kz*H*H;
    const __nv_bfloat16* Wgl = awl + (size_t)kz*H*H;
    #pragma unroll
    for (int i = 0; i < 8; ++i) {
        int idx = tid + i*256;
        int r = idx >> 4, seg = (idx & 15)*8;
        cpa16(Bh + r*QKS + seg, Wgh + (size_t)r*H + seg);
        cpa16(Bl + r*QKS + seg, Wgl + (size_t)r*H + seg);
    }
    cp_commit(); cp_wait0();
    __syncthreads();

    run_gemm();
    #pragma unroll
    for (int mi = 0; mi < 2; ++mi)
        #pragma unroll
        for (int ni = 0; ni < 8; ++ni)
            #pragma unroll
            for (int e = 0; e < 4; ++e) {
                int r = wm + mi*16 + gid + ((e >= 2) ? 8 : 0);
                int c = wn + ni*8 + 2*tig + (e & 1);
                wh2[((size_t)z*Bq + mt*128 + r)*H + c] = acc[mi][ni][e];
            }
}

// ======== fused h1/vh GEMM + attention (pure fp16: 1 MMA per k16) ========
#define FU_GEMM_BYTES ((128*QKS + 256*QKS)*2)
#define FU_EPI_BYTES  ((128*132 + 128*132 + 8*128 + 128 + 128)*4)
#define FU_SMEM       (FU_EPI_BYTES > FU_GEMM_BYTES ? FU_EPI_BYTES : FU_GEMM_BYTES)
__global__ __launch_bounds__(512,1) void fused_attn(
    const __half* __restrict__ yhg,
    const __half* __restrict__ ckh, const float* __restrict__ ckb,
    const __half* __restrict__ vwh, const float* __restrict__ vb,
    const float* __restrict__ wh2,
    const float* __restrict__ xsh, float* __restrict__ sout)
{
    extern __shared__ __align__(16) char smc[];
    float* sm = (float*)smc;
    __half* As = (__half*)smc;         // [128*QKS]
    __half* Bs = As + 128*QKS;         // [256*QKS]
    int mt = blockIdx.x, z = blockIdx.y;
    int tid = threadIdx.x;

    const __half* Ag = yhg + ((size_t)z*BM_ + mt*128)*H;
    size_t wkb = (size_t)z*H*H;

    #pragma unroll
    for (int i = 0; i < 4; ++i) {
        int idx = tid + i*512;
        int r = idx >> 4, seg = (idx & 15)*8;
        cpa16(As + r*QKS + seg, Ag + (size_t)r*H + seg);
    }
    #pragma unroll
    for (int i = 0; i < 8; ++i) {
        int idx = tid + i*512;
        int n = idx >> 4, seg = (idx & 15)*8;
        const __half* src = (n < 128) ? (ckh + wkb + (size_t)n*H)
                                      : (vwh + wkb + (size_t)(n-128)*H);
        cpa16(Bs + n*QKS + seg, src + seg);
    }
    cp_commit(); cp_wait0();
    __syncthreads();

    int w = tid >> 5, lane = tid & 31, gid = lane >> 2, tig = lane & 3;
    int wm = (w & 3)*32, wn = (w >> 2)*64;
    int arow = lane & 15, acol = (lane & 16) ? 8 : 0;
    int bn = (lane & 7) + ((lane & 16) ? 8 : 0), bk = (lane & 8) ? 8 : 0;
    unsigned aA = s2u(As), aB = s2u(Bs);

    float acc[2][8][4];
    #pragma unroll
    for (int i = 0; i < 2; ++i)
        #pragma unroll
        for (int j = 0; j < 8; ++j)
            #pragma unroll
            for (int e = 0; e < 4; ++e) acc[i][j][e] = 0.f;

    #pragma unroll
    for (int kk = 0; kk < 8; ++kk) {
        int kb = kk*16;
        unsigned ah[2][4];
        #pragma unroll
        for (int mi = 0; mi < 2; ++mi) {
            unsigned off = (unsigned)(((wm + mi*16 + arow)*QKS + kb + acol)*2);
            ldsm4(ah[mi][0], ah[mi][1], ah[mi][2], ah[mi][3], aA + off);
        }
        unsigned b_[8][2];
        #pragma unroll
        for (int nj = 0; nj < 4; ++nj) {
            unsigned off_ = (unsigned)(((wn + nj*16 + bn)*QKS + kb + bk)*2);
            ldsm4(b_[nj*2][0], b_[nj*2][1], b_[nj*2+1][0], b_[nj*2+1][1], aB + off_);
        }
        #pragma unroll
        for (int ni = 0; ni < 8; ++ni)
            #pragma unroll
            for (int mi = 0; mi < 2; ++mi)
                mma_f16(acc[mi][ni], ah[mi], b_[ni]);
    }
    __syncthreads();   // all smem reads done before epilogue aliasing

    float* SP  = sm;                 // [128][132]  h1 (lrelu+bias)
    float* SV  = SP + 128*132;       // [128][132]  vh (+bias)
    float* SW  = SV + 128*132;       // [8][128]    wh2 rows
    float* SSC = SW + 8*128;         // [128] scores
    float* SE  = SSC + 128;          // [128] softmax weights

    #pragma unroll
    for (int mi = 0; mi < 2; ++mi)
        #pragma unroll
        for (int ni = 0; ni < 8; ++ni)
            #pragma unroll
            for (int e = 0; e < 4; ++e) {
                int r = wm + mi*16 + gid + ((e >= 2) ? 8 : 0);
                int c = wn + ni*8 + 2*tig + (e & 1);
                float v = acc[mi][ni][e];
                if (c < 128) SP[r*132 + c] = lrelu_f(v + ckb[z*H + c]);
                else         SV[r*132 + (c-128)] = v + vb[z*H + (c-128)];
            }
    #pragma unroll
    for (int t = 0; t < 2; ++t) {
        int idx = tid + t*512;
        int bl = idx >> 7, o = idx & 127;
        SW[idx] = wh2[((size_t)z*Bq + mt*8 + bl)*H + o];
    }
    __syncthreads();

    #pragma unroll
    for (int i = 0; i < 8; ++i) {
        int rr = w*8 + i;
        const float* wrow = SW + (rr >> 4)*128;
        float p = 0.f;
        #pragma unroll
        for (int o = 0; o < 128; o += 32) p += SP[rr*132 + o + lane]*wrow[o + lane];
        #pragma unroll
        for (int d_ = 16; d_ > 0; d_ >>= 1) p += __shfl_xor_sync(0xffffffffu, p, d_);
        if (lane == 0) SSC[rr] = p;
    }
    __syncthreads();
    if (tid < 8) {
        float mx = -1e30f;
        #pragma unroll
        for (int m = 0; m < M; ++m) mx = fmaxf(mx, SSC[tid*M + m]);
        float es[M], sum = 0.f;
        #pragma unroll
        for (int m = 0; m < M; ++m) { es[m] = expf(SSC[tid*M + m] - mx); sum += es[m]; }
        float inv = 1.f/sum;
        #pragma unroll
        for (int m = 0; m < M; ++m) SE[tid*M + m] = es[m]*inv;
    }
    __syncthreads();

    int s = z/HN, hh = z%HN;
    #pragma unroll
    for (int t = 0; t < 2; ++t) {
        int idx = tid + t*512;
        int bl = idx >> 7, o = idx & 127;
        float a = 0.f;
        #pragma unroll
        for (int m = 0; m < M; ++m) {
            float v = SV[(bl*M + m)*132 + o]*SE[bl*M + m];
            a += (v >= 0.f) ? v : ALPHA*v;
        }
        int b = mt*8 + bl;
        sout[((size_t)s*Bq + b)*D + hh*H + o] =
            0.5f*(xsh[((size_t)z*Bq + b)*H + o] + a);
    }
}

// ---------------- semantic attention (smem-tiled weights, 8 targets/block) -----
#define SEM_SMEM(P) ((8*(P)*D + 64*132 + 8*(P)*132 + 32)*4)
template<int P>
__global__ __launch_bounds__(128) void semantic(
    const float* __restrict__ zin, const float* __restrict__ p1w,
    const float* __restrict__ p1b, const float* __restrict__ p2w,
    float* __restrict__ outp, int in_pstride, int in_bstride, int out_bstride)
{
    extern __shared__ __align__(16) float sem[];
    float* zs   = sem;                         // [8P][512]
    float* pwT  = sem + 8*P*D;                 // [64][132] transposed chunk
    float* sred = pwT + 64*132;                // [8P][132]
    float* ssc  = sred + 8*P*132;              // [8P]
    int b0 = blockIdx.x*8, tid = threadIdx.x;

    for (int idx = tid; idx < 8*P*(D/4); idx += 128) {
        int d4 = idx & (D/4 - 1); int rp = idx / (D/4);
        int p = rp % P, bl = rp / P;
        *(float4*)&zs[(bl*P+p)*D + d4*4] =
            *(const float4*)(zin + (size_t)(b0+bl)*in_bstride + (size_t)p*in_pstride + d4*4);
    }
    __syncthreads();

    float acc[8][P];
    #pragma unroll
    for (int bl = 0; bl < 8; ++bl)
        #pragma unroll
        for (int p = 0; p < P; ++p) acc[bl][p] = 0.f;

    for (int d0 = 0; d0 < D; d0 += 64) {
        #pragma unroll
        for (int i = 0; i < 16; ++i) {
            int idx = tid + i*128;
            int r = idx >> 4, c4 = (idx & 15)*4;
            float4 v = *(const float4*)(p1w + (size_t)r*D + d0 + c4);
            pwT[c4*132 + r]     = v.x;
            pwT[(c4+1)*132 + r] = v.y;
            pwT[(c4+2)*132 + r] = v.z;
            pwT[(c4+3)*132 + r] = v.w;
        }
        __syncthreads();
        #pragma unroll 4
        for (int dd = 0; dd < 64; dd += 4) {
            float w0 = pwT[dd*132 + tid],     w1 = pwT[(dd+1)*132 + tid];
            float w2 = pwT[(dd+2)*132 + tid], w3 = pwT[(dd+3)*132 + tid];
            #pragma unroll
            for (int bl = 0; bl < 8; ++bl)
                #pragma unroll
                for (int p = 0; p < P; ++p) {
                    float4 zv = *(const float4*)&zs[(bl*P+p)*D + d0 + dd];
                    acc[bl][p] += w0*zv.x + w1*zv.y + w2*zv.z + w3*zv.w;
                }
        }
        __syncthreads();
    }

    float bias = p1b[tid], p2 = p2w[tid];
    #pragma unroll
    for (int bl = 0; bl < 8; ++bl)
        #pragma unroll
        for (int p = 0; p < P; ++p)
            sred[(bl*P+p)*132 + tid] = tanhf(acc[bl][p] + bias)*p2;
    __syncthreads();
    if (tid < 8*P) {
        float s_ = 0.f;
        for (int o = 0; o < H; ++o) s_ += sred[tid*132 + o];
        ssc[tid] = s_;
    }
    __syncthreads();
    if (tid < 8) {
        float mx = -1e30f;
        #pragma unroll
        for (int p = 0; p < P; ++p) mx = fmaxf(mx, ssc[tid*P + p]);
        float e[P]; float esum = 0.f;
        #pragma unroll
        for (int p = 0; p < P; ++p) { e[p] = expf(ssc[tid*P + p] - mx); esum += e[p]; }
        float inv = 1.f/esum;
        #pragma unroll
        for (int p = 0; p < P; ++p) ssc[tid*P + p] = e[p]*inv;
    }
    __syncthreads();
    for (int idx = tid; idx < 8*(D/4); idx += 128) {
        int d4 = (idx & (D/4 - 1))*4; int bl = idx / (D/4);
        float4 o = {0.f, 0.f, 0.f, 0.f};
        #pragma unroll
        for (int p = 0; p < P; ++p) {
            float e = ssc[bl*P + p];
            float4 zv = *(const float4*)&zs[(bl*P+p)*D + d4];
            o.x += e*zv.x; o.y += e*zv.y; o.z += e*zv.z; o.w += e*zv.w;
        }
        *(float4*)(outp + (size_t)(b0+bl)*out_bstride + d4) = o;
    }
}

extern "C" void kernel_launch(void* const* d_in, const int* in_sizes, int n_in,
                              void* d_out, int out_size)
{
    const float* x     = (const float*)d_in[0];
    const int*   tgt   = (const int*)  d_in[1];
    const int*   neigh = (const int*)  d_in[2];
    const float* fc_w  = (const float*)d_in[3];
    const float* fc_b  = (const float*)d_in[4];
    const float* q_w   = (const float*)d_in[5];
    const float* q_b   = (const float*)d_in[6];
    const float* k_w   = (const float*)d_in[7];
    const float* k_b   = (const float*)d_in[8];
    const float* v_w   = (const float*)d_in[9];
    const float* v_b   = (const float*)d_in[10];
    const float* att_W = (const float*)d_in[11];
    const float* a1w   = (const float*)d_in[12];
    const float* a1b   = (const float*)d_in[13];
    const float* a2w   = (const float*)d_in[14];
    const float* a2b   = (const float*)d_in[15];
    const float* ip1w  = (const float*)d_in[16];
    const float* ip1b  = (const float*)d_in[17];
    const float* ip2w  = (const float*)d_in[18];
    const float* bp1w  = (const float*)d_in[19];
    const float* bp1b  = (const float*)d_in[20];
    const float* bp2w  = (const float*)d_in[21];
    float* out = (float*)d_out;

    __nv_bfloat16 *awh,*awl,*cqwh,*cqwl,*xshh,*xshl;
    __half *xh,*fwh,*vwh,*ckh,*yh;
    float *ckb,*cqb,*xsh,*wh2,*sout,*mp;
    cudaGetSymbolAddress((void**)&xh,   g_xh);
    cudaGetSymbolAddress((void**)&fwh,  g_fwh);
    cudaGetSymbolAddress((void**)&vwh,  g_vwh);
    cudaGetSymbolAddress((void**)&awh,  g_awh);
    cudaGetSymbolAddress((void**)&awl,  g_awl);
    cudaGetSymbolAddress((void**)&ckh,  g_ckh);
    cudaGetSymbolAddress((void**)&ckb,  g_ckb);
    cudaGetSymbolAddress((void**)&cqwh, g_cqwh);
    cudaGetSymbolAddress((void**)&cqwl, g_cqwl);
    cudaGetSymbolAddress((void**)&cqb,  g_cqb);
    cudaGetSymbolAddress((void**)&xsh,  g_xsh);
    cudaGetSymbolAddress((void**)&xshh, g_xshh);
    cudaGetSymbolAddress((void**)&xshl, g_xshl);
    cudaGetSymbolAddress((void**)&yh,   g_yh);
    cudaGetSymbolAddress((void**)&wh2,  g_wh2);
    cudaGetSymbolAddress((void**)&sout, g_sout);
    cudaGetSymbolAddress((void**)&mp,   g_mp);

    static int smem_set = 0;
    if (!smem_set) {
        cudaFuncSetAttribute(fc_f16,      cudaFuncAttributeMaxDynamicSharedMemorySize, FC2_SMEM);
        cudaFuncSetAttribute(qk_fused,    cudaFuncAttributeMaxDynamicSharedMemorySize, QK_SMEM);
        cudaFuncSetAttribute(fused_attn,  cudaFuncAttributeMaxDynamicSharedMemorySize, FU_SMEM);
        cudaFuncSetAttribute(semantic<2>, cudaFuncAttributeMaxDynamicSharedMemorySize, SEM_SMEM(2));
        cudaFuncSetAttribute(semantic<3>, cudaFuncAttributeMaxDynamicSharedMemorySize, SEM_SMEM(3));
        smem_set = 1;
    }

    // 0. operand prep
    split_all<<<(SPL_TOT + 255)/256, 256>>>(x, xh, fc_w, fwh,
                                            v_w, vwh, att_W, awh, awl);

    // 1. fold attention-layer weights into k/q projections
    combine_gemm<<<dim3(4, PAIRS, 2), 256>>>(a1w, a1b, k_w, k_b, ckh, ckb,
                                             a2w, a2b, q_w, q_b, cqwh, cqwl, cqb);

    // 2. shared fc + leakyrelu on gathered neighbors + targets (pure fp16)
    fc_f16<<<dim3(R_/128, 4, S), 256, FC2_SMEM>>>(xh, neigh, tgt, fwh,
                                                  fc_b, yh, xsh, xshh, xshl);

    // 3. wh2 = (lrelu(xsh@cq^T + cqb)) @ attW^T (bf16 3-term)
    qk_fused<<<dim3(Bq/128, PAIRS), 256, QK_SMEM>>>(xshh, xshl, cqwh, cqwl, cqb,
                                                    awh, awl, wh2);

    // 4. fused h1/vh GEMM + neighbor attention + residual (pure fp16)
    fused_attn<<<dim3(BM_/128, PAIRS), 512, FU_SMEM>>>(yh, ckh, ckb,
                                                       vwh, v_b, wh2, xsh, sout);

    // 5. semantic attention within each metapath
    semantic<2><<<Bq/8, 128, SEM_SMEM(2)>>>(sout,          ip1w,       ip1b,     ip2w,     mp,     Bq*D, D, KM*D);
    semantic<3><<<Bq/8, 128, SEM_SMEM(3)>>>(sout + 2*Bq*D, ip1w + H*D, ip1b + H, ip2w + H, mp + D, Bq*D, D, KM*D);

    // 6. semantic attention between metapaths -> final output
    semantic<2><<<Bq/8, 128, SEM_SMEM(2)>>>(mp, bp1w, bp1b, bp2w, out, D, KM*D, D);
}

// round 17
// speedup vs baseline: 1.8907x; 1.1248x over previous
#include <cuda_runtime.h>
#include <cuda_bf16.h>
#include <cuda_fp16.h>
#include <math.h>

#define NN    20000
#define IN_F  256
#define H     128
#define HN    4
#define S     5
#define KM    2
#define Bq    1024
#define M     16
#define D     512
#define ALPHA 0.2f
#define BM_   (Bq*M)      /* 16384 */
#define R_    (BM_ + Bq)  /* 17408 */
#define PAIRS (S*HN)      /* 20 */

#define KC    32          /* K halves per pipeline stage (fc) */
#define HS    40          /* fc smem row stride in halves */
#define QKS   136         /* full-K smem row stride in halves */

__constant__ int c_kofs[S] = {0,0,1,1,1};

// ---------------- scratch ----------------
__device__ __half g_xh [NN*IN_F];                   /* single fp16 */
__device__ __half g_fwh[S*4*H*IN_F];                /* single fp16 */
__device__ __half g_vwh[PAIRS*H*H];                 /* single fp16 */
__device__ __half g_awf[KM*HN*H*H];                 /* single fp16 */
__device__ __half g_ckh[PAIRS*H*H];                 /* single fp16 */
__device__ float g_ckb[PAIRS*H];
__device__ __half g_cqh[PAIRS*H*H];                 /* single fp16 */
__device__ float g_cqb[PAIRS*H];
__device__ float g_xsh[PAIRS*Bq*H];
__device__ __half g_xshf[PAIRS*Bq*H];               /* single fp16 */
__device__ __half g_yh[(size_t)PAIRS*BM_*H];        /* single fp16 */
__device__ float g_wh2[PAIRS*Bq*H];
__device__ float g_sout[S*Bq*D];
__device__ float g_mp[Bq*KM*D];

// ---------------- helpers ----------------
__device__ __forceinline__ void mma_f16(float* d, const unsigned* a, const unsigned* b) {
    asm volatile(
      "mma.sync.aligned.m16n8k16.row.col.f32.f16.f16.f32 "
      "{%0,%1,%2,%3}, {%4,%5,%6,%7}, {%8,%9}, {%0,%1,%2,%3};\n"
      : "+f"(d[0]), "+f"(d[1]), "+f"(d[2]), "+f"(d[3])
      : "r"(a[0]), "r"(a[1]), "r"(a[2]), "r"(a[3]), "r"(b[0]), "r"(b[1]));
}
__device__ __forceinline__ void ldsm4(unsigned& r0, unsigned& r1, unsigned& r2, unsigned& r3,
                                      unsigned addr) {
    asm volatile("ldmatrix.sync.aligned.m8n8.x4.shared.b16 {%0,%1,%2,%3}, [%4];\n"
      : "=r"(r0), "=r"(r1), "=r"(r2), "=r"(r3) : "r"(addr));
}
__device__ __forceinline__ unsigned s2u(const void* p) {
    return (unsigned)__cvta_generic_to_shared(p);
}
__device__ __forceinline__ void cpa16(void* dst, const void* src) {
    unsigned d = (unsigned)__cvta_generic_to_shared(dst);
    asm volatile("cp.async.cg.shared.global [%0], [%1], 16;\n" :: "r"(d), "l"(src));
}
__device__ __forceinline__ void cp_commit() { asm volatile("cp.async.commit_group;\n"); }
__device__ __forceinline__ void cp_wait1() { asm volatile("cp.async.wait_group 1;\n"); }
__device__ __forceinline__ void cp_wait0() { asm volatile("cp.async.wait_group 0;\n"); }
__device__ __forceinline__ float lrelu_f(float v) { return v >= 0.f ? v : ALPHA*v; }

// ---------------- all operand-prep conversions in ONE launch ----------------
#define SPL_N1 (NN*IN_F)
#define SPL_N2 (S*4*H*IN_F)
#define SPL_N3 (PAIRS*H*H)
#define SPL_N4 (KM*HN*H*H)
#define SPL_TOT (SPL_N1 + SPL_N2 + SPL_N3 + SPL_N4)
__global__ void split_all(
    const float* __restrict__ x,    __half* __restrict__ xh,
    const float* __restrict__ fcw,  __half* __restrict__ fwh,
    const float* __restrict__ vw,   __half* __restrict__ vwh,
    const float* __restrict__ attw, __half* __restrict__ awf)
{
    int i = blockIdx.x*256 + threadIdx.x;
    if (i < SPL_N1) { xh[i] = __float2half_rn(x[i]); return; }
    if (i < SPL_N1+SPL_N2) { int j = i - SPL_N1; fwh[j] = __float2half_rn(fcw[j]); return; }
    if (i < SPL_N1+SPL_N2+SPL_N3) {
        int j = i - SPL_N1 - SPL_N2;
        vwh[j] = __float2half_rn(vw[j]);
        return;
    }
    if (i < SPL_TOT) { int j = i - SPL_N1 - SPL_N2 - SPL_N3; awf[j] = __float2half_rn(attw[j]); }
}

// ---------------- combined weights (ck, cq -> single fp16) -------
__global__ __launch_bounds__(256) void combine_gemm(
    const float* __restrict__ a1w, const float* __restrict__ a1b,
    const float* __restrict__ k_w, const float* __restrict__ k_b,
    __half* __restrict__ ckh, float* __restrict__ ckb,
    const float* __restrict__ a2w, const float* __restrict__ a2b,
    const float* __restrict__ q_w, const float* __restrict__ q_b,
    __half* __restrict__ cqh, float* __restrict__ cqb)
{
    int ot = blockIdx.x, z = blockIdx.y, which = blockIdx.z, tid = threadIdx.x;
    const float* aw = which ? a2w : a1w;
    const float* ab = which ? a2b : a1b;
    const float* w  = which ? q_w : k_w;
    const float* wb = which ? q_b : k_b;
    __half* ch = which ? cqh : ckh;
    float* cb = which ? cqb : ckb;
    int kz = c_kofs[z/HN]*HN + (z % HN);
    const float* A = aw + ((size_t)kz*H + ot*32)*H;
    const float* W = w + (size_t)z*H*H;
    __shared__ float sa[32][36];
    __shared__ float sw[32][132];
    int tx = tid & 15, ty = tid >> 4;
    float acc[2][8];
    #pragma unroll
    for (int r = 0; r < 2; ++r)
        #pragma unroll
        for (int c = 0; c < 8; ++c) acc[r][c] = 0.f;
    for (int kc = 0; kc < 4; ++kc) {
        {
            int r = tid >> 3, c4 = (tid & 7)*4;
            *(float4*)&sa[r][c4] = *(const float4*)(A + r*H + kc*32 + c4);
        }
        #pragma unroll
        for (int i = 0; i < 4; ++i) {
            int idx = tid + i*256;
            int r = idx >> 5, c4 = (idx & 31)*4;
            *(float4*)&sw[r][c4] = *(const float4*)(W + (kc*32 + r)*H + c4);
        }
        __syncthreads();
        #pragma unroll 8
        for (int j = 0; j < 32; ++j) {
            float a0 = sa[ty*2][j], a1 = sa[ty*2+1][j];
            #pragma unroll
            for (int c = 0; c < 8; ++c) {
                float wv = sw[j][tx*8 + c];
                acc[0][c] += a0*wv;
                acc[1][c] += a1*wv;
            }
        }
        __syncthreads();
    }
    #pragma unroll
    for (int r = 0; r < 2; ++r)
        #pragma unroll
        for (int c = 0; c < 8; ++c) {
            size_t idx = ((size_t)z*H + ot*32 + ty*2 + r)*H + tx*8 + c;
            ch[idx] = __float2half_rn(acc[r][c]);
        }
    if (tid < 32) {
        int o = ot*32 + tid;
        float bacc = ab[kz*H + o];
        const float* arow = aw + ((size_t)kz*H + o)*H;
        const float* brow = wb + z*H;
        for (int j = 0; j < H; ++j) bacc += arow[j]*brow[j];
        cb[z*H + o] = bacc;
    }
}

// ========= fc GEMM (pure fp16: 1 MMA per k16) =========
#define FC_GEMM_BYTES (4*128*HS*2)
#define FC_EPI_BYTES  (128*132*4)
#define FC_CORE_BYTES (FC_EPI_BYTES > FC_GEMM_BYTES ? FC_EPI_BYTES : FC_GEMM_BYTES)
#define FC2_SMEM      (FC_CORE_BYTES + 512)
__global__ __launch_bounds__(256,2) void fc_f16(
    const __half* __restrict__ xh,
    const int* __restrict__ neigh, const int* __restrict__ tgt,
    const __half* __restrict__ fwh,
    const float* __restrict__ fcb,
    __half* __restrict__ yh,
    float* __restrict__ xsh, __half* __restrict__ xshf)
{
    extern __shared__ __align__(16) char smc[];
    __half* As = (__half*)smc;          // [2][128*HS]
    __half* Bs = As + 2*128*HS;         // [2][128*HS]
    int* rows = (int*)(smc + FC_CORE_BYTES);
    int mt = blockIdx.x, nt = blockIdx.y, s = blockIdx.z;
    int tid = threadIdx.x;
    if (tid < 128) {
        int r = mt*128 + tid;
        rows[tid] = (r < BM_) ? neigh[s*BM_ + r] : tgt[r - BM_];
    }
    __syncthreads();
    size_t wb = ((size_t)s*512 + nt*128)*IN_F;

    auto prefetch = [&](int kc, int buf) {
        #pragma unroll
        for (int i = 0; i < 2; ++i) {
            int idx = tid + i*256;
            int r = idx >> 2, seg = (idx & 3)*8;
            int so = buf*128*HS + r*HS + seg;
            size_t ga = (size_t)rows[r]*IN_F + kc*KC + seg;
            size_t gb = wb + (size_t)r*IN_F + kc*KC + seg;
            cpa16(As + so, xh + ga);
            cpa16(Bs + so, fwh + gb);
        }
    };

    int w = tid >> 5, lane = tid & 31;
    int wm = (w & 3)*32, wn = (w >> 2)*64;
    int arow = lane & 15, acol = (lane & 16) ? 8 : 0;
    int bn = (lane & 7) + ((lane & 16) ? 8 : 0), bk = (lane & 8) ? 8 : 0;
    unsigned aA = s2u(As), aB = s2u(Bs);

    float acc[2][8][4];
    #pragma unroll
    for (int i = 0; i < 2; ++i)
        #pragma unroll
        for (int j = 0; j < 8; ++j)
            #pragma unroll
            for (int e = 0; e < 4; ++e) acc[i][j][e] = 0.f;

    prefetch(0, 0); cp_commit();
    const int NCH = IN_F/KC;  // 8
    for (int kc = 0; kc < NCH; ++kc) {
        if (kc+1 < NCH) { prefetch(kc+1, (kc+1)&1); cp_commit(); cp_wait1(); }
        else            { cp_wait0(); }
        __syncthreads();
        unsigned bufo = (unsigned)((kc&1)*128*HS);
        #pragma unroll
        for (int kk = 0; kk < 2; ++kk) {
            int kb = kk*16;
            unsigned ah[2][4];
            #pragma unroll
            for (int mi = 0; mi < 2; ++mi) {
                unsigned off = (unsigned)((bufo + (wm + mi*16 + arow)*HS + kb + acol)*2);
                ldsm4(ah[mi][0], ah[mi][1], ah[mi][2], ah[mi][3], aA + off);
            }
            unsigned b_[8][2];
            #pragma unroll
            for (int nj = 0; nj < 4; ++nj) {
                unsigned off_ = (unsigned)((bufo + (wn + nj*16 + bn)*HS + kb + bk)*2);
                ldsm4(b_[nj*2][0], b_[nj*2][1], b_[nj*2+1][0], b_[nj*2+1][1], aB + off_);
            }
            #pragma unroll
            for (int ni = 0; ni < 8; ++ni)
                #pragma unroll
                for (int mi = 0; mi < 2; ++mi)
                    mma_f16(acc[mi][ni], ah[mi], b_[ni]);
        }
        __syncthreads();
    }

    int zp = s*HN + nt;
    int gid = lane >> 2, tig = lane & 3;
    float* Cs = (float*)smc;  // 128x132
    #pragma unroll
    for (int mi = 0; mi < 2; ++mi)
        #pragma unroll
        for (int ni = 0; ni < 8; ++ni)
            #pragma unroll
            for (int e = 0; e < 4; ++e) {
                int r = wm + mi*16 + gid + ((e >= 2) ? 8 : 0);
                int c = wn + ni*8 + 2*tig + (e & 1);
                Cs[r*132 + c] = lrelu_f(acc[mi][ni][e] + fcb[zp*H + c]);
            }
    __syncthreads();
    #pragma unroll
    for (int t = 0; t < 16; ++t) {
        int idx = tid + t*256;
        int rr = idx >> 5, c4 = (idx & 31)*4;
        float4 v = *(const float4*)(Cs + rr*132 + c4);
        int gr = mt*128 + rr;
        __half2 p0 = {__float2half_rn(v.x), __float2half_rn(v.y)};
        __half2 p1 = {__float2half_rn(v.z), __float2half_rn(v.w)};
        uint2 uh; uh.x = *(unsigned*)&p0; uh.y = *(unsigned*)&p1;
        if (gr < BM_) {
            *(uint2*)(yh + ((size_t)zp*BM_ + gr)*H + c4) = uh;
        } else {
            size_t base = ((size_t)zp*Bq + (gr - BM_))*H + c4;
            *(float4*)(xsh + base) = v;
            *(uint2*)(xshf + base) = uh;
        }
    }
}

// ================= qk_fused (pure fp16: 1 MMA per k16) =================
#define QK_SMEM (2*128*QKS*2)
__global__ __launch_bounds__(256,1) void qk_fused(
    const __half* __restrict__ xshf,
    const __half* __restrict__ cqh, const float* __restrict__ cqb,
    const __half* __restrict__ awf,
    float* __restrict__ wh2)
{
    extern __shared__ __align__(16) char smc[];
    __half* As = (__half*)smc;          // [128*QKS]
    __half* Bs = As + 128*QKS;          // [128*QKS]
    int mt = blockIdx.x, z = blockIdx.y;
    int tid = threadIdx.x;
    int kz = c_kofs[z/HN]*HN + (z % HN);

    const __half* Ag = xshf + ((size_t)z*Bq + mt*128)*H;
    const __half* Bg = cqh + (size_t)z*H*H;

    #pragma unroll
    for (int i = 0; i < 8; ++i) {
        int idx = tid + i*256;
        int r = idx >> 4, seg = (idx & 15)*8;
        cpa16(As + r*QKS + seg, Ag + (size_t)r*H + seg);
        cpa16(Bs + r*QKS + seg, Bg + (size_t)r*H + seg);
    }
    cp_commit(); cp_wait0();
    __syncthreads();

    int w = tid >> 5, lane = tid & 31, gid = lane >> 2, tig = lane & 3;
    int wm = (w & 3)*32, wn = (w >> 2)*64;
    int arow = lane & 15, acol = (lane & 16) ? 8 : 0;
    int bn = (lane & 7) + ((lane & 16) ? 8 : 0), bk = (lane & 8) ? 8 : 0;
    unsigned aA = s2u(As), aB = s2u(Bs);
    float acc[2][8][4];

    auto run_gemm = [&]() {
        #pragma unroll
        for (int i = 0; i < 2; ++i)
            #pragma unroll
            for (int j = 0; j < 8; ++j)
                #pragma unroll
                for (int e = 0; e < 4; ++e) acc[i][j][e] = 0.f;
        #pragma unroll
        for (int kk = 0; kk < 8; ++kk) {
            int kb = kk*16;
            unsigned ah[2][4];
            #pragma unroll
            for (int mi = 0; mi < 2; ++mi) {
                unsigned off = (unsigned)(((wm + mi*16 + arow)*QKS + kb + acol)*2);
                ldsm4(ah[mi][0], ah[mi][1], ah[mi][2], ah[mi][3], aA + off);
            }
            unsigned b_[8][2];
            #pragma unroll
            for (int nj = 0; nj < 4; ++nj) {
                unsigned off_ = (unsigned)(((wn + nj*16 + bn)*QKS + kb + bk)*2);
                ldsm4(b_[nj*2][0], b_[nj*2][1], b_[nj*2+1][0], b_[nj*2+1][1], aB + off_);
            }
            #pragma unroll
            for (int ni = 0; ni < 8; ++ni)
                #pragma unroll
                for (int mi = 0; mi < 2; ++mi)
                    mma_f16(acc[mi][ni], ah[mi], b_[ni]);
        }
    };

    // GEMM1: h2 = lrelu(xsh @ cq^T + cqb)
    run_gemm();
    __syncthreads();
    #pragma unroll
    for (int mi = 0; mi < 2; ++mi)
        #pragma unroll
        for (int ni = 0; ni < 8; ++ni)
            #pragma unroll
            for (int e = 0; e < 4; ++e) {
                int r = wm + mi*16 + gid + ((e >= 2) ? 8 : 0);
                int c = wn + ni*8 + 2*tig + (e & 1);
                float v = lrelu_f(acc[mi][ni][e] + cqb[z*H + c]);
                As[r*QKS + c] = __float2half_rn(v);
            }
    const __half* Wg = awf + (size_t)kz*H*H;
    #pragma unroll
    for (int i = 0; i < 8; ++i) {
        int idx = tid + i*256;
        int r = idx >> 4, seg = (idx & 15)*8;
        cpa16(Bs + r*QKS + seg, Wg + (size_t)r*H + seg);
    }
    cp_commit(); cp_wait0();
    __syncthreads();

    // GEMM2: wh2 = h2 @ attW^T
    run_gemm();
    #pragma unroll
    for (int mi = 0; mi < 2; ++mi)
        #pragma unroll
        for (int ni = 0; ni < 8; ++ni)
            #pragma unroll
            for (int e = 0; e < 4; ++e) {
                int r = wm + mi*16 + gid + ((e >= 2) ? 8 : 0);
                int c = wn + ni*8 + 2*tig + (e & 1);
                wh2[((size_t)z*Bq + mt*128 + r)*H + c] = acc[mi][ni][e];
            }
}

// ======== fused h1/vh GEMM + attention (pure fp16: 1 MMA per k16) ========
#define FU_GEMM_BYTES ((128*QKS + 256*QKS)*2)
#define FU_EPI_BYTES  ((128*132 + 128*132 + 8*128 + 128 + 128)*4)
#define FU_SMEM       (FU_EPI_BYTES > FU_GEMM_BYTES ? FU_EPI_BYTES : FU_GEMM_BYTES)
__global__ __launch_bounds__(512,1) void fused_attn(
    const __half* __restrict__ yhg,
    const __half* __restrict__ ckh, const float* __restrict__ ckb,
    const __half* __restrict__ vwh, const float* __restrict__ vb,
    const float* __restrict__ wh2,
    const float* __restrict__ xsh, float* __restrict__ sout)
{
    extern __shared__ __align__(16) char smc[];
    float* sm = (float*)smc;
    __half* As = (__half*)smc;         // [128*QKS]
    __half* Bs = As + 128*QKS;         // [256*QKS]
    int mt = blockIdx.x, z = blockIdx.y;
    int tid = threadIdx.x;

    const __half* Ag = yhg + ((size_t)z*BM_ + mt*128)*H;
    size_t wkb = (size_t)z*H*H;

    #pragma unroll
    for (int i = 0; i < 4; ++i) {
        int idx = tid + i*512;
        int r = idx >> 4, seg = (idx & 15)*8;
        cpa16(As + r*QKS + seg, Ag + (size_t)r*H + seg);
    }
    #pragma unroll
    for (int i = 0; i < 8; ++i) {
        int idx = tid + i*512;
        int n = idx >> 4, seg = (idx & 15)*8;
        const __half* src = (n < 128) ? (ckh + wkb + (size_t)n*H)
                                      : (vwh + wkb + (size_t)(n-128)*H);
        cpa16(Bs + n*QKS + seg, src + seg);
    }
    cp_commit(); cp_wait0();
    __syncthreads();

    int w = tid >> 5, lane = tid & 31, gid = lane >> 2, tig = lane & 3;
    int wm = (w & 3)*32, wn = (w >> 2)*64;
    int arow = lane & 15, acol = (lane & 16) ? 8 : 0;
    int bn = (lane & 7) + ((lane & 16) ? 8 : 0), bk = (lane & 8) ? 8 : 0;
    unsigned aA = s2u(As), aB = s2u(Bs);

    float acc[2][8][4];
    #pragma unroll
    for (int i = 0; i < 2; ++i)
        #pragma unroll
        for (int j = 0; j < 8; ++j)
            #pragma unroll
            for (int e = 0; e < 4; ++e) acc[i][j][e] = 0.f;

    #pragma unroll
    for (int kk = 0; kk < 8; ++kk) {
        int kb = kk*16;
        unsigned ah[2][4];
        #pragma unroll
        for (int mi = 0; mi < 2; ++mi) {
            unsigned off = (unsigned)(((wm + mi*16 + arow)*QKS + kb + acol)*2);
            ldsm4(ah[mi][0], ah[mi][1], ah[mi][2], ah[mi][3], aA + off);
        }
        unsigned b_[8][2];
        #pragma unroll
        for (int nj = 0; nj < 4; ++nj) {
            unsigned off_ = (unsigned)(((wn + nj*16 + bn)*QKS + kb + bk)*2);
            ldsm4(b_[nj*2][0], b_[nj*2][1], b_[nj*2+1][0], b_[nj*2+1][1], aB + off_);
        }
        #pragma unroll
        for (int ni = 0; ni < 8; ++ni)
            #pragma unroll
            for (int mi = 0; mi < 2; ++mi)
                mma_f16(acc[mi][ni], ah[mi], b_[ni]);
    }
    __syncthreads();   // all smem reads done before epilogue aliasing

    float* SP  = sm;                 // [128][132]  h1 (lrelu+bias)
    float* SV  = SP + 128*132;       // [128][132]  vh (+bias)
    float* SW  = SV + 128*132;       // [8][128]    wh2 rows
    float* SSC = SW + 8*128;         // [128] scores
    float* SE  = SSC + 128;          // [128] softmax weights

    #pragma unroll
    for (int mi = 0; mi < 2; ++mi)
        #pragma unroll
        for (int ni = 0; ni < 8; ++ni)
            #pragma unroll
            for (int e = 0; e < 4; ++e) {
                int r = wm + mi*16 + gid + ((e >= 2) ? 8 : 0);
                int c = wn + ni*8 + 2*tig + (e & 1);
                float v = acc[mi][ni][e];
                if (c < 128) SP[r*132 + c] = lrelu_f(v + ckb[z*H + c]);
                else         SV[r*132 + (c-128)] = v + vb[z*H + (c-128)];
            }
    #pragma unroll
    for (int t = 0; t < 2; ++t) {
        int idx = tid + t*512;
        int bl = idx >> 7, o = idx & 127;
        SW[idx] = wh2[((size_t)z*Bq + mt*8 + bl)*H + o];
    }
    __syncthreads();

    #pragma unroll
    for (int i = 0; i < 8; ++i) {
        int rr = w*8 + i;
        const float* wrow = SW + (rr >> 4)*128;
        float p = 0.f;
        #pragma unroll
        for (int o = 0; o < 128; o += 32) p += SP[rr*132 + o + lane]*wrow[o + lane];
        #pragma unroll
        for (int d_ = 16; d_ > 0; d_ >>= 1) p += __shfl_xor_sync(0xffffffffu, p, d_);
        if (lane == 0) SSC[rr] = p;
    }
    __syncthreads();
    if (tid < 8) {
        float mx = -1e30f;
        #pragma unroll
        for (int m = 0; m < M; ++m) mx = fmaxf(mx, SSC[tid*M + m]);
        float es[M], sum = 0.f;
        #pragma unroll
        for (int m = 0; m < M; ++m) { es[m] = expf(SSC[tid*M + m] - mx); sum += es[m]; }
        float inv = 1.f/sum;
        #pragma unroll
        for (int m = 0; m < M; ++m) SE[tid*M + m] = es[m]*inv;
    }
    __syncthreads();

    int s = z/HN, hh = z%HN;
    #pragma unroll
    for (int t = 0; t < 2; ++t) {
        int idx = tid + t*512;
        int bl = idx >> 7, o = idx & 127;
        float a = 0.f;
        #pragma unroll
        for (int m = 0; m < M; ++m) {
            float v = SV[(bl*M + m)*132 + o]*SE[bl*M + m];
            a += (v >= 0.f) ? v : ALPHA*v;
        }
        int b = mt*8 + bl;
        sout[((size_t)s*Bq + b)*D + hh*H + o] =
            0.5f*(xsh[((size_t)z*Bq + b)*H + o] + a);
    }
}

// ---------------- semantic attention (256 thr, D-split halves) -----------------
#define SEM_SMEM(P) ((8*(P)*D + 2*64*132 + 2*8*(P)*132 + 32)*4)
template<int P>
__global__ __launch_bounds__(256) void semantic(
    const float* __restrict__ zin, const float* __restrict__ p1w,
    const float* __restrict__ p1b, const float* __restrict__ p2w,
    float* __restrict__ outp, int in_pstride, int in_bstride, int out_bstride)
{
    extern __shared__ __align__(16) float sem[];
    float* zs    = sem;                          // [8P][512]
    float* pw    = sem + 8*P*D;                  // [2][64][132] transposed chunks
    float* spart = pw + 2*64*132;                // [2][8P][132] partial accs
    float* ssc   = spart + 2*8*P*132;            // [8P]
    int b0 = blockIdx.x*8, tid = threadIdx.x;
    int h = tid & 127, half = tid >> 7;

    for (int idx = tid; idx < 8*P*(D/4); idx += 256) {
        int d4 = idx & (D/4 - 1); int rp = idx / (D/4);
        int p = rp % P, bl = rp / P;
        *(float4*)&zs[(bl*P+p)*D + d4*4] =
            *(const float4*)(zin + (size_t)(b0+bl)*in_bstride + (size_t)p*in_pstride + d4*4);
    }
    __syncthreads();

    float acc[8][P];
    #pragma unroll
    for (int bl = 0; bl < 8; ++bl)
        #pragma unroll
        for (int p = 0; p < P; ++p) acc[bl][p] = 0.f;

    for (int t = 0; t < 4; ++t) {
        #pragma unroll
        for (int i = 0; i < 16; ++i) {
            int idx = tid + i*256;
            int plane = idx >> 11;               // 2048 f4 per plane
            int j = idx & 2047;
            int r = j >> 4, c4 = (j & 15)*4;
            float4 v = *(const float4*)(p1w + (size_t)r*D + plane*256 + t*64 + c4);
            float* dst = pw + plane*64*132;
            dst[c4*132 + r]     = v.x;
            dst[(c4+1)*132 + r] = v.y;
            dst[(c4+2)*132 + r] = v.z;
            dst[(c4+3)*132 + r] = v.w;
        }
        __syncthreads();
        int dbase = half*256 + t*64;
        const float* mypw = pw + half*64*132;
        #pragma unroll 4
        for (int dd = 0; dd < 64; dd += 4) {
            float w0 = mypw[dd*132 + h],     w1 = mypw[(dd+1)*132 + h];
            float w2 = mypw[(dd+2)*132 + h], w3 = mypw[(dd+3)*132 + h];
            #pragma unroll
            for (int bl = 0; bl < 8; ++bl)
                #pragma unroll
                for (int p = 0; p < P; ++p) {
                    float4 zv = *(const float4*)&zs[(bl*P+p)*D + dbase + dd];
                    acc[bl][p] += w0*zv.x + w1*zv.y + w2*zv.z + w3*zv.w;
                }
        }
        __syncthreads();
    }

    #pragma unroll
    for (int bl = 0; bl < 8; ++bl)
        #pragma unroll
        for (int p = 0; p < P; ++p)
            spart[half*8*P*132 + (bl*P+p)*132 + h] = acc[bl][p];
    __syncthreads();
    if (half == 0) {
        float bias = p1b[h], p2 = p2w[h];
        #pragma unroll
        for (int bl = 0; bl < 8; ++bl)
            #pragma unroll
            for (int p = 0; p < P; ++p) {
                int o = (bl*P+p)*132 + h;
                spart[o] = tanhf(spart[o] + spart[8*P*132 + o] + bias)*p2;
            }
    }
    __syncthreads();
    if (tid < 8*P) {
        float s_ = 0.f;
        for (int o = 0; o < H; ++o) s_ += spart[tid*132 + o];
        ssc[tid] = s_;
    }
    __syncthreads();
    if (tid < 8) {
        float mx = -1e30f;
        #pragma unroll
        for (int p = 0; p < P; ++p) mx = fmaxf(mx, ssc[tid*P + p]);
        float e[P]; float esum = 0.f;
        #pragma unroll
        for (int p = 0; p < P; ++p) { e[p] = expf(ssc[tid*P + p] - mx); esum += e[p]; }
        float inv = 1.f/esum;
        #pragma unroll
        for (int p = 0; p < P; ++p) ssc[tid*P + p] = e[p]*inv;
    }
    __syncthreads();
    for (int idx = tid; idx < 8*(D/4); idx += 256) {
        int d4 = (idx & (D/4 - 1))*4; int bl = idx / (D/4);
        float4 o = {0.f, 0.f, 0.f, 0.f};
        #pragma unroll
        for (int p = 0; p < P; ++p) {
            float e = ssc[bl*P + p];
            float4 zv = *(const float4*)&zs[(bl*P+p)*D + d4];
            o.x += e*zv.x; o.y += e*zv.y; o.z += e*zv.z; o.w += e*zv.w;
        }
        *(float4*)(outp + (size_t)(b0+bl)*out_bstride + d4) = o;
    }
}

extern "C" void kernel_launch(void* const* d_in, const int* in_sizes, int n_in,
                              void* d_out, int out_size)
{
    const float* x     = (const float*)d_in[0];
    const int*   tgt   = (const int*)  d_in[1];
    const int*   neigh = (const int*)  d_in[2];
    const float* fc_w  = (const float*)d_in[3];
    const float* fc_b  = (const float*)d_in[4];
    const float* q_w   = (const float*)d_in[5];
    const float* q_b   = (const float*)d_in[6];
    const float* k_w   = (const float*)d_in[7];
    const float* k_b   = (const float*)d_in[8];
    const float* v_w   = (const float*)d_in[9];
    const float* v_b   = (const float*)d_in[10];
    const float* att_W = (const float*)d_in[11];
    const float* a1w   = (const float*)d_in[12];
    const float* a1b   = (const float*)d_in[13];
    const float* a2w   = (const float*)d_in[14];
    const float* a2b   = (const float*)d_in[15];
    const float* ip1w  = (const float*)d_in[16];
    const float* ip1b  = (const float*)d_in[17];
    const float* ip2w  = (const float*)d_in[18];
    const float* bp1w  = (const float*)d_in[19];
    const float* bp1b  = (const float*)d_in[20];
    const float* bp2w  = (const float*)d_in[21];
    float* out = (float*)d_out;

    __half *xh,*fwh,*vwh,*awf,*ckh,*cqh,*yh,*xshf;
    float *ckb,*cqb,*xsh,*wh2,*sout,*mp;
    cudaGetSymbolAddress((void**)&xh,   g_xh);
    cudaGetSymbolAddress((void**)&fwh,  g_fwh);
    cudaGetSymbolAddress((void**)&vwh,  g_vwh);
    cudaGetSymbolAddress((void**)&awf,  g_awf);
    cudaGetSymbolAddress((void**)&ckh,  g_ckh);
    cudaGetSymbolAddress((void**)&ckb,  g_ckb);
    cudaGetSymbolAddress((void**)&cqh,  g_cqh);
    cudaGetSymbolAddress((void**)&cqb,  g_cqb);
    cudaGetSymbolAddress((void**)&xsh,  g_xsh);
    cudaGetSymbolAddress((void**)&xshf, g_xshf);
    cudaGetSymbolAddress((void**)&yh,   g_yh);
    cudaGetSymbolAddress((void**)&wh2,  g_wh2);
    cudaGetSymbolAddress((void**)&sout, g_sout);
    cudaGetSymbolAddress((void**)&mp,   g_mp);

    static int smem_set = 0;
    if (!smem_set) {
        cudaFuncSetAttribute(fc_f16,      cudaFuncAttributeMaxDynamicSharedMemorySize, FC2_SMEM);
        cudaFuncSetAttribute(qk_fused,    cudaFuncAttributeMaxDynamicSharedMemorySize, QK_SMEM);
        cudaFuncSetAttribute(fused_attn,  cudaFuncAttributeMaxDynamicSharedMemorySize, FU_SMEM);
        cudaFuncSetAttribute(semantic<2>, cudaFuncAttributeMaxDynamicSharedMemorySize, SEM_SMEM(2));
        cudaFuncSetAttribute(semantic<3>, cudaFuncAttributeMaxDynamicSharedMemorySize, SEM_SMEM(3));
        smem_set = 1;
    }

    // 0. operand prep
    split_all<<<(SPL_TOT + 255)/256, 256>>>(x, xh, fc_w, fwh, v_w, vwh, att_W, awf);

    // 1. fold attention-layer weights into k/q projections
    combine_gemm<<<dim3(4, PAIRS, 2), 256>>>(a1w, a1b, k_w, k_b, ckh, ckb,
                                             a2w, a2b, q_w, q_b, cqh, cqb);

    // 2. shared fc + leakyrelu on gathered neighbors + targets (pure fp16)
    fc_f16<<<dim3(R_/128, 4, S), 256, FC2_SMEM>>>(xh, neigh, tgt, fwh,
                                                  fc_b, yh, xsh, xshf);

    // 3. wh2 = (lrelu(xsh@cq^T + cqb)) @ attW^T (pure fp16)
    qk_fused<<<dim3(Bq/128, PAIRS), 256, QK_SMEM>>>(xshf, cqh, cqb, awf, wh2);

    // 4. fused h1/vh GEMM + neighbor attention + residual (pure fp16)
    fused_attn<<<dim3(BM_/128, PAIRS), 512, FU_SMEM>>>(yh, ckh, ckb,
                                                       vwh, v_b, wh2, xsh, sout);

    // 5. semantic attention within each metapath
    semantic<2><<<Bq/8, 256, SEM_SMEM(2)>>>(sout,          ip1w,       ip1b,     ip2w,     mp,     Bq*D, D, KM*D);
    semantic<3><<<Bq/8, 256, SEM_SMEM(3)>>>(sout + 2*Bq*D, ip1w + H*D, ip1b + H, ip2w + H, mp + D, Bq*D, D, KM*D);

    // 6. semantic attention between metapaths -> final output
    semantic<2><<<Bq/8, 256, SEM_SMEM(2)>>>(mp, bp1w, bp1b, bp2w, out, D, KM*D, D);
}